// round 1
// baseline (speedup 1.0000x reference)
#include <cuda_runtime.h>
#include <math.h>

#define BB 2
#define LL 2048
#define DD 1024
#define NH 16
#define NKV 4
#define HD 64
#define WIN 1024
#define QKV_DIM 1536
#define EPSV 1.1920929e-07f

// ---------------- scratch (no cudaMalloc allowed) ----------------
__device__ float g_h[BB * LL * DD];          // rmsnorm(x)
__device__ float g_qkv[BB * LL * QKV_DIM];   // qkv projection
__device__ float g_q[BB * NH * LL * HD];     // q (normed, roped, pre-scaled)
__device__ float g_k[BB * NKV * LL * HD];    // k (normed, roped)
__device__ float g_v[BB * NKV * LL * HD];    // v
__device__ float g_y[BB * LL * DD];          // attention output
__device__ int   g_lo[BB * LL];              // first valid key per query

// ---------------- kernel 0: segment scan -> lo[i] ----------------
// lo[i] = max(i - (WIN-1), seg_start(i)); seg_start = prefix-max of (reset[i]? i : 0)
// Robust to mask marshalled as int32, uint8/bool, or float32.
__global__ void seg_kernel(const void* __restrict__ mask) {
    __shared__ int s0[LL];
    __shared__ int s1[LL];
    __shared__ int enc;  // 0=int32, 1=byte, 2=float
    const int b = blockIdx.x;
    const int t = threadIdx.x;  // 1024 threads

    if (t == 0) {
        const unsigned* mi = (const unsigned*)mask;
        int e = 0;
        for (int i = 0; i < 64; i++) {
            unsigned v = mi[i];
            if (v == 0x3F800000u) { e = 2; break; }
            if (v > 1u) e = 1;
        }
        enc = e;
    }
    __syncthreads();
    const int e = enc;

    for (int i = t; i < LL; i += 1024) {
        int mset;
        if (e == 0)      mset = ((const int*)mask)[b * LL + i] != 0;
        else if (e == 1) mset = ((const unsigned char*)mask)[b * LL + i] != 0;
        else             mset = ((const float*)mask)[b * LL + i] != 0.0f;
        s0[i] = mset ? i : 0;
    }
    __syncthreads();

    int* src = s0;
    int* dst = s1;
    for (int off = 1; off < LL; off <<= 1) {
        for (int i = t; i < LL; i += 1024) {
            int v = src[i];
            if (i >= off) v = max(v, src[i - off]);
            dst[i] = v;
        }
        __syncthreads();
        int* tmp = src; src = dst; dst = tmp;
    }
    for (int i = t; i < LL; i += 1024) {
        g_lo[b * LL + i] = max(i - (WIN - 1), src[i]);
    }
}

// ---------------- kernel 1: rmsnorm over D ----------------
__global__ void __launch_bounds__(256) rmsnorm_kernel(const float* __restrict__ x) {
    const int row = blockIdx.x;
    const float* xr = x + (size_t)row * DD;
    float* hr = g_h + (size_t)row * DD;
    const int t = threadIdx.x;

    float v[4];
    float ss = 0.f;
#pragma unroll
    for (int i = 0; i < 4; i++) { v[i] = xr[t + i * 256]; ss += v[i] * v[i]; }

    __shared__ float red[8];
#pragma unroll
    for (int m = 16; m; m >>= 1) ss += __shfl_xor_sync(0xffffffffu, ss, m);
    if ((t & 31) == 0) red[t >> 5] = ss;
    __syncthreads();
    if (t < 8) {
        float r = red[t];
#pragma unroll
        for (int m = 4; m; m >>= 1) r += __shfl_xor_sync(0xffu, r, m, 8);
        if (t == 0) red[0] = r;
    }
    __syncthreads();
    const float inv = rsqrtf(red[0] * (1.0f / DD) + EPSV);
#pragma unroll
    for (int i = 0; i < 4; i++) hr[t + i * 256] = v[i] * inv;
}

// ---------------- kernel 2/5: SGEMM C = A @ W^T (+res) ----------------
// A [M,K] row-major, W [N,K] row-major. 128x128 block, 8x8 per-thread, BK=8.
template <int RES>
__global__ void __launch_bounds__(256) sgemm_kernel(
    const float* __restrict__ A, const float* __restrict__ W,
    const float* __restrict__ res, float* __restrict__ C,
    int M, int N, int K)
{
    __shared__ float As[8][132];
    __shared__ float Bs[8][132];
    const int tid = threadIdx.x;
    const int m0 = blockIdx.y * 128;
    const int n0 = blockIdx.x * 128;
    const int lr = tid >> 1;          // 0..127
    const int lc = (tid & 1) << 2;    // 0 or 4
    const float* Ap = A + (size_t)(m0 + lr) * K + lc;
    const float* Wp = W + (size_t)(n0 + lr) * K + lc;
    const int tm = (tid >> 4) << 3;
    const int tn = (tid & 15) << 3;

    float acc[8][8];
#pragma unroll
    for (int i = 0; i < 8; i++)
#pragma unroll
        for (int j = 0; j < 8; j++) acc[i][j] = 0.f;

    for (int k0 = 0; k0 < K; k0 += 8) {
        float4 av = *(const float4*)(Ap + k0);
        float4 wv = *(const float4*)(Wp + k0);
        As[lc + 0][lr] = av.x; As[lc + 1][lr] = av.y;
        As[lc + 2][lr] = av.z; As[lc + 3][lr] = av.w;
        Bs[lc + 0][lr] = wv.x; Bs[lc + 1][lr] = wv.y;
        Bs[lc + 2][lr] = wv.z; Bs[lc + 3][lr] = wv.w;
        __syncthreads();
#pragma unroll
        for (int k = 0; k < 8; k++) {
            float ra[8], rb[8];
            *(float4*)&ra[0] = *(const float4*)&As[k][tm];
            *(float4*)&ra[4] = *(const float4*)&As[k][tm + 4];
            *(float4*)&rb[0] = *(const float4*)&Bs[k][tn];
            *(float4*)&rb[4] = *(const float4*)&Bs[k][tn + 4];
#pragma unroll
            for (int i = 0; i < 8; i++)
#pragma unroll
                for (int j = 0; j < 8; j++)
                    acc[i][j] += ra[i] * rb[j];
        }
        __syncthreads();
    }

#pragma unroll
    for (int i = 0; i < 8; i++) {
        const int m = m0 + tm + i;
        float* crow = C + (size_t)m * N + n0 + tn;
        if (RES) {
            const float* rrow = res + (size_t)m * N + n0 + tn;
#pragma unroll
            for (int j = 0; j < 8; j++) crow[j] = acc[i][j] + rrow[j];
        } else {
#pragma unroll
            for (int j = 0; j < 8; j++) crow[j] = acc[i][j];
        }
    }
}

// ---------------- kernel 3: per-head rmsnorm + rope + scatter ----------------
// 384 threads: 24 heads x 16 threads. heads 0-15 q, 16-19 k, 20-23 v.
__global__ void __launch_bounds__(384) qkrope_kernel() {
    const int row = blockIdx.x;          // b*LL + l
    const int b = row / LL;
    const int l = row % LL;
    const int t = threadIdx.x;
    const int head = t >> 4;             // 0..23
    const int tl = t & 15;
    const int j = tl * 2;                // 0..30 (pairs j, j+1; partners j+32, j+33)

    const float* src = g_qkv + (size_t)row * QKV_DIM + head * 64;

    if (head < 20) {
        float a0 = src[j], a1 = src[j + 1];
        float b0 = src[j + 32], b1 = src[j + 33];
        float ss = a0 * a0 + a1 * a1 + b0 * b0 + b1 * b1;
#pragma unroll
        for (int m = 8; m; m >>= 1) ss += __shfl_xor_sync(0xffffffffu, ss, m, 16);
        const float inv = rsqrtf(ss * (1.0f / HD) + EPSV);
        a0 *= inv; a1 *= inv; b0 *= inv; b1 *= inv;

        // rope: inv_freq_j = 10000^{-j/32}
        const float lg = logf(10000.0f) * (1.0f / 32.0f);
        const float f0 = expf(-lg * (float)j);
        const float f1 = expf(-lg * (float)(j + 1));
        float s0, c0, s1, c1;
        sincosf((float)l * f0, &s0, &c0);
        sincosf((float)l * f1, &s1, &c1);
        const float o0 = a0 * c0 - b0 * s0;
        const float o1 = a1 * c1 - b1 * s1;
        const float o2 = a0 * s0 + b0 * c0;
        const float o3 = a1 * s1 + b1 * c1;

        if (head < 16) {
            const float sc = 0.125f;  // 1/sqrt(64), folded into q
            float* dq = g_q + (((size_t)(b * NH + head)) * LL + l) * HD;
            dq[j] = o0 * sc; dq[j + 1] = o1 * sc;
            dq[j + 32] = o2 * sc; dq[j + 33] = o3 * sc;
        } else {
            float* dk = g_k + (((size_t)(b * NKV + (head - 16))) * LL + l) * HD;
            dk[j] = o0; dk[j + 1] = o1;
            dk[j + 32] = o2; dk[j + 33] = o3;
        }
    } else {
        float* dv = g_v + (((size_t)(b * NKV + (head - 20))) * LL + l) * HD;
        dv[j] = src[j]; dv[j + 1] = src[j + 1];
        dv[j + 32] = src[j + 32]; dv[j + 33] = src[j + 33];
    }
}

// ---------------- kernel 4: flash attention over contiguous valid range ----------------
// grid (32 qblocks, 16 heads, 2 batch), 256 threads.
// 64x64 tiles; 4x4 micro-tile per thread; cols strided by 16 for conflict-free LDS.
#define SP 65  // shared row stride
__global__ void __launch_bounds__(256) attn_kernel() {
    extern __shared__ float sm[];
    float* Qs = sm;
    float* Ks = Qs + 64 * SP;
    float* Vs = Ks + 64 * SP;
    float* Ps = Vs + 64 * SP;
    __shared__ int lo_s[64];

    const int qb = blockIdx.x, h = blockIdx.y, b = blockIdx.z;
    const int t = threadIdx.x;
    const int q0 = qb * 64;
    const int kvh = h >> 2;
    const float* Qg = g_q + (((size_t)(b * NH + h)) * LL + q0) * HD;
    const float* Kg = g_k + ((size_t)(b * NKV + kvh)) * LL * HD;
    const float* Vg = g_v + ((size_t)(b * NKV + kvh)) * LL * HD;

    for (int i = t; i < 64 * 64; i += 256) {
        Qs[(i >> 6) * SP + (i & 63)] = Qg[i];
    }
    if (t < 64) lo_s[t] = g_lo[b * LL + q0 + t];
    __syncthreads();

    const int tr = t >> 4;  // 0..15 -> rows tr*4..tr*4+3
    const int tc = t & 15;  // cols tc, tc+16, tc+32, tc+48

    float m[4], lsum[4], o[4][4];
    int lo[4];
#pragma unroll
    for (int i = 0; i < 4; i++) {
        m[i] = -1e30f; lsum[i] = 0.f;
        lo[i] = lo_s[tr * 4 + i];
#pragma unroll
        for (int jj = 0; jj < 4; jj++) o[i][jj] = 0.f;
    }

    const int kb0 = lo_s[0] & ~63;  // lo is non-decreasing -> lo_s[0] is the min
    for (int kb = kb0; kb <= q0 + 63; kb += 64) {
        for (int i = t; i < 64 * 64; i += 256) {
            Ks[(i >> 6) * SP + (i & 63)] = Kg[(size_t)kb * 64 + i];
            Vs[(i >> 6) * SP + (i & 63)] = Vg[(size_t)kb * 64 + i];
        }
        __syncthreads();

        float s[4][4];
#pragma unroll
        for (int i = 0; i < 4; i++)
#pragma unroll
            for (int jj = 0; jj < 4; jj++) s[i][jj] = 0.f;

        for (int d = 0; d < 64; d++) {
            float qv[4], kv[4];
#pragma unroll
            for (int i = 0; i < 4; i++) qv[i] = Qs[(tr * 4 + i) * SP + d];
#pragma unroll
            for (int jj = 0; jj < 4; jj++) kv[jj] = Ks[(tc + jj * 16) * SP + d];
#pragma unroll
            for (int i = 0; i < 4; i++)
#pragma unroll
                for (int jj = 0; jj < 4; jj++) s[i][jj] += qv[i] * kv[jj];
        }

#pragma unroll
        for (int i = 0; i < 4; i++) {
            const int qg = q0 + tr * 4 + i;
            float rmax = -1e30f;
#pragma unroll
            for (int jj = 0; jj < 4; jj++) {
                const int kg = kb + tc + jj * 16;
                if (kg < lo[i] || kg > qg) s[i][jj] = -1e30f;
                rmax = fmaxf(rmax, s[i][jj]);
            }
#pragma unroll
            for (int sh = 8; sh; sh >>= 1)
                rmax = fmaxf(rmax, __shfl_xor_sync(0xffffffffu, rmax, sh, 16));
            const float mn = fmaxf(m[i], rmax);
            const float alpha = __expf(m[i] - mn);
            float lpart = 0.f;
#pragma unroll
            for (int jj = 0; jj < 4; jj++) {
                // guard: masked entries stay exactly 0 even when mn is still -1e30
                const float p = (s[i][jj] > -1e29f) ? __expf(s[i][jj] - mn) : 0.f;
                Ps[(tr * 4 + i) * SP + tc + jj * 16] = p;
                lpart += p;
            }
#pragma unroll
            for (int sh = 8; sh; sh >>= 1)
                lpart += __shfl_xor_sync(0xffffffffu, lpart, sh, 16);
            lsum[i] = lsum[i] * alpha + lpart;
            m[i] = mn;
#pragma unroll
            for (int jj = 0; jj < 4; jj++) o[i][jj] *= alpha;
        }
        __syncthreads();

        for (int kj = 0; kj < 64; kj++) {
            float pv[4], vv[4];
#pragma unroll
            for (int i = 0; i < 4; i++) pv[i] = Ps[(tr * 4 + i) * SP + kj];
#pragma unroll
            for (int jj = 0; jj < 4; jj++) vv[jj] = Vs[kj * SP + tc + jj * 16];
#pragma unroll
            for (int i = 0; i < 4; i++)
#pragma unroll
                for (int jj = 0; jj < 4; jj++) o[i][jj] += pv[i] * vv[jj];
        }
        __syncthreads();
    }

#pragma unroll
    for (int i = 0; i < 4; i++) {
        const float invl = 1.0f / lsum[i];
        const int qg = q0 + tr * 4 + i;
        float* yr = g_y + ((size_t)(b * LL) + qg) * DD + h * HD;
#pragma unroll
        for (int jj = 0; jj < 4; jj++) yr[tc + jj * 16] = o[i][jj] * invl;
    }
}

// ---------------- launch ----------------
extern "C" void kernel_launch(void* const* d_in, const int* in_sizes, int n_in,
                              void* d_out, int out_size) {
    const float* x     = (const float*)d_in[0];
    const float* w_qkv = (const float*)d_in[1];
    const float* w_out = (const float*)d_in[2];
    const void*  mask  = d_in[3];
    float* out = (float*)d_out;

    float *ph, *pqkv, *py;
    cudaGetSymbolAddress((void**)&ph, g_h);
    cudaGetSymbolAddress((void**)&pqkv, g_qkv);
    cudaGetSymbolAddress((void**)&py, g_y);

    const int M = BB * LL;

    seg_kernel<<<BB, 1024>>>(mask);
    rmsnorm_kernel<<<M, 256>>>(x);
    sgemm_kernel<0><<<dim3(QKV_DIM / 128, M / 128), 256>>>(ph, w_qkv, nullptr, pqkv,
                                                           M, QKV_DIM, DD);
    qkrope_kernel<<<M, 384>>>();

    const size_t attn_smem = 4 * 64 * SP * sizeof(float);
    cudaFuncSetAttribute(attn_kernel, cudaFuncAttributeMaxDynamicSharedMemorySize,
                         (int)attn_smem);
    attn_kernel<<<dim3(LL / 64, NH, BB), 256, attn_smem>>>();

    sgemm_kernel<1><<<dim3(DD / 128, M / 128), 256>>>(py, w_out, x, out,
                                                      M, DD, DD);
}

// round 2
// speedup vs baseline: 2.1257x; 2.1257x over previous
#include <cuda_runtime.h>
#include <math.h>
#include <stdint.h>

#define BB 2
#define LL 2048
#define DD 1024
#define NH 16
#define NKV 4
#define HD 64
#define WIN 1024
#define QKV_DIM 1536
#define EPSV 1.1920929e-07f

// ---------------- scratch (no cudaMalloc allowed) ----------------
__device__ float g_h[BB * LL * DD];          // rmsnorm(x)
__device__ float g_qkv[BB * LL * QKV_DIM];   // qkv projection
__device__ float g_q[BB * NH * LL * HD];     // q (normed, roped, pre-scaled)
__device__ float g_k[BB * NKV * LL * HD];    // k (normed, roped)
__device__ float g_v[BB * NKV * LL * HD];    // v
__device__ float g_y[BB * LL * DD];          // attention output
__device__ int   g_lo[BB * LL];              // first valid key per query

// ---------------- kernel 0: segment scan -> lo[i] ----------------
__global__ void seg_kernel(const void* __restrict__ mask) {
    __shared__ int s0[LL];
    __shared__ int s1[LL];
    __shared__ int enc;  // 0=int32, 1=byte, 2=float
    const int b = blockIdx.x;
    const int t = threadIdx.x;  // 1024 threads

    if (t == 0) {
        const unsigned* mi = (const unsigned*)mask;
        int e = 0;
        for (int i = 0; i < 64; i++) {
            unsigned v = mi[i];
            if (v == 0x3F800000u) { e = 2; break; }
            if (v > 1u) e = 1;
        }
        enc = e;
    }
    __syncthreads();
    const int e = enc;

    for (int i = t; i < LL; i += 1024) {
        int mset;
        if (e == 0)      mset = ((const int*)mask)[b * LL + i] != 0;
        else if (e == 1) mset = ((const unsigned char*)mask)[b * LL + i] != 0;
        else             mset = ((const float*)mask)[b * LL + i] != 0.0f;
        s0[i] = mset ? i : 0;
    }
    __syncthreads();

    int* src = s0;
    int* dst = s1;
    for (int off = 1; off < LL; off <<= 1) {
        for (int i = t; i < LL; i += 1024) {
            int v = src[i];
            if (i >= off) v = max(v, src[i - off]);
            dst[i] = v;
        }
        __syncthreads();
        int* tmp = src; src = dst; dst = tmp;
    }
    for (int i = t; i < LL; i += 1024) {
        g_lo[b * LL + i] = max(i - (WIN - 1), src[i]);
    }
}

// ---------------- kernel 1: rmsnorm over D ----------------
__global__ void __launch_bounds__(256) rmsnorm_kernel(const float* __restrict__ x) {
    const int row = blockIdx.x;
    const float* xr = x + (size_t)row * DD;
    float* hr = g_h + (size_t)row * DD;
    const int t = threadIdx.x;

    float v[4];
    float ss = 0.f;
#pragma unroll
    for (int i = 0; i < 4; i++) { v[i] = xr[t + i * 256]; ss += v[i] * v[i]; }

    __shared__ float red[8];
#pragma unroll
    for (int m = 16; m; m >>= 1) ss += __shfl_xor_sync(0xffffffffu, ss, m);
    if ((t & 31) == 0) red[t >> 5] = ss;
    __syncthreads();
    if (t < 8) {
        float r = red[t];
#pragma unroll
        for (int m = 4; m; m >>= 1) r += __shfl_xor_sync(0xffu, r, m, 8);
        if (t == 0) red[0] = r;
    }
    __syncthreads();
    const float inv = rsqrtf(red[0] * (1.0f / DD) + EPSV);
#pragma unroll
    for (int i = 0; i < 4; i++) hr[t + i * 256] = v[i] * inv;
}

// ---------------- tf32 tensor-core GEMM: C = A @ W^T (+res) ----------------
// A [M,K] row-major, W [N,K] row-major, both K-major => mma row.col form.
// 128x128 block tile, BK=16, 8 warps (2 m x 4 n), warp tile 64x32.
__device__ __forceinline__ uint32_t f2tf32(float x) {
    uint32_t r;
    asm("cvt.rna.tf32.f32 %0, %1;" : "=r"(r) : "f"(x));
    return r;
}

__device__ __forceinline__ void mma_tf32(float* c, const uint32_t* a, const uint32_t* b) {
    asm volatile(
        "mma.sync.aligned.m16n8k8.row.col.f32.tf32.tf32.f32 "
        "{%0,%1,%2,%3}, {%4,%5,%6,%7}, {%8,%9}, {%0,%1,%2,%3};\n"
        : "+f"(c[0]), "+f"(c[1]), "+f"(c[2]), "+f"(c[3])
        : "r"(a[0]), "r"(a[1]), "r"(a[2]), "r"(a[3]), "r"(b[0]), "r"(b[1]));
}

#define GSTR 136  // shared k-row stride: 136 % 32 = 8 -> conflict-free frag loads

template <int RES>
__global__ void __launch_bounds__(256) mma_gemm_kernel(
    const float* __restrict__ A, const float* __restrict__ W,
    const float* __restrict__ res, float* __restrict__ C,
    int M, int N, int K)
{
    __shared__ uint32_t As[16][GSTR];
    __shared__ uint32_t Bs[16][GSTR];

    const int tid = threadIdx.x;
    const int lane = tid & 31;
    const int wid = tid >> 5;
    const int wm = (wid & 1) * 64;        // warp m offset in block
    const int wn = (wid >> 1) * 32;       // warp n offset in block
    const int m0 = blockIdx.y * 128;
    const int n0 = blockIdx.x * 128;

    // loader mapping: 128 rows x 16 cols per array; each thread 8 floats
    const int lr = tid >> 1;              // 0..127
    const int lc = (tid & 1) << 3;        // 0 or 8
    const float* Ap = A + (size_t)(m0 + lr) * K + lc;
    const float* Wp = W + (size_t)(n0 + lr) * K + lc;

    float acc[4][4][4];
#pragma unroll
    for (int i = 0; i < 4; i++)
#pragma unroll
        for (int j = 0; j < 4; j++)
#pragma unroll
            for (int r = 0; r < 4; r++) acc[i][j][r] = 0.f;

    const int g = lane >> 2;   // 0..7
    const int tg = lane & 3;   // 0..3

    for (int k0 = 0; k0 < K; k0 += 16) {
        float4 av0 = *(const float4*)(Ap + k0);
        float4 av1 = *(const float4*)(Ap + k0 + 4);
        float4 wv0 = *(const float4*)(Wp + k0);
        float4 wv1 = *(const float4*)(Wp + k0 + 4);
        __syncthreads();
        As[lc + 0][lr] = f2tf32(av0.x); As[lc + 1][lr] = f2tf32(av0.y);
        As[lc + 2][lr] = f2tf32(av0.z); As[lc + 3][lr] = f2tf32(av0.w);
        As[lc + 4][lr] = f2tf32(av1.x); As[lc + 5][lr] = f2tf32(av1.y);
        As[lc + 6][lr] = f2tf32(av1.z); As[lc + 7][lr] = f2tf32(av1.w);
        Bs[lc + 0][lr] = f2tf32(wv0.x); Bs[lc + 1][lr] = f2tf32(wv0.y);
        Bs[lc + 2][lr] = f2tf32(wv0.z); Bs[lc + 3][lr] = f2tf32(wv0.w);
        Bs[lc + 4][lr] = f2tf32(wv1.x); Bs[lc + 5][lr] = f2tf32(wv1.y);
        Bs[lc + 6][lr] = f2tf32(wv1.z); Bs[lc + 7][lr] = f2tf32(wv1.w);
        __syncthreads();

#pragma unroll
        for (int ks = 0; ks < 16; ks += 8) {
            uint32_t afr[4][4];
            uint32_t bfr[4][2];
#pragma unroll
            for (int mi = 0; mi < 4; mi++) {
                const int row = wm + mi * 16 + g;
                afr[mi][0] = As[ks + tg][row];
                afr[mi][1] = As[ks + tg][row + 8];
                afr[mi][2] = As[ks + tg + 4][row];
                afr[mi][3] = As[ks + tg + 4][row + 8];
            }
#pragma unroll
            for (int ni = 0; ni < 4; ni++) {
                const int col = wn + ni * 8 + g;
                bfr[ni][0] = Bs[ks + tg][col];
                bfr[ni][1] = Bs[ks + tg + 4][col];
            }
#pragma unroll
            for (int mi = 0; mi < 4; mi++)
#pragma unroll
                for (int ni = 0; ni < 4; ni++)
                    mma_tf32(acc[mi][ni], afr[mi], bfr[ni]);
        }
    }

    // epilogue
#pragma unroll
    for (int mi = 0; mi < 4; mi++) {
#pragma unroll
        for (int ni = 0; ni < 4; ni++) {
            const int row = m0 + wm + mi * 16 + g;
            const int col = n0 + wn + ni * 8 + (tg << 1);
            float2 v0 = make_float2(acc[mi][ni][0], acc[mi][ni][1]);
            float2 v1 = make_float2(acc[mi][ni][2], acc[mi][ni][3]);
            if (RES) {
                const float2 r0 = *(const float2*)(res + (size_t)row * N + col);
                const float2 r1 = *(const float2*)(res + (size_t)(row + 8) * N + col);
                v0.x += r0.x; v0.y += r0.y;
                v1.x += r1.x; v1.y += r1.y;
            }
            *(float2*)(C + (size_t)row * N + col) = v0;
            *(float2*)(C + (size_t)(row + 8) * N + col) = v1;
        }
    }
}

// ---------------- kernel 3: per-head rmsnorm + rope + scatter ----------------
__global__ void __launch_bounds__(384) qkrope_kernel() {
    const int row = blockIdx.x;          // b*LL + l
    const int b = row / LL;
    const int l = row % LL;
    const int t = threadIdx.x;
    const int head = t >> 4;             // 0..23
    const int tl = t & 15;
    const int j = tl * 2;                // pairs j, j+1; partners j+32, j+33

    const float* src = g_qkv + (size_t)row * QKV_DIM + head * 64;

    if (head < 20) {
        float a0 = src[j], a1 = src[j + 1];
        float b0 = src[j + 32], b1 = src[j + 33];
        float ss = a0 * a0 + a1 * a1 + b0 * b0 + b1 * b1;
#pragma unroll
        for (int m = 8; m; m >>= 1) ss += __shfl_xor_sync(0xffffffffu, ss, m, 16);
        const float inv = rsqrtf(ss * (1.0f / HD) + EPSV);
        a0 *= inv; a1 *= inv; b0 *= inv; b1 *= inv;

        const float lg = logf(10000.0f) * (1.0f / 32.0f);
        const float f0 = expf(-lg * (float)j);
        const float f1 = expf(-lg * (float)(j + 1));
        float s0, c0, s1, c1;
        sincosf((float)l * f0, &s0, &c0);
        sincosf((float)l * f1, &s1, &c1);
        const float o0 = a0 * c0 - b0 * s0;
        const float o1 = a1 * c1 - b1 * s1;
        const float o2 = a0 * s0 + b0 * c0;
        const float o3 = a1 * s1 + b1 * c1;

        if (head < 16) {
            const float sc = 0.125f;  // 1/sqrt(64) folded into q
            float* dq = g_q + (((size_t)(b * NH + head)) * LL + l) * HD;
            dq[j] = o0 * sc; dq[j + 1] = o1 * sc;
            dq[j + 32] = o2 * sc; dq[j + 33] = o3 * sc;
        } else {
            float* dk = g_k + (((size_t)(b * NKV + (head - 16))) * LL + l) * HD;
            dk[j] = o0; dk[j + 1] = o1;
            dk[j + 32] = o2; dk[j + 33] = o3;
        }
    } else {
        float* dv = g_v + (((size_t)(b * NKV + (head - 20))) * LL + l) * HD;
        dv[j] = src[j]; dv[j + 1] = src[j + 1];
        dv[j + 32] = src[j + 32]; dv[j + 33] = src[j + 33];
    }
}

// ---------------- kernel 4: flash attention over contiguous valid range ----------------
#define SP 65
__global__ void __launch_bounds__(256) attn_kernel() {
    extern __shared__ float sm[];
    float* Qs = sm;
    float* Ks = Qs + 64 * SP;
    float* Vs = Ks + 64 * SP;
    float* Ps = Vs + 64 * SP;
    __shared__ int lo_s[64];

    const int qb = blockIdx.x, h = blockIdx.y, b = blockIdx.z;
    const int t = threadIdx.x;
    const int q0 = qb * 64;
    const int kvh = h >> 2;
    const float* Qg = g_q + (((size_t)(b * NH + h)) * LL + q0) * HD;
    const float* Kg = g_k + ((size_t)(b * NKV + kvh)) * LL * HD;
    const float* Vg = g_v + ((size_t)(b * NKV + kvh)) * LL * HD;

    for (int i = t; i < 64 * 64; i += 256) {
        Qs[(i >> 6) * SP + (i & 63)] = Qg[i];
    }
    if (t < 64) lo_s[t] = g_lo[b * LL + q0 + t];
    __syncthreads();

    const int tr = t >> 4;
    const int tc = t & 15;

    float m[4], lsum[4], o[4][4];
    int lo[4];
#pragma unroll
    for (int i = 0; i < 4; i++) {
        m[i] = -1e30f; lsum[i] = 0.f;
        lo[i] = lo_s[tr * 4 + i];
#pragma unroll
        for (int jj = 0; jj < 4; jj++) o[i][jj] = 0.f;
    }

    const int kb0 = lo_s[0] & ~63;
    for (int kb = kb0; kb <= q0 + 63; kb += 64) {
        for (int i = t; i < 64 * 64; i += 256) {
            Ks[(i >> 6) * SP + (i & 63)] = Kg[(size_t)kb * 64 + i];
            Vs[(i >> 6) * SP + (i & 63)] = Vg[(size_t)kb * 64 + i];
        }
        __syncthreads();

        float s[4][4];
#pragma unroll
        for (int i = 0; i < 4; i++)
#pragma unroll
            for (int jj = 0; jj < 4; jj++) s[i][jj] = 0.f;

        for (int d = 0; d < 64; d++) {
            float qv[4], kv[4];
#pragma unroll
            for (int i = 0; i < 4; i++) qv[i] = Qs[(tr * 4 + i) * SP + d];
#pragma unroll
            for (int jj = 0; jj < 4; jj++) kv[jj] = Ks[(tc + jj * 16) * SP + d];
#pragma unroll
            for (int i = 0; i < 4; i++)
#pragma unroll
                for (int jj = 0; jj < 4; jj++) s[i][jj] += qv[i] * kv[jj];
        }

#pragma unroll
        for (int i = 0; i < 4; i++) {
            const int qg = q0 + tr * 4 + i;
            float rmax = -1e30f;
#pragma unroll
            for (int jj = 0; jj < 4; jj++) {
                const int kg = kb + tc + jj * 16;
                if (kg < lo[i] || kg > qg) s[i][jj] = -1e30f;
                rmax = fmaxf(rmax, s[i][jj]);
            }
#pragma unroll
            for (int sh = 8; sh; sh >>= 1)
                rmax = fmaxf(rmax, __shfl_xor_sync(0xffffffffu, rmax, sh, 16));
            const float mn = fmaxf(m[i], rmax);
            const float alpha = __expf(m[i] - mn);
            float lpart = 0.f;
#pragma unroll
            for (int jj = 0; jj < 4; jj++) {
                const float p = (s[i][jj] > -1e29f) ? __expf(s[i][jj] - mn) : 0.f;
                Ps[(tr * 4 + i) * SP + tc + jj * 16] = p;
                lpart += p;
            }
#pragma unroll
            for (int sh = 8; sh; sh >>= 1)
                lpart += __shfl_xor_sync(0xffffffffu, lpart, sh, 16);
            lsum[i] = lsum[i] * alpha + lpart;
            m[i] = mn;
#pragma unroll
            for (int jj = 0; jj < 4; jj++) o[i][jj] *= alpha;
        }
        __syncthreads();

        for (int kj = 0; kj < 64; kj++) {
            float pv[4], vv[4];
#pragma unroll
            for (int i = 0; i < 4; i++) pv[i] = Ps[(tr * 4 + i) * SP + kj];
#pragma unroll
            for (int jj = 0; jj < 4; jj++) vv[jj] = Vs[kj * SP + tc + jj * 16];
#pragma unroll
            for (int i = 0; i < 4; i++)
#pragma unroll
                for (int jj = 0; jj < 4; jj++) o[i][jj] += pv[i] * vv[jj];
        }
        __syncthreads();
    }

#pragma unroll
    for (int i = 0; i < 4; i++) {
        const float invl = 1.0f / lsum[i];
        const int qg = q0 + tr * 4 + i;
        float* yr = g_y + ((size_t)(b * LL) + qg) * DD + h * HD;
#pragma unroll
        for (int jj = 0; jj < 4; jj++) yr[tc + jj * 16] = o[i][jj] * invl;
    }
}

// ---------------- launch ----------------
extern "C" void kernel_launch(void* const* d_in, const int* in_sizes, int n_in,
                              void* d_out, int out_size) {
    const float* x     = (const float*)d_in[0];
    const float* w_qkv = (const float*)d_in[1];
    const float* w_out = (const float*)d_in[2];
    const void*  mask  = d_in[3];
    float* out = (float*)d_out;

    float *ph, *pqkv, *py;
    cudaGetSymbolAddress((void**)&ph, g_h);
    cudaGetSymbolAddress((void**)&pqkv, g_qkv);
    cudaGetSymbolAddress((void**)&py, g_y);

    const int M = BB * LL;

    seg_kernel<<<BB, 1024>>>(mask);
    rmsnorm_kernel<<<M, 256>>>(x);
    mma_gemm_kernel<0><<<dim3(QKV_DIM / 128, M / 128), 256>>>(ph, w_qkv, nullptr, pqkv,
                                                              M, QKV_DIM, DD);
    qkrope_kernel<<<M, 384>>>();

    const size_t attn_smem = 4 * 64 * SP * sizeof(float);
    cudaFuncSetAttribute(attn_kernel, cudaFuncAttributeMaxDynamicSharedMemorySize,
                         (int)attn_smem);
    attn_kernel<<<dim3(LL / 64, NH, BB), 256, attn_smem>>>();

    mma_gemm_kernel<1><<<dim3(DD / 128, M / 128), 256>>>(py, w_out, x, out,
                                                         M, DD, DD);
}

// round 3
// speedup vs baseline: 2.1470x; 1.0100x over previous
#include <cuda_runtime.h>
#include <math.h>
#include <stdint.h>

#define BB 2
#define LL 2048
#define DD 1024
#define NH 16
#define NKV 4
#define HD 64
#define WIN 1024
#define QKV_DIM 1536
#define EPSV 1.1920929e-07f

// ---------------- scratch (no cudaMalloc allowed) ----------------
__device__ float g_h[BB * LL * DD];          // rmsnorm(x)
__device__ float g_qkv[BB * LL * QKV_DIM];   // qkv projection
__device__ float g_q[BB * NH * LL * HD];     // q (normed, roped, pre-scaled)
__device__ float g_k[BB * NKV * LL * HD];    // k (normed, roped)
__device__ float g_v[BB * NKV * LL * HD];    // v
__device__ float g_y[BB * LL * DD];          // attention output
__device__ int   g_lo[BB * LL];              // first valid key per query

// ---------------- kernel 0: segment scan -> lo[i] ----------------
__global__ void seg_kernel(const void* __restrict__ mask) {
    __shared__ int s0[LL];
    __shared__ int s1[LL];
    __shared__ int enc;  // 0=int32, 1=byte, 2=float
    const int b = blockIdx.x;
    const int t = threadIdx.x;  // 1024 threads

    if (t == 0) {
        const unsigned* mi = (const unsigned*)mask;
        int e = 0;
        for (int i = 0; i < 64; i++) {
            unsigned v = mi[i];
            if (v == 0x3F800000u) { e = 2; break; }
            if (v > 1u) e = 1;
        }
        enc = e;
    }
    __syncthreads();
    const int e = enc;

    for (int i = t; i < LL; i += 1024) {
        int mset;
        if (e == 0)      mset = ((const int*)mask)[b * LL + i] != 0;
        else if (e == 1) mset = ((const unsigned char*)mask)[b * LL + i] != 0;
        else             mset = ((const float*)mask)[b * LL + i] != 0.0f;
        s0[i] = mset ? i : 0;
    }
    __syncthreads();

    int* src = s0;
    int* dst = s1;
    for (int off = 1; off < LL; off <<= 1) {
        for (int i = t; i < LL; i += 1024) {
            int v = src[i];
            if (i >= off) v = max(v, src[i - off]);
            dst[i] = v;
        }
        __syncthreads();
        int* tmp = src; src = dst; dst = tmp;
    }
    for (int i = t; i < LL; i += 1024) {
        g_lo[b * LL + i] = max(i - (WIN - 1), src[i]);
    }
}

// ---------------- kernel 1: rmsnorm over D ----------------
__global__ void __launch_bounds__(256) rmsnorm_kernel(const float* __restrict__ x) {
    const int row = blockIdx.x;
    const float* xr = x + (size_t)row * DD;
    float* hr = g_h + (size_t)row * DD;
    const int t = threadIdx.x;

    float v[4];
    float ss = 0.f;
#pragma unroll
    for (int i = 0; i < 4; i++) { v[i] = xr[t + i * 256]; ss += v[i] * v[i]; }

    __shared__ float red[8];
#pragma unroll
    for (int m = 16; m; m >>= 1) ss += __shfl_xor_sync(0xffffffffu, ss, m);
    if ((t & 31) == 0) red[t >> 5] = ss;
    __syncthreads();
    if (t < 8) {
        float r = red[t];
#pragma unroll
        for (int m = 4; m; m >>= 1) r += __shfl_xor_sync(0xffu, r, m, 8);
        if (t == 0) red[0] = r;
    }
    __syncthreads();
    const float inv = rsqrtf(red[0] * (1.0f / DD) + EPSV);
#pragma unroll
    for (int i = 0; i < 4; i++) hr[t + i * 256] = v[i] * inv;
}

// ---------------- tf32 tensor-core GEMM, cp.async 3-stage pipeline ----------------
// C = A @ W^T (+res). A [M,K] rm, W [N,K] rm. 128x128 tile, BK=16,
// 8 warps 2x4, warp tile 64x32. smem row-major fp32 stride 20 (conflict-free).
__device__ __forceinline__ uint32_t f2tf32(float x) {
    uint32_t r;
    asm("cvt.rna.tf32.f32 %0, %1;" : "=r"(r) : "f"(x));
    return r;
}

__device__ __forceinline__ void mma_tf32(float* c, const uint32_t* a, const uint32_t* b) {
    asm volatile(
        "mma.sync.aligned.m16n8k8.row.col.f32.tf32.tf32.f32 "
        "{%0,%1,%2,%3}, {%4,%5,%6,%7}, {%8,%9}, {%0,%1,%2,%3};\n"
        : "+f"(c[0]), "+f"(c[1]), "+f"(c[2]), "+f"(c[3])
        : "r"(a[0]), "r"(a[1]), "r"(a[2]), "r"(a[3]), "r"(b[0]), "r"(b[1]));
}

__device__ __forceinline__ void cp16(void* smem_dst, const void* gsrc) {
    uint32_t s;
    asm("{ .reg .u64 t; cvta.to.shared.u64 t, %1; cvt.u32.u64 %0, t; }"
        : "=r"(s) : "l"(smem_dst));
    asm volatile("cp.async.cg.shared.global [%0], [%1], 16;\n" :: "r"(s), "l"(gsrc));
}
__device__ __forceinline__ void cp_commit() {
    asm volatile("cp.async.commit_group;\n");
}
template <int N>
__device__ __forceinline__ void cp_wait() {
    asm volatile("cp.async.wait_group %0;\n" :: "n"(N));
}

#define SSTR 20           // smem row stride (floats)
#define NSTG 3            // pipeline stages
#define STG_F (128 * SSTR)  // floats per stage per operand

template <int RES>
__global__ void __launch_bounds__(256) mma_gemm_kernel(
    const float* __restrict__ A, const float* __restrict__ W,
    const float* __restrict__ res, float* __restrict__ C,
    int M, int N, int K)
{
    extern __shared__ float sm[];
    float* As = sm;                    // [NSTG][128][SSTR]
    float* Bs = sm + NSTG * STG_F;

    const int tid = threadIdx.x;
    const int lane = tid & 31;
    const int wid = tid >> 5;
    const int wm = (wid & 1) * 64;
    const int wn = (wid >> 1) * 32;
    const int m0 = blockIdx.y * 128;
    const int n0 = blockIdx.x * 128;

    // loader: 128 rows x 16 k; 2 float4 per thread per operand
    const int lr = tid >> 1;
    const int lc = (tid & 1) << 3;     // 0 or 8
    const float* Ap = A + (size_t)(m0 + lr) * K + lc;
    const float* Wp = W + (size_t)(n0 + lr) * K + lc;

    float acc[4][4][4];
#pragma unroll
    for (int i = 0; i < 4; i++)
#pragma unroll
        for (int j = 0; j < 4; j++)
#pragma unroll
            for (int r = 0; r < 4; r++) acc[i][j][r] = 0.f;

    const int g = lane >> 2;
    const int tg = lane & 3;
    const int kiters = K >> 4;

    // preload stages 0..NSTG-2
#pragma unroll
    for (int s = 0; s < NSTG - 1; s++) {
        const int koff = s << 4;
        float* as = As + s * STG_F + lr * SSTR + lc;
        float* bs = Bs + s * STG_F + lr * SSTR + lc;
        cp16(as, Ap + koff);
        cp16(as + 4, Ap + koff + 4);
        cp16(bs, Wp + koff);
        cp16(bs + 4, Wp + koff + 4);
        cp_commit();
    }

    for (int it = 0; it < kiters; it++) {
        cp_wait<NSTG - 2>();
        __syncthreads();

        // prefetch stage it+NSTG-1
        const int pf = it + NSTG - 1;
        if (pf < kiters) {
            const int s = pf % NSTG;
            const int koff = pf << 4;
            float* as = As + s * STG_F + lr * SSTR + lc;
            float* bs = Bs + s * STG_F + lr * SSTR + lc;
            cp16(as, Ap + koff);
            cp16(as + 4, Ap + koff + 4);
            cp16(bs, Wp + koff);
            cp16(bs + 4, Wp + koff + 4);
        }
        cp_commit();

        const float* as = As + (it % NSTG) * STG_F;
        const float* bs = Bs + (it % NSTG) * STG_F;

#pragma unroll
        for (int ks = 0; ks < 16; ks += 8) {
            uint32_t afr[4][4];
            uint32_t bfr[4][2];
#pragma unroll
            for (int mi = 0; mi < 4; mi++) {
                const int row = wm + mi * 16 + g;
                afr[mi][0] = f2tf32(as[row * SSTR + ks + tg]);
                afr[mi][1] = f2tf32(as[(row + 8) * SSTR + ks + tg]);
                afr[mi][2] = f2tf32(as[row * SSTR + ks + tg + 4]);
                afr[mi][3] = f2tf32(as[(row + 8) * SSTR + ks + tg + 4]);
            }
#pragma unroll
            for (int ni = 0; ni < 4; ni++) {
                const int col = wn + ni * 8 + g;
                bfr[ni][0] = f2tf32(bs[col * SSTR + ks + tg]);
                bfr[ni][1] = f2tf32(bs[col * SSTR + ks + tg + 4]);
            }
#pragma unroll
            for (int mi = 0; mi < 4; mi++)
#pragma unroll
                for (int ni = 0; ni < 4; ni++)
                    mma_tf32(acc[mi][ni], afr[mi], bfr[ni]);
        }
        __syncthreads();
    }

    // epilogue
#pragma unroll
    for (int mi = 0; mi < 4; mi++) {
#pragma unroll
        for (int ni = 0; ni < 4; ni++) {
            const int row = m0 + wm + mi * 16 + g;
            const int col = n0 + wn + ni * 8 + (tg << 1);
            float2 v0 = make_float2(acc[mi][ni][0], acc[mi][ni][1]);
            float2 v1 = make_float2(acc[mi][ni][2], acc[mi][ni][3]);
            if (RES) {
                const float2 r0 = *(const float2*)(res + (size_t)row * N + col);
                const float2 r1 = *(const float2*)(res + (size_t)(row + 8) * N + col);
                v0.x += r0.x; v0.y += r0.y;
                v1.x += r1.x; v1.y += r1.y;
            }
            *(float2*)(C + (size_t)row * N + col) = v0;
            *(float2*)(C + (size_t)(row + 8) * N + col) = v1;
        }
    }
}

// ---------------- kernel 3: per-head rmsnorm + rope + scatter ----------------
__global__ void __launch_bounds__(384) qkrope_kernel() {
    const int row = blockIdx.x;
    const int b = row / LL;
    const int l = row % LL;
    const int t = threadIdx.x;
    const int head = t >> 4;
    const int tl = t & 15;
    const int j = tl * 2;

    const float* src = g_qkv + (size_t)row * QKV_DIM + head * 64;

    if (head < 20) {
        float a0 = src[j], a1 = src[j + 1];
        float b0 = src[j + 32], b1 = src[j + 33];
        float ss = a0 * a0 + a1 * a1 + b0 * b0 + b1 * b1;
#pragma unroll
        for (int m = 8; m; m >>= 1) ss += __shfl_xor_sync(0xffffffffu, ss, m, 16);
        const float inv = rsqrtf(ss * (1.0f / HD) + EPSV);
        a0 *= inv; a1 *= inv; b0 *= inv; b1 *= inv;

        const float lg = logf(10000.0f) * (1.0f / 32.0f);
        const float f0 = expf(-lg * (float)j);
        const float f1 = expf(-lg * (float)(j + 1));
        float s0, c0, s1, c1;
        sincosf((float)l * f0, &s0, &c0);
        sincosf((float)l * f1, &s1, &c1);
        const float o0 = a0 * c0 - b0 * s0;
        const float o1 = a1 * c1 - b1 * s1;
        const float o2 = a0 * s0 + b0 * c0;
        const float o3 = a1 * s1 + b1 * c1;

        if (head < 16) {
            const float sc = 0.125f;
            float* dq = g_q + (((size_t)(b * NH + head)) * LL + l) * HD;
            dq[j] = o0 * sc; dq[j + 1] = o1 * sc;
            dq[j + 32] = o2 * sc; dq[j + 33] = o3 * sc;
        } else {
            float* dk = g_k + (((size_t)(b * NKV + (head - 16))) * LL + l) * HD;
            dk[j] = o0; dk[j + 1] = o1;
            dk[j + 32] = o2; dk[j + 33] = o3;
        }
    } else {
        float* dv = g_v + (((size_t)(b * NKV + (head - 20))) * LL + l) * HD;
        dv[j] = src[j]; dv[j + 1] = src[j + 1];
        dv[j + 32] = src[j + 32]; dv[j + 33] = src[j + 33];
    }
}

// ---------------- kernel 4: flash attention over contiguous valid range ----------------
#define SP 65
__global__ void __launch_bounds__(256) attn_kernel() {
    extern __shared__ float sm[];
    float* Qs = sm;
    float* Ks = Qs + 64 * SP;
    float* Vs = Ks + 64 * SP;
    float* Ps = Vs + 64 * SP;
    __shared__ int lo_s[64];

    const int qb = blockIdx.x, h = blockIdx.y, b = blockIdx.z;
    const int t = threadIdx.x;
    const int q0 = qb * 64;
    const int kvh = h >> 2;
    const float* Qg = g_q + (((size_t)(b * NH + h)) * LL + q0) * HD;
    const float* Kg = g_k + ((size_t)(b * NKV + kvh)) * LL * HD;
    const float* Vg = g_v + ((size_t)(b * NKV + kvh)) * LL * HD;

    for (int i = t; i < 64 * 64; i += 256) {
        Qs[(i >> 6) * SP + (i & 63)] = Qg[i];
    }
    if (t < 64) lo_s[t] = g_lo[b * LL + q0 + t];
    __syncthreads();

    const int tr = t >> 4;
    const int tc = t & 15;

    float m[4], lsum[4], o[4][4];
    int lo[4];
#pragma unroll
    for (int i = 0; i < 4; i++) {
        m[i] = -1e30f; lsum[i] = 0.f;
        lo[i] = lo_s[tr * 4 + i];
#pragma unroll
        for (int jj = 0; jj < 4; jj++) o[i][jj] = 0.f;
    }

    const int kb0 = lo_s[0] & ~63;
    for (int kb = kb0; kb <= q0 + 63; kb += 64) {
        for (int i = t; i < 64 * 64; i += 256) {
            Ks[(i >> 6) * SP + (i & 63)] = Kg[(size_t)kb * 64 + i];
            Vs[(i >> 6) * SP + (i & 63)] = Vg[(size_t)kb * 64 + i];
        }
        __syncthreads();

        float s[4][4];
#pragma unroll
        for (int i = 0; i < 4; i++)
#pragma unroll
            for (int jj = 0; jj < 4; jj++) s[i][jj] = 0.f;

        for (int d = 0; d < 64; d++) {
            float qv[4], kv[4];
#pragma unroll
            for (int i = 0; i < 4; i++) qv[i] = Qs[(tr * 4 + i) * SP + d];
#pragma unroll
            for (int jj = 0; jj < 4; jj++) kv[jj] = Ks[(tc + jj * 16) * SP + d];
#pragma unroll
            for (int i = 0; i < 4; i++)
#pragma unroll
                for (int jj = 0; jj < 4; jj++) s[i][jj] += qv[i] * kv[jj];
        }

#pragma unroll
        for (int i = 0; i < 4; i++) {
            const int qg = q0 + tr * 4 + i;
            float rmax = -1e30f;
#pragma unroll
            for (int jj = 0; jj < 4; jj++) {
                const int kg = kb + tc + jj * 16;
                if (kg < lo[i] || kg > qg) s[i][jj] = -1e30f;
                rmax = fmaxf(rmax, s[i][jj]);
            }
#pragma unroll
            for (int sh = 8; sh; sh >>= 1)
                rmax = fmaxf(rmax, __shfl_xor_sync(0xffffffffu, rmax, sh, 16));
            const float mn = fmaxf(m[i], rmax);
            const float alpha = __expf(m[i] - mn);
            float lpart = 0.f;
#pragma unroll
            for (int jj = 0; jj < 4; jj++) {
                const float p = (s[i][jj] > -1e29f) ? __expf(s[i][jj] - mn) : 0.f;
                Ps[(tr * 4 + i) * SP + tc + jj * 16] = p;
                lpart += p;
            }
#pragma unroll
            for (int sh = 8; sh; sh >>= 1)
                lpart += __shfl_xor_sync(0xffffffffu, lpart, sh, 16);
            lsum[i] = lsum[i] * alpha + lpart;
            m[i] = mn;
#pragma unroll
            for (int jj = 0; jj < 4; jj++) o[i][jj] *= alpha;
        }
        __syncthreads();

        for (int kj = 0; kj < 64; kj++) {
            float pv[4], vv[4];
#pragma unroll
            for (int i = 0; i < 4; i++) pv[i] = Ps[(tr * 4 + i) * SP + kj];
#pragma unroll
            for (int jj = 0; jj < 4; jj++) vv[jj] = Vs[kj * SP + tc + jj * 16];
#pragma unroll
            for (int i = 0; i < 4; i++)
#pragma unroll
                for (int jj = 0; jj < 4; jj++) o[i][jj] += pv[i] * vv[jj];
        }
        __syncthreads();
    }

#pragma unroll
    for (int i = 0; i < 4; i++) {
        const float invl = 1.0f / lsum[i];
        const int qg = q0 + tr * 4 + i;
        float* yr = g_y + ((size_t)(b * LL) + qg) * DD + h * HD;
#pragma unroll
        for (int jj = 0; jj < 4; jj++) yr[tc + jj * 16] = o[i][jj] * invl;
    }
}

// ---------------- launch ----------------
extern "C" void kernel_launch(void* const* d_in, const int* in_sizes, int n_in,
                              void* d_out, int out_size) {
    const float* x     = (const float*)d_in[0];
    const float* w_qkv = (const float*)d_in[1];
    const float* w_out = (const float*)d_in[2];
    const void*  mask  = d_in[3];
    float* out = (float*)d_out;

    float *ph, *pqkv, *py;
    cudaGetSymbolAddress((void**)&ph, g_h);
    cudaGetSymbolAddress((void**)&pqkv, g_qkv);
    cudaGetSymbolAddress((void**)&py, g_y);

    const int M = BB * LL;
    const size_t gemm_smem = 2u * NSTG * STG_F * sizeof(float);  // ~61 KB

    cudaFuncSetAttribute(mma_gemm_kernel<0>, cudaFuncAttributeMaxDynamicSharedMemorySize,
                         (int)gemm_smem);
    cudaFuncSetAttribute(mma_gemm_kernel<1>, cudaFuncAttributeMaxDynamicSharedMemorySize,
                         (int)gemm_smem);

    seg_kernel<<<BB, 1024>>>(mask);
    rmsnorm_kernel<<<M, 256>>>(x);
    mma_gemm_kernel<0><<<dim3(QKV_DIM / 128, M / 128), 256, gemm_smem>>>(
        ph, w_qkv, nullptr, pqkv, M, QKV_DIM, DD);
    qkrope_kernel<<<M, 384>>>();

    const size_t attn_smem = 4 * 64 * SP * sizeof(float);
    cudaFuncSetAttribute(attn_kernel, cudaFuncAttributeMaxDynamicSharedMemorySize,
                         (int)attn_smem);
    attn_kernel<<<dim3(LL / 64, NH, BB), 256, attn_smem>>>();

    mma_gemm_kernel<1><<<dim3(DD / 128, M / 128), 256, gemm_smem>>>(
        py, w_out, x, out, M, DD, DD);
}

// round 5
// speedup vs baseline: 3.7258x; 1.7354x over previous
#include <cuda_runtime.h>
#include <cuda_fp16.h>
#include <math.h>
#include <stdint.h>

#define BB 2
#define LL 2048
#define DD 1024
#define NH 16
#define NKV 4
#define HD 64
#define WIN 1024
#define QKV_DIM 1536
#define EPSV 1.1920929e-07f

// ---------------- scratch (no cudaMalloc allowed) ----------------
__device__ __half g_hh[BB * LL * DD];        // rmsnorm(x) in fp16
__device__ __half g_wqkvh[QKV_DIM * DD];     // w_qkv fp16
__device__ __half g_wouth[DD * DD];          // w_out fp16
__device__ __half g_yh[BB * LL * DD];        // attention out fp16
__device__ float g_qkv[BB * LL * QKV_DIM];   // qkv projection (fp32)
__device__ float g_q[BB * NH * LL * HD];
__device__ float g_k[BB * NKV * LL * HD];
__device__ float g_v[BB * NKV * LL * HD];
__device__ int   g_lo[BB * LL];

// ---------------- ptx helpers ----------------
__device__ __forceinline__ uint32_t smem_u32(const void* p) {
    uint32_t a;
    asm("{ .reg .u64 t; cvta.to.shared.u64 t, %1; cvt.u32.u64 %0, t; }"
        : "=r"(a) : "l"(p));
    return a;
}
__device__ __forceinline__ void cp16(uint32_t smem_dst, const void* gsrc) {
    asm volatile("cp.async.cg.shared.global [%0], [%1], 16;\n"
                 :: "r"(smem_dst), "l"(gsrc));
}
__device__ __forceinline__ void cp_commit() {
    asm volatile("cp.async.commit_group;\n");
}
template <int N>
__device__ __forceinline__ void cp_wait() {
    asm volatile("cp.async.wait_group %0;\n" :: "n"(N));
}
__device__ __forceinline__ void ldsm4(uint32_t& r0, uint32_t& r1,
                                      uint32_t& r2, uint32_t& r3, uint32_t addr) {
    asm volatile("ldmatrix.sync.aligned.m8n8.x4.shared.b16 {%0,%1,%2,%3}, [%4];"
                 : "=r"(r0), "=r"(r1), "=r"(r2), "=r"(r3) : "r"(addr));
}
__device__ __forceinline__ void mma_f16(float* c, const uint32_t* a, const uint32_t* b) {
    asm volatile(
        "mma.sync.aligned.m16n8k16.row.col.f32.f16.f16.f32 "
        "{%0,%1,%2,%3}, {%4,%5,%6,%7}, {%8,%9}, {%0,%1,%2,%3};"
        : "+f"(c[0]), "+f"(c[1]), "+f"(c[2]), "+f"(c[3])
        : "r"(a[0]), "r"(a[1]), "r"(a[2]), "r"(a[3]), "r"(b[0]), "r"(b[1]));
}

// ---------------- kernel 0: segment scan -> lo[i] ----------------
__global__ void seg_kernel(const void* __restrict__ mask) {
    __shared__ int s0[LL];
    __shared__ int s1[LL];
    __shared__ int enc;
    const int b = blockIdx.x;
    const int t = threadIdx.x;

    if (t == 0) {
        const unsigned* mi = (const unsigned*)mask;
        int e = 0;
        for (int i = 0; i < 64; i++) {
            unsigned v = mi[i];
            if (v == 0x3F800000u) { e = 2; break; }
            if (v > 1u) e = 1;
        }
        enc = e;
    }
    __syncthreads();
    const int e = enc;

    for (int i = t; i < LL; i += 1024) {
        int mset;
        if (e == 0)      mset = ((const int*)mask)[b * LL + i] != 0;
        else if (e == 1) mset = ((const unsigned char*)mask)[b * LL + i] != 0;
        else             mset = ((const float*)mask)[b * LL + i] != 0.0f;
        s0[i] = mset ? i : 0;
    }
    __syncthreads();

    int* src = s0;
    int* dst = s1;
    for (int off = 1; off < LL; off <<= 1) {
        for (int i = t; i < LL; i += 1024) {
            int v = src[i];
            if (i >= off) v = max(v, src[i - off]);
            dst[i] = v;
        }
        __syncthreads();
        int* tmp = src; src = dst; dst = tmp;
    }
    for (int i = t; i < LL; i += 1024) {
        g_lo[b * LL + i] = max(i - (WIN - 1), src[i]);
    }
}

// ---------------- weight fp32 -> fp16 convert ----------------
__global__ void __launch_bounds__(256) conv_h_kernel(
    const float* __restrict__ s, __half* __restrict__ d, int n)
{
    const int i = (blockIdx.x * 256 + threadIdx.x) * 4;
    if (i < n) {
        float4 v = *(const float4*)(s + i);
        __half2 p0 = __floats2half2_rn(v.x, v.y);
        __half2 p1 = __floats2half2_rn(v.z, v.w);
        *(__half2*)(d + i) = p0;
        *(__half2*)(d + i + 2) = p1;
    }
}

// ---------------- kernel 1: rmsnorm over D -> fp16 ----------------
__global__ void __launch_bounds__(256) rmsnorm_kernel(const float* __restrict__ x) {
    const int row = blockIdx.x;
    const float* xr = x + (size_t)row * DD;
    __half* hr = g_hh + (size_t)row * DD;
    const int t = threadIdx.x;

    float v[4];
    float ss = 0.f;
#pragma unroll
    for (int i = 0; i < 4; i++) { v[i] = xr[t + i * 256]; ss += v[i] * v[i]; }

    __shared__ float red[8];
#pragma unroll
    for (int m = 16; m; m >>= 1) ss += __shfl_xor_sync(0xffffffffu, ss, m);
    if ((t & 31) == 0) red[t >> 5] = ss;
    __syncthreads();
    if (t < 8) {
        float r = red[t];
#pragma unroll
        for (int m = 4; m; m >>= 1) r += __shfl_xor_sync(0xffu, r, m, 8);
        if (t == 0) red[0] = r;
    }
    __syncthreads();
    const float inv = rsqrtf(red[0] * (1.0f / DD) + EPSV);
#pragma unroll
    for (int i = 0; i < 4; i++) hr[t + i * 256] = __float2half(v[i] * inv);
}

// ---------------- fp16 mma.sync GEMM: C = A @ W^T (+res) ----------------
// A [M,K] f16 rm, W [N,K] f16 rm. CTA tile 128x128, BK=64 (128B rows),
// XOR-swizzled smem, ldmatrix fragments, 3-stage cp.async pipeline.
// 256 threads = 8 warps (2m x 4n), warp tile 64x32.
#define NSTG 3
#define STG_B (128 * 128)   // bytes per stage per operand (16KB)
#define GSMEM (2 * NSTG * STG_B)

template <int RES>
__global__ void __launch_bounds__(256) hgemm_kernel(
    const __half* __restrict__ A, const __half* __restrict__ W,
    const float* __restrict__ res, float* __restrict__ C,
    int M, int N, int K)
{
    extern __shared__ char smem[];
    const uint32_t sb = smem_u32(smem);
    const uint32_t Asm = sb;
    const uint32_t Bsm = sb + NSTG * STG_B;

    const int t = threadIdx.x;
    const int lane = t & 31;
    const int wid = t >> 5;
    const int wm = (wid & 1) * 64;
    const int wn = (wid >> 1) * 32;
    const int m0 = blockIdx.y * 128;
    const int n0 = blockIdx.x * 128;

    // loader mapping: thread -> row t/2, 4 x 16B chunks at (t&1)*64 + i*16
    const int lrow = t >> 1;
    const int lcb0 = (t & 1) * 64;
    const int lswz = (lrow & 7) << 4;
    const char* Agb = (const char*)(A + (size_t)(m0 + lrow) * K);
    const char* Wgb = (const char*)(W + (size_t)(n0 + lrow) * K);
    const uint32_t arow = Asm + lrow * 128;
    const uint32_t brow = Bsm + lrow * 128;

    float acc[4][4][4];
#pragma unroll
    for (int i = 0; i < 4; i++)
#pragma unroll
        for (int j = 0; j < 4; j++)
#pragma unroll
            for (int r = 0; r < 4; r++) acc[i][j][r] = 0.f;

    // ldmatrix lane constants
    const int grp = lane >> 3;   // matrix index group
    const int li = lane & 7;
    uint32_t a_ro[4]; int a_sw[4];
    uint32_t b_ro[2]; int b_sw[2];
#pragma unroll
    for (int mi = 0; mi < 4; mi++) {
        const int r = wm + mi * 16 + li + (grp & 1) * 8;
        a_ro[mi] = r * 128;
        a_sw[mi] = (r & 7) << 4;
    }
#pragma unroll
    for (int nb = 0; nb < 2; nb++) {
        const int r = wn + nb * 16 + li + (grp >> 1) * 8;
        b_ro[nb] = r * 128;
        b_sw[nb] = (r & 7) << 4;
    }
    const int a_g16 = (grp >> 1) * 16;
    const int b_g16 = (grp & 1) * 16;

    const int nch = K >> 6;

    // preload stages 0..NSTG-2
#pragma unroll
    for (int s = 0; s < NSTG - 1; s++) {
#pragma unroll
        for (int i = 0; i < 4; i++) {
            const int cb = lcb0 + i * 16;
            cp16(arow + s * STG_B + (cb ^ lswz), Agb + s * 128 + cb);
            cp16(brow + s * STG_B + (cb ^ lswz), Wgb + s * 128 + cb);
        }
        cp_commit();
    }

    for (int c = 0; c < nch; c++) {
        cp_wait<NSTG - 2>();
        __syncthreads();

        const int pf = c + NSTG - 1;
        if (pf < nch) {
            const int s = pf % NSTG;
#pragma unroll
            for (int i = 0; i < 4; i++) {
                const int cb = lcb0 + i * 16;
                cp16(arow + s * STG_B + (cb ^ lswz), Agb + (size_t)pf * 128 + cb);
                cp16(brow + s * STG_B + (cb ^ lswz), Wgb + (size_t)pf * 128 + cb);
            }
        }
        cp_commit();

        const uint32_t as = Asm + (c % NSTG) * STG_B;
        const uint32_t bs = Bsm + (c % NSTG) * STG_B;

#pragma unroll
        for (int ks = 0; ks < 4; ks++) {
            uint32_t af[4][4], bf[2][4];
#pragma unroll
            for (int mi = 0; mi < 4; mi++)
                ldsm4(af[mi][0], af[mi][1], af[mi][2], af[mi][3],
                      as + a_ro[mi] + ((ks * 32 + a_g16) ^ a_sw[mi]));
#pragma unroll
            for (int nb = 0; nb < 2; nb++)
                ldsm4(bf[nb][0], bf[nb][1], bf[nb][2], bf[nb][3],
                      bs + b_ro[nb] + ((ks * 32 + b_g16) ^ b_sw[nb]));
#pragma unroll
            for (int mi = 0; mi < 4; mi++)
#pragma unroll
                for (int ni = 0; ni < 4; ni++)
                    mma_f16(acc[mi][ni], af[mi], &bf[ni >> 1][(ni & 1) * 2]);
        }
    }

    // epilogue from registers
    const int g = lane >> 2;
    const int tg = lane & 3;
#pragma unroll
    for (int mi = 0; mi < 4; mi++) {
#pragma unroll
        for (int ni = 0; ni < 4; ni++) {
            const int row = m0 + wm + mi * 16 + g;
            const int col = n0 + wn + ni * 8 + tg * 2;
            float2 v0 = make_float2(acc[mi][ni][0], acc[mi][ni][1]);
            float2 v1 = make_float2(acc[mi][ni][2], acc[mi][ni][3]);
            if (RES) {
                const float2 r0 = *(const float2*)(res + (size_t)row * N + col);
                const float2 r1 = *(const float2*)(res + (size_t)(row + 8) * N + col);
                v0.x += r0.x; v0.y += r0.y;
                v1.x += r1.x; v1.y += r1.y;
            }
            *(float2*)(C + (size_t)row * N + col) = v0;
            *(float2*)(C + (size_t)(row + 8) * N + col) = v1;
        }
    }
}

// ---------------- kernel 3: per-head rmsnorm + rope + scatter ----------------
__global__ void __launch_bounds__(384) qkrope_kernel() {
    const int row = blockIdx.x;
    const int b = row / LL;
    const int l = row % LL;
    const int t = threadIdx.x;
    const int head = t >> 4;
    const int tl = t & 15;
    const int j = tl * 2;

    const float* src = g_qkv + (size_t)row * QKV_DIM + head * 64;

    if (head < 20) {
        float a0 = src[j], a1 = src[j + 1];
        float b0 = src[j + 32], b1 = src[j + 33];
        float ss = a0 * a0 + a1 * a1 + b0 * b0 + b1 * b1;
#pragma unroll
        for (int m = 8; m; m >>= 1) ss += __shfl_xor_sync(0xffffffffu, ss, m, 16);
        const float inv = rsqrtf(ss * (1.0f / HD) + EPSV);
        a0 *= inv; a1 *= inv; b0 *= inv; b1 *= inv;

        const float lg = logf(10000.0f) * (1.0f / 32.0f);
        const float f0 = expf(-lg * (float)j);
        const float f1 = expf(-lg * (float)(j + 1));
        float s0, c0, s1, c1;
        sincosf((float)l * f0, &s0, &c0);
        sincosf((float)l * f1, &s1, &c1);
        const float o0 = a0 * c0 - b0 * s0;
        const float o1 = a1 * c1 - b1 * s1;
        const float o2 = a0 * s0 + b0 * c0;
        const float o3 = a1 * s1 + b1 * c1;

        if (head < 16) {
            const float sc = 0.125f;
            float* dq = g_q + (((size_t)(b * NH + head)) * LL + l) * HD;
            dq[j] = o0 * sc; dq[j + 1] = o1 * sc;
            dq[j + 32] = o2 * sc; dq[j + 33] = o3 * sc;
        } else {
            float* dk = g_k + (((size_t)(b * NKV + (head - 16))) * LL + l) * HD;
            dk[j] = o0; dk[j + 1] = o1;
            dk[j + 32] = o2; dk[j + 33] = o3;
        }
    } else {
        float* dv = g_v + (((size_t)(b * NKV + (head - 20))) * LL + l) * HD;
        dv[j] = src[j]; dv[j + 1] = src[j + 1];
        dv[j + 32] = src[j + 32]; dv[j + 33] = src[j + 33];
    }
}

// ---------------- kernel 4: flash attention -> fp16 y ----------------
#define SP 65
__global__ void __launch_bounds__(256) attn_kernel() {
    extern __shared__ float sm[];
    float* Qs = sm;
    float* Ks = Qs + 64 * SP;
    float* Vs = Ks + 64 * SP;
    float* Ps = Vs + 64 * SP;
    __shared__ int lo_s[64];

    const int qb = blockIdx.x, h = blockIdx.y, b = blockIdx.z;
    const int t = threadIdx.x;
    const int q0 = qb * 64;
    const int kvh = h >> 2;
    const float* Qg = g_q + (((size_t)(b * NH + h)) * LL + q0) * HD;
    const float* Kg = g_k + ((size_t)(b * NKV + kvh)) * LL * HD;
    const float* Vg = g_v + ((size_t)(b * NKV + kvh)) * LL * HD;

    for (int i = t; i < 64 * 64; i += 256) {
        Qs[(i >> 6) * SP + (i & 63)] = Qg[i];
    }
    if (t < 64) lo_s[t] = g_lo[b * LL + q0 + t];
    __syncthreads();

    const int tr = t >> 4;
    const int tc = t & 15;

    float m[4], lsum[4], o[4][4];
    int lo[4];
#pragma unroll
    for (int i = 0; i < 4; i++) {
        m[i] = -1e30f; lsum[i] = 0.f;
        lo[i] = lo_s[tr * 4 + i];
#pragma unroll
        for (int jj = 0; jj < 4; jj++) o[i][jj] = 0.f;
    }

    const int kb0 = lo_s[0] & ~63;
    for (int kb = kb0; kb <= q0 + 63; kb += 64) {
        for (int i = t; i < 64 * 64; i += 256) {
            Ks[(i >> 6) * SP + (i & 63)] = Kg[(size_t)kb * 64 + i];
            Vs[(i >> 6) * SP + (i & 63)] = Vg[(size_t)kb * 64 + i];
        }
        __syncthreads();

        float s[4][4];
#pragma unroll
        for (int i = 0; i < 4; i++)
#pragma unroll
            for (int jj = 0; jj < 4; jj++) s[i][jj] = 0.f;

        for (int d = 0; d < 64; d++) {
            float qv[4], kv[4];
#pragma unroll
            for (int i = 0; i < 4; i++) qv[i] = Qs[(tr * 4 + i) * SP + d];
#pragma unroll
            for (int jj = 0; jj < 4; jj++) kv[jj] = Ks[(tc + jj * 16) * SP + d];
#pragma unroll
            for (int i = 0; i < 4; i++)
#pragma unroll
                for (int jj = 0; jj < 4; jj++) s[i][jj] += qv[i] * kv[jj];
        }

#pragma unroll
        for (int i = 0; i < 4; i++) {
            const int qg = q0 + tr * 4 + i;
            float rmax = -1e30f;
#pragma unroll
            for (int jj = 0; jj < 4; jj++) {
                const int kg = kb + tc + jj * 16;
                if (kg < lo[i] || kg > qg) s[i][jj] = -1e30f;
                rmax = fmaxf(rmax, s[i][jj]);
            }
#pragma unroll
            for (int sh = 8; sh; sh >>= 1)
                rmax = fmaxf(rmax, __shfl_xor_sync(0xffffffffu, rmax, sh, 16));
            const float mn = fmaxf(m[i], rmax);
            const float alpha = __expf(m[i] - mn);
            float lpart = 0.f;
#pragma unroll
            for (int jj = 0; jj < 4; jj++) {
                const float p = (s[i][jj] > -1e29f) ? __expf(s[i][jj] - mn) : 0.f;
                Ps[(tr * 4 + i) * SP + tc + jj * 16] = p;
                lpart += p;
            }
#pragma unroll
            for (int sh = 8; sh; sh >>= 1)
                lpart += __shfl_xor_sync(0xffffffffu, lpart, sh, 16);
            lsum[i] = lsum[i] * alpha + lpart;
            m[i] = mn;
#pragma unroll
            for (int jj = 0; jj < 4; jj++) o[i][jj] *= alpha;
        }
        __syncthreads();

        for (int kj = 0; kj < 64; kj++) {
            float pv[4], vv[4];
#pragma unroll
            for (int i = 0; i < 4; i++) pv[i] = Ps[(tr * 4 + i) * SP + kj];
#pragma unroll
            for (int jj = 0; jj < 4; jj++) vv[jj] = Vs[kj * SP + tc + jj * 16];
#pragma unroll
            for (int i = 0; i < 4; i++)
#pragma unroll
                for (int jj = 0; jj < 4; jj++) o[i][jj] += pv[i] * vv[jj];
        }
        __syncthreads();
    }

#pragma unroll
    for (int i = 0; i < 4; i++) {
        const float invl = 1.0f / lsum[i];
        const int qg = q0 + tr * 4 + i;
        __half* yr = g_yh + ((size_t)(b * LL) + qg) * DD + h * HD;
#pragma unroll
        for (int jj = 0; jj < 4; jj++)
            yr[tc + jj * 16] = __float2half(o[i][jj] * invl);
    }
}

// ---------------- launch ----------------
extern "C" void kernel_launch(void* const* d_in, const int* in_sizes, int n_in,
                              void* d_out, int out_size) {
    const float* x     = (const float*)d_in[0];
    const float* w_qkv = (const float*)d_in[1];
    const float* w_out = (const float*)d_in[2];
    const void*  mask  = d_in[3];
    float* out = (float*)d_out;

    __half *phh, *pwqh, *pwoh, *pyh;
    float *pqkv;
    cudaGetSymbolAddress((void**)&phh, g_hh);
    cudaGetSymbolAddress((void**)&pwqh, g_wqkvh);
    cudaGetSymbolAddress((void**)&pwoh, g_wouth);
    cudaGetSymbolAddress((void**)&pyh, g_yh);
    cudaGetSymbolAddress((void**)&pqkv, g_qkv);

    const int M = BB * LL;

    cudaFuncSetAttribute(hgemm_kernel<0>,
                         cudaFuncAttributeMaxDynamicSharedMemorySize, GSMEM);
    cudaFuncSetAttribute(hgemm_kernel<1>,
                         cudaFuncAttributeMaxDynamicSharedMemorySize, GSMEM);

    seg_kernel<<<BB, 1024>>>(mask);
    conv_h_kernel<<<(QKV_DIM * DD / 4 + 255) / 256, 256>>>(w_qkv, pwqh, QKV_DIM * DD);
    conv_h_kernel<<<(DD * DD / 4 + 255) / 256, 256>>>(w_out, pwoh, DD * DD);
    rmsnorm_kernel<<<M, 256>>>(x);

    hgemm_kernel<0><<<dim3(QKV_DIM / 128, M / 128), 256, GSMEM>>>(
        phh, pwqh, nullptr, pqkv, M, QKV_DIM, DD);

    qkrope_kernel<<<M, 384>>>();

    const size_t attn_smem = 4 * 64 * SP * sizeof(float);
    cudaFuncSetAttribute(attn_kernel, cudaFuncAttributeMaxDynamicSharedMemorySize,
                         (int)attn_smem);
    attn_kernel<<<dim3(LL / 64, NH, BB), 256, attn_smem>>>();

    hgemm_kernel<1><<<dim3(DD / 128, M / 128), 256, GSMEM>>>(
        pyh, pwoh, x, out, M, DD, DD);
}

// round 6
// speedup vs baseline: 5.1762x; 1.3893x over previous
#include <cuda_runtime.h>
#include <cuda_fp16.h>
#include <math.h>
#include <stdint.h>

#define BB 2
#define LL 2048
#define DD 1024
#define NH 16
#define NKV 4
#define HD 64
#define WIN 1024
#define QKV_DIM 1536
#define EPSV 1.1920929e-07f

// ---------------- scratch (no cudaMalloc allowed) ----------------
__device__ __half g_hh[BB * LL * DD];        // rmsnorm(x) in fp16
__device__ __half g_wqkvh[QKV_DIM * DD];     // w_qkv fp16
__device__ __half g_wouth[DD * DD];          // w_out fp16
__device__ __half g_yh[BB * LL * DD];        // attention out fp16
__device__ float g_qkv[BB * LL * QKV_DIM];   // qkv projection (fp32)
__device__ __half g_qh[BB * NH * LL * HD];   // q fp16 (normed, roped, pre-scaled)
__device__ __half g_kh[BB * NKV * LL * HD];  // k fp16
__device__ __half g_vh[BB * NKV * LL * HD];  // v fp16
__device__ int   g_lo[BB * LL];

// ---------------- ptx helpers ----------------
__device__ __forceinline__ uint32_t smem_u32(const void* p) {
    uint32_t a;
    asm("{ .reg .u64 t; cvta.to.shared.u64 t, %1; cvt.u32.u64 %0, t; }"
        : "=r"(a) : "l"(p));
    return a;
}
__device__ __forceinline__ void cp16(uint32_t smem_dst, const void* gsrc) {
    asm volatile("cp.async.cg.shared.global [%0], [%1], 16;\n"
                 :: "r"(smem_dst), "l"(gsrc));
}
__device__ __forceinline__ void cp_commit() {
    asm volatile("cp.async.commit_group;\n");
}
template <int N>
__device__ __forceinline__ void cp_wait() {
    asm volatile("cp.async.wait_group %0;\n" :: "n"(N));
}
__device__ __forceinline__ void ldsm4(uint32_t* r, uint32_t addr) {
    asm volatile("ldmatrix.sync.aligned.m8n8.x4.shared.b16 {%0,%1,%2,%3}, [%4];"
                 : "=r"(r[0]), "=r"(r[1]), "=r"(r[2]), "=r"(r[3]) : "r"(addr));
}
__device__ __forceinline__ void ldsm4t(uint32_t* r, uint32_t addr) {
    asm volatile("ldmatrix.sync.aligned.m8n8.x4.trans.shared.b16 {%0,%1,%2,%3}, [%4];"
                 : "=r"(r[0]), "=r"(r[1]), "=r"(r[2]), "=r"(r[3]) : "r"(addr));
}
__device__ __forceinline__ void mma_f16(float* c, const uint32_t* a, const uint32_t* b) {
    asm volatile(
        "mma.sync.aligned.m16n8k16.row.col.f32.f16.f16.f32 "
        "{%0,%1,%2,%3}, {%4,%5,%6,%7}, {%8,%9}, {%0,%1,%2,%3};"
        : "+f"(c[0]), "+f"(c[1]), "+f"(c[2]), "+f"(c[3])
        : "r"(a[0]), "r"(a[1]), "r"(a[2]), "r"(a[3]), "r"(b[0]), "r"(b[1]));
}

// ---------------- kernel 0: segment scan -> lo[i] ----------------
__global__ void seg_kernel(const void* __restrict__ mask) {
    __shared__ int s0[LL];
    __shared__ int s1[LL];
    __shared__ int enc;
    const int b = blockIdx.x;
    const int t = threadIdx.x;

    if (t == 0) {
        const unsigned* mi = (const unsigned*)mask;
        int e = 0;
        for (int i = 0; i < 64; i++) {
            unsigned v = mi[i];
            if (v == 0x3F800000u) { e = 2; break; }
            if (v > 1u) e = 1;
        }
        enc = e;
    }
    __syncthreads();
    const int e = enc;

    for (int i = t; i < LL; i += 1024) {
        int mset;
        if (e == 0)      mset = ((const int*)mask)[b * LL + i] != 0;
        else if (e == 1) mset = ((const unsigned char*)mask)[b * LL + i] != 0;
        else             mset = ((const float*)mask)[b * LL + i] != 0.0f;
        s0[i] = mset ? i : 0;
    }
    __syncthreads();

    int* src = s0;
    int* dst = s1;
    for (int off = 1; off < LL; off <<= 1) {
        for (int i = t; i < LL; i += 1024) {
            int v = src[i];
            if (i >= off) v = max(v, src[i - off]);
            dst[i] = v;
        }
        __syncthreads();
        int* tmp = src; src = dst; dst = tmp;
    }
    for (int i = t; i < LL; i += 1024) {
        g_lo[b * LL + i] = max(i - (WIN - 1), src[i]);
    }
}

// ---------------- weight fp32 -> fp16 convert ----------------
__global__ void __launch_bounds__(256) conv_h_kernel(
    const float* __restrict__ s, __half* __restrict__ d, int n)
{
    const int i = (blockIdx.x * 256 + threadIdx.x) * 4;
    if (i < n) {
        float4 v = *(const float4*)(s + i);
        __half2 p0 = __floats2half2_rn(v.x, v.y);
        __half2 p1 = __floats2half2_rn(v.z, v.w);
        *(__half2*)(d + i) = p0;
        *(__half2*)(d + i + 2) = p1;
    }
}

// ---------------- kernel 1: rmsnorm over D -> fp16 ----------------
__global__ void __launch_bounds__(256) rmsnorm_kernel(const float* __restrict__ x) {
    const int row = blockIdx.x;
    const float* xr = x + (size_t)row * DD;
    __half* hr = g_hh + (size_t)row * DD;
    const int t = threadIdx.x;

    float v[4];
    float ss = 0.f;
#pragma unroll
    for (int i = 0; i < 4; i++) { v[i] = xr[t + i * 256]; ss += v[i] * v[i]; }

    __shared__ float red[8];
#pragma unroll
    for (int m = 16; m; m >>= 1) ss += __shfl_xor_sync(0xffffffffu, ss, m);
    if ((t & 31) == 0) red[t >> 5] = ss;
    __syncthreads();
    if (t < 8) {
        float r = red[t];
#pragma unroll
        for (int m = 4; m; m >>= 1) r += __shfl_xor_sync(0xffu, r, m, 8);
        if (t == 0) red[0] = r;
    }
    __syncthreads();
    const float inv = rsqrtf(red[0] * (1.0f / DD) + EPSV);
#pragma unroll
    for (int i = 0; i < 4; i++) hr[t + i * 256] = __float2half(v[i] * inv);
}

// ---------------- fp16 mma.sync GEMM: C = A @ W^T (+res) ----------------
#define NSTG 3
#define STG_B (128 * 128)
#define GSMEM (2 * NSTG * STG_B)

template <int RES>
__global__ void __launch_bounds__(256) hgemm_kernel(
    const __half* __restrict__ A, const __half* __restrict__ W,
    const float* __restrict__ res, float* __restrict__ C,
    int M, int N, int K)
{
    extern __shared__ char smem[];
    const uint32_t sb = smem_u32(smem);
    const uint32_t Asm = sb;
    const uint32_t Bsm = sb + NSTG * STG_B;

    const int t = threadIdx.x;
    const int lane = t & 31;
    const int wid = t >> 5;
    const int wm = (wid & 1) * 64;
    const int wn = (wid >> 1) * 32;
    const int m0 = blockIdx.y * 128;
    const int n0 = blockIdx.x * 128;

    const int lrow = t >> 1;
    const int lcb0 = (t & 1) * 64;
    const int lswz = (lrow & 7) << 4;
    const char* Agb = (const char*)(A + (size_t)(m0 + lrow) * K);
    const char* Wgb = (const char*)(W + (size_t)(n0 + lrow) * K);
    const uint32_t arow = Asm + lrow * 128;
    const uint32_t brow = Bsm + lrow * 128;

    float acc[4][4][4];
#pragma unroll
    for (int i = 0; i < 4; i++)
#pragma unroll
        for (int j = 0; j < 4; j++)
#pragma unroll
            for (int r = 0; r < 4; r++) acc[i][j][r] = 0.f;

    const int grp = lane >> 3;
    const int li = lane & 7;
    uint32_t a_ro[4]; int a_sw[4];
    uint32_t b_ro[2]; int b_sw[2];
#pragma unroll
    for (int mi = 0; mi < 4; mi++) {
        const int r = wm + mi * 16 + li + (grp & 1) * 8;
        a_ro[mi] = r * 128;
        a_sw[mi] = (r & 7) << 4;
    }
#pragma unroll
    for (int nb = 0; nb < 2; nb++) {
        const int r = wn + nb * 16 + li + (grp >> 1) * 8;
        b_ro[nb] = r * 128;
        b_sw[nb] = (r & 7) << 4;
    }
    const int a_g16 = (grp >> 1) * 16;
    const int b_g16 = (grp & 1) * 16;

    const int nch = K >> 6;

#pragma unroll
    for (int s = 0; s < NSTG - 1; s++) {
#pragma unroll
        for (int i = 0; i < 4; i++) {
            const int cb = lcb0 + i * 16;
            cp16(arow + s * STG_B + (cb ^ lswz), Agb + s * 128 + cb);
            cp16(brow + s * STG_B + (cb ^ lswz), Wgb + s * 128 + cb);
        }
        cp_commit();
    }

    for (int c = 0; c < nch; c++) {
        cp_wait<NSTG - 2>();
        __syncthreads();

        const int pf = c + NSTG - 1;
        if (pf < nch) {
            const int s = pf % NSTG;
#pragma unroll
            for (int i = 0; i < 4; i++) {
                const int cb = lcb0 + i * 16;
                cp16(arow + s * STG_B + (cb ^ lswz), Agb + (size_t)pf * 128 + cb);
                cp16(brow + s * STG_B + (cb ^ lswz), Wgb + (size_t)pf * 128 + cb);
            }
        }
        cp_commit();

        const uint32_t as = Asm + (c % NSTG) * STG_B;
        const uint32_t bs = Bsm + (c % NSTG) * STG_B;

#pragma unroll
        for (int ks = 0; ks < 4; ks++) {
            uint32_t af[4][4], bf[2][4];
#pragma unroll
            for (int mi = 0; mi < 4; mi++)
                ldsm4(af[mi], as + a_ro[mi] + ((ks * 32 + a_g16) ^ a_sw[mi]));
#pragma unroll
            for (int nb = 0; nb < 2; nb++)
                ldsm4(bf[nb], bs + b_ro[nb] + ((ks * 32 + b_g16) ^ b_sw[nb]));
#pragma unroll
            for (int mi = 0; mi < 4; mi++)
#pragma unroll
                for (int ni = 0; ni < 4; ni++)
                    mma_f16(acc[mi][ni], af[mi], &bf[ni >> 1][(ni & 1) * 2]);
        }
    }

    const int g = lane >> 2;
    const int tg = lane & 3;
#pragma unroll
    for (int mi = 0; mi < 4; mi++) {
#pragma unroll
        for (int ni = 0; ni < 4; ni++) {
            const int row = m0 + wm + mi * 16 + g;
            const int col = n0 + wn + ni * 8 + tg * 2;
            float2 v0 = make_float2(acc[mi][ni][0], acc[mi][ni][1]);
            float2 v1 = make_float2(acc[mi][ni][2], acc[mi][ni][3]);
            if (RES) {
                const float2 r0 = *(const float2*)(res + (size_t)row * N + col);
                const float2 r1 = *(const float2*)(res + (size_t)(row + 8) * N + col);
                v0.x += r0.x; v0.y += r0.y;
                v1.x += r1.x; v1.y += r1.y;
            }
            *(float2*)(C + (size_t)row * N + col) = v0;
            *(float2*)(C + (size_t)(row + 8) * N + col) = v1;
        }
    }
}

// ---------------- kernel 3: per-head rmsnorm + rope -> fp16 q/k/v ----------------
__global__ void __launch_bounds__(384) qkrope_kernel() {
    const int row = blockIdx.x;
    const int b = row / LL;
    const int l = row % LL;
    const int t = threadIdx.x;
    const int head = t >> 4;
    const int tl = t & 15;
    const int j = tl * 2;

    const float* src = g_qkv + (size_t)row * QKV_DIM + head * 64;

    if (head < 20) {
        float a0 = src[j], a1 = src[j + 1];
        float b0 = src[j + 32], b1 = src[j + 33];
        float ss = a0 * a0 + a1 * a1 + b0 * b0 + b1 * b1;
#pragma unroll
        for (int m = 8; m; m >>= 1) ss += __shfl_xor_sync(0xffffffffu, ss, m, 16);
        const float inv = rsqrtf(ss * (1.0f / HD) + EPSV);
        a0 *= inv; a1 *= inv; b0 *= inv; b1 *= inv;

        const float lg = logf(10000.0f) * (1.0f / 32.0f);
        const float f0 = expf(-lg * (float)j);
        const float f1 = expf(-lg * (float)(j + 1));
        float s0, c0, s1, c1;
        sincosf((float)l * f0, &s0, &c0);
        sincosf((float)l * f1, &s1, &c1);
        const float o0 = a0 * c0 - b0 * s0;
        const float o1 = a1 * c1 - b1 * s1;
        const float o2 = a0 * s0 + b0 * c0;
        const float o3 = a1 * s1 + b1 * c1;

        if (head < 16) {
            const float sc = 0.125f;  // 1/sqrt(64); exact power of 2
            __half* dq = g_qh + (((size_t)(b * NH + head)) * LL + l) * HD;
            dq[j] = __float2half(o0 * sc); dq[j + 1] = __float2half(o1 * sc);
            dq[j + 32] = __float2half(o2 * sc); dq[j + 33] = __float2half(o3 * sc);
        } else {
            __half* dk = g_kh + (((size_t)(b * NKV + (head - 16))) * LL + l) * HD;
            dk[j] = __float2half(o0); dk[j + 1] = __float2half(o1);
            dk[j + 32] = __float2half(o2); dk[j + 33] = __float2half(o3);
        }
    } else {
        __half* dv = g_vh + (((size_t)(b * NKV + (head - 20))) * LL + l) * HD;
        dv[j] = __float2half(src[j]); dv[j + 1] = __float2half(src[j + 1]);
        dv[j + 32] = __float2half(src[j + 32]); dv[j + 33] = __float2half(src[j + 33]);
    }
}

// ---------------- kernel 4: tensor-core flash attention ----------------
// 64 q-rows per CTA, 4 warps x 16 rows. fp16 QK^T and PV via mma.sync,
// S/P kept in registers, V via ldmatrix.trans. Double-buffered K/V tiles.
#define ATT_SMEM (5 * 8192)
__global__ void __launch_bounds__(128) attn_mma_kernel() {
    extern __shared__ char smc[];
    const uint32_t sb = smem_u32(smc);
    const uint32_t Qs = sb;            // 8KB
    const uint32_t Ks = sb + 8192;     // 2 x 8KB
    const uint32_t Vs = sb + 3 * 8192; // 2 x 8KB
    __shared__ int lo_s[64];

    const int qb = blockIdx.x, h = blockIdx.y, b = blockIdx.z;
    const int t = threadIdx.x;
    const int lane = t & 31;
    const int w = t >> 5;
    const int q0 = qb * 64;
    const int kvh = h >> 2;
    const char* Qg = (const char*)(g_qh + (((size_t)(b * NH + h)) * LL + q0) * HD);
    const char* Kg = (const char*)(g_kh + ((size_t)(b * NKV + kvh)) * LL * HD);
    const char* Vg = (const char*)(g_vh + ((size_t)(b * NKV + kvh)) * LL * HD);

    const int kb0 = g_lo[b * LL + q0] & ~63;   // lo non-decreasing
    const int nt = ((q0 + 63 - kb0) >> 6) + 1;
    if (t < 64) lo_s[t] = g_lo[b * LL + q0 + t];

    // loaders: thread -> row t/2, 4 x 16B at (t&1)*64
    const int lrow = t >> 1;
    const int lcb0 = (t & 1) * 64;
    const int lswz = (lrow & 7) << 4;
    const uint32_t qrow_s = Qs + lrow * 128;
    const uint32_t krow_s = Ks + lrow * 128;
    const uint32_t vrow_s = Vs + lrow * 128;

    // preload Q + tile 0 of K/V (group 0)
#pragma unroll
    for (int i = 0; i < 4; i++) {
        const int cb = lcb0 + i * 16;
        cp16(qrow_s + (cb ^ lswz), Qg + lrow * 128 + cb);
        cp16(krow_s + (cb ^ lswz), Kg + (size_t)(kb0 + lrow) * 128 + cb);
        cp16(vrow_s + (cb ^ lswz), Vg + (size_t)(kb0 + lrow) * 128 + cb);
    }
    cp_commit();

    const int grp = lane >> 3;
    const int li = lane & 7;
    const int g = lane >> 2;
    const int tg = lane & 3;
    const int row0 = w * 16 + g;
    const int qg0 = q0 + row0;
    const int qg1 = qg0 + 8;

    cp_wait<0>();
    __syncthreads();

    // Q fragments (held across tiles)
    uint32_t aQ[4][4];
    {
        const int qr = w * 16 + li + (grp & 1) * 8;
        const uint32_t qa = Qs + qr * 128;
        const int qsw = (qr & 7) << 4;
        const int qg16 = (grp >> 1) * 16;
#pragma unroll
        for (int kk = 0; kk < 4; kk++)
            ldsm4(aQ[kk], qa + ((kk * 32 + qg16) ^ qsw));
    }

    const int lo0 = lo_s[row0];
    const int lo1 = lo_s[row0 + 8];

    // B-frag address constants (K non-trans; V trans)
    uint32_t k_ro[4]; int k_sw[4];
    uint32_t v_co[4]; // per nb column byte base for V
#pragma unroll
    for (int nb = 0; nb < 4; nb++) {
        const int r = nb * 16 + li + (grp >> 1) * 8;
        k_ro[nb] = r * 128;
        k_sw[nb] = (r & 7) << 4;
        v_co[nb] = nb * 32 + (grp >> 1) * 16;
    }
    const int k_g16 = (grp & 1) * 16;
    const int v_r8 = (grp & 1) * 8 + li;

    float m0 = -1e30f, m1 = -1e30f, l0 = 0.f, l1 = 0.f;
    float o[8][4];
#pragma unroll
    for (int jn = 0; jn < 8; jn++)
#pragma unroll
        for (int r = 0; r < 4; r++) o[jn][r] = 0.f;

    for (int i = 0; i < nt; i++) {
        const int kb = kb0 + i * 64;
        // prefetch tile i+1 into alt buffer (safe: BAR at end of prev iter)
        if (i + 1 < nt) {
            const int bo = ((i + 1) & 1) * 8192;
            const size_t go = (size_t)(kb + 64 + lrow) * 128;
#pragma unroll
            for (int c2 = 0; c2 < 4; c2++) {
                const int cb = lcb0 + c2 * 16;
                cp16(krow_s + bo + (cb ^ lswz), Kg + go + cb);
                cp16(vrow_s + bo + (cb ^ lswz), Vg + go + cb);
            }
        }
        cp_commit();
        cp_wait<1>();
        __syncthreads();

        const uint32_t Kb = Ks + (i & 1) * 8192;
        const uint32_t Vb = Vs + (i & 1) * 8192;

        // ---- S = Q K^T ----
        float sc[8][4];
#pragma unroll
        for (int j = 0; j < 8; j++)
#pragma unroll
            for (int r = 0; r < 4; r++) sc[j][r] = 0.f;

#pragma unroll
        for (int kk = 0; kk < 4; kk++) {
            uint32_t bf[4][4];
#pragma unroll
            for (int nb = 0; nb < 4; nb++)
                ldsm4(bf[nb], Kb + k_ro[nb] + ((kk * 32 + k_g16) ^ k_sw[nb]));
#pragma unroll
            for (int j = 0; j < 8; j++)
                mma_f16(sc[j], aQ[kk], &bf[j >> 1][(j & 1) * 2]);
        }

        // ---- mask + online softmax ----
        float mx0 = -1e30f, mx1 = -1e30f;
#pragma unroll
        for (int j = 0; j < 8; j++) {
            const int c0 = kb + j * 8 + tg * 2;
            const int c1 = c0 + 1;
            if (c0 < lo0 || c0 > qg0) sc[j][0] = -1e30f;
            if (c1 < lo0 || c1 > qg0) sc[j][1] = -1e30f;
            if (c0 < lo1 || c0 > qg1) sc[j][2] = -1e30f;
            if (c1 < lo1 || c1 > qg1) sc[j][3] = -1e30f;
            mx0 = fmaxf(mx0, fmaxf(sc[j][0], sc[j][1]));
            mx1 = fmaxf(mx1, fmaxf(sc[j][2], sc[j][3]));
        }
        mx0 = fmaxf(mx0, __shfl_xor_sync(0xffffffffu, mx0, 1));
        mx0 = fmaxf(mx0, __shfl_xor_sync(0xffffffffu, mx0, 2));
        mx1 = fmaxf(mx1, __shfl_xor_sync(0xffffffffu, mx1, 1));
        mx1 = fmaxf(mx1, __shfl_xor_sync(0xffffffffu, mx1, 2));

        const float mn0 = fmaxf(m0, mx0);
        const float mn1 = fmaxf(m1, mx1);
        const float al0 = __expf(m0 - mn0);
        const float al1 = __expf(m1 - mn1);

        float lp0 = 0.f, lp1 = 0.f;
        uint32_t ph[8][2];
#pragma unroll
        for (int j = 0; j < 8; j++) {
            const float p0 = (sc[j][0] > -1e29f) ? __expf(sc[j][0] - mn0) : 0.f;
            const float p1 = (sc[j][1] > -1e29f) ? __expf(sc[j][1] - mn0) : 0.f;
            const float p2 = (sc[j][2] > -1e29f) ? __expf(sc[j][2] - mn1) : 0.f;
            const float p3 = (sc[j][3] > -1e29f) ? __expf(sc[j][3] - mn1) : 0.f;
            lp0 += p0 + p1;
            lp1 += p2 + p3;
            __half2 h0 = __floats2half2_rn(p0, p1);
            __half2 h1 = __floats2half2_rn(p2, p3);
            ph[j][0] = *(uint32_t*)&h0;
            ph[j][1] = *(uint32_t*)&h1;
        }
        lp0 += __shfl_xor_sync(0xffffffffu, lp0, 1);
        lp0 += __shfl_xor_sync(0xffffffffu, lp0, 2);
        lp1 += __shfl_xor_sync(0xffffffffu, lp1, 1);
        lp1 += __shfl_xor_sync(0xffffffffu, lp1, 2);

        l0 = l0 * al0 + lp0;
        l1 = l1 * al1 + lp1;
        m0 = mn0; m1 = mn1;
#pragma unroll
        for (int jn = 0; jn < 8; jn++) {
            o[jn][0] *= al0; o[jn][1] *= al0;
            o[jn][2] *= al1; o[jn][3] *= al1;
        }

        // ---- O += P V ----
#pragma unroll
        for (int kk = 0; kk < 4; kk++) {
            uint32_t vf[4][4];
            const int vr = kk * 16 + v_r8;
            const uint32_t va = Vb + vr * 128;
            const int vsw = (vr & 7) << 4;
#pragma unroll
            for (int nb = 0; nb < 4; nb++)
                ldsm4t(vf[nb], va + (v_co[nb] ^ vsw));
            uint32_t aP[4] = { ph[2 * kk][0], ph[2 * kk][1],
                               ph[2 * kk + 1][0], ph[2 * kk + 1][1] };
#pragma unroll
            for (int jn = 0; jn < 8; jn++)
                mma_f16(o[jn], aP, &vf[jn >> 1][(jn & 1) * 2]);
        }
        __syncthreads();  // before next iter's prefetch overwrites buffer
    }

    // ---- epilogue ----
    const float iv0 = 1.0f / l0;
    const float iv1 = 1.0f / l1;
    __half* y0 = g_yh + ((size_t)(b * LL) + qg0) * DD + h * HD;
    __half* y1 = g_yh + ((size_t)(b * LL) + qg1) * DD + h * HD;
#pragma unroll
    for (int jn = 0; jn < 8; jn++) {
        __half2 r0 = __floats2half2_rn(o[jn][0] * iv0, o[jn][1] * iv0);
        __half2 r1 = __floats2half2_rn(o[jn][2] * iv1, o[jn][3] * iv1);
        *(__half2*)(y0 + jn * 8 + tg * 2) = r0;
        *(__half2*)(y1 + jn * 8 + tg * 2) = r1;
    }
}

// ---------------- launch ----------------
extern "C" void kernel_launch(void* const* d_in, const int* in_sizes, int n_in,
                              void* d_out, int out_size) {
    const float* x     = (const float*)d_in[0];
    const float* w_qkv = (const float*)d_in[1];
    const float* w_out = (const float*)d_in[2];
    const void*  mask  = d_in[3];
    float* out = (float*)d_out;

    __half *phh, *pwqh, *pwoh, *pyh;
    float *pqkv;
    cudaGetSymbolAddress((void**)&phh, g_hh);
    cudaGetSymbolAddress((void**)&pwqh, g_wqkvh);
    cudaGetSymbolAddress((void**)&pwoh, g_wouth);
    cudaGetSymbolAddress((void**)&pyh, g_yh);
    cudaGetSymbolAddress((void**)&pqkv, g_qkv);

    const int M = BB * LL;

    cudaFuncSetAttribute(hgemm_kernel<0>,
                         cudaFuncAttributeMaxDynamicSharedMemorySize, GSMEM);
    cudaFuncSetAttribute(hgemm_kernel<1>,
                         cudaFuncAttributeMaxDynamicSharedMemorySize, GSMEM);
    cudaFuncSetAttribute(attn_mma_kernel,
                         cudaFuncAttributeMaxDynamicSharedMemorySize, ATT_SMEM);

    seg_kernel<<<BB, 1024>>>(mask);
    conv_h_kernel<<<(QKV_DIM * DD / 4 + 255) / 256, 256>>>(w_qkv, pwqh, QKV_DIM * DD);
    conv_h_kernel<<<(DD * DD / 4 + 255) / 256, 256>>>(w_out, pwoh, DD * DD);
    rmsnorm_kernel<<<M, 256>>>(x);

    hgemm_kernel<0><<<dim3(QKV_DIM / 128, M / 128), 256, GSMEM>>>(
        phh, pwqh, nullptr, pqkv, M, QKV_DIM, DD);

    qkrope_kernel<<<M, 384>>>();

    attn_mma_kernel<<<dim3(LL / 64, NH, BB), 128, ATT_SMEM>>>();

    hgemm_kernel<1><<<dim3(DD / 128, M / 128), 256, GSMEM>>>(
        pyh, pwoh, x, out, M, DD, DD);
}

// round 7
// speedup vs baseline: 5.5022x; 1.0630x over previous
#include <cuda_runtime.h>
#include <cuda_fp16.h>
#include <math.h>
#include <stdint.h>

#define BB 2
#define LL 2048
#define DD 1024
#define NH 16
#define NKV 4
#define HD 64
#define WIN 1024
#define QKV_DIM 1536
#define EPSV 1.1920929e-07f

// ---------------- scratch (no cudaMalloc allowed) ----------------
__device__ __half g_hh[BB * LL * DD];        // rmsnorm(x) in fp16
__device__ __half g_wqkvh[QKV_DIM * DD];     // w_qkv fp16
__device__ __half g_wouth[DD * DD];          // w_out fp16
__device__ __half g_yh[BB * LL * DD];        // attention out fp16
__device__ __half g_qh[BB * NH * LL * HD];   // q fp16 (normed, roped, pre-scaled)
__device__ __half g_kh[BB * NKV * LL * HD];  // k fp16
__device__ __half g_vh[BB * NKV * LL * HD];  // v fp16
__device__ int    g_lo[BB * LL];
__device__ float4 g_rope[LL * 16];           // (c0,c1,s0,s1) per (l, pair)

// ---------------- ptx helpers ----------------
__device__ __forceinline__ uint32_t smem_u32(const void* p) {
    uint32_t a;
    asm("{ .reg .u64 t; cvta.to.shared.u64 t, %1; cvt.u32.u64 %0, t; }"
        : "=r"(a) : "l"(p));
    return a;
}
__device__ __forceinline__ void cp16(uint32_t smem_dst, const void* gsrc) {
    asm volatile("cp.async.cg.shared.global [%0], [%1], 16;\n"
                 :: "r"(smem_dst), "l"(gsrc));
}
__device__ __forceinline__ void cp_commit() {
    asm volatile("cp.async.commit_group;\n");
}
template <int N>
__device__ __forceinline__ void cp_wait() {
    asm volatile("cp.async.wait_group %0;\n" :: "n"(N));
}
__device__ __forceinline__ void ldsm4(uint32_t* r, uint32_t addr) {
    asm volatile("ldmatrix.sync.aligned.m8n8.x4.shared.b16 {%0,%1,%2,%3}, [%4];"
                 : "=r"(r[0]), "=r"(r[1]), "=r"(r[2]), "=r"(r[3]) : "r"(addr));
}
__device__ __forceinline__ void ldsm4t(uint32_t* r, uint32_t addr) {
    asm volatile("ldmatrix.sync.aligned.m8n8.x4.trans.shared.b16 {%0,%1,%2,%3}, [%4];"
                 : "=r"(r[0]), "=r"(r[1]), "=r"(r[2]), "=r"(r[3]) : "r"(addr));
}
__device__ __forceinline__ void mma_f16(float* c, const uint32_t* a, const uint32_t* b) {
    asm volatile(
        "mma.sync.aligned.m16n8k16.row.col.f32.f16.f16.f32 "
        "{%0,%1,%2,%3}, {%4,%5,%6,%7}, {%8,%9}, {%0,%1,%2,%3};"
        : "+f"(c[0]), "+f"(c[1]), "+f"(c[2]), "+f"(c[3])
        : "r"(a[0]), "r"(a[1]), "r"(a[2]), "r"(a[3]), "r"(b[0]), "r"(b[1]));
}

// ---------------- kernel 0: segment scan -> lo[i] ----------------
__global__ void seg_kernel(const void* __restrict__ mask) {
    __shared__ int s0[LL];
    __shared__ int s1[LL];
    __shared__ int enc;
    const int b = blockIdx.x;
    const int t = threadIdx.x;

    if (t == 0) {
        const unsigned* mi = (const unsigned*)mask;
        int e = 0;
        for (int i = 0; i < 64; i++) {
            unsigned v = mi[i];
            if (v == 0x3F800000u) { e = 2; break; }
            if (v > 1u) e = 1;
        }
        enc = e;
    }
    __syncthreads();
    const int e = enc;

    for (int i = t; i < LL; i += 1024) {
        int mset;
        if (e == 0)      mset = ((const int*)mask)[b * LL + i] != 0;
        else if (e == 1) mset = ((const unsigned char*)mask)[b * LL + i] != 0;
        else             mset = ((const float*)mask)[b * LL + i] != 0.0f;
        s0[i] = mset ? i : 0;
    }
    __syncthreads();

    int* src = s0;
    int* dst = s1;
    for (int off = 1; off < LL; off <<= 1) {
        for (int i = t; i < LL; i += 1024) {
            int v = src[i];
            if (i >= off) v = max(v, src[i - off]);
            dst[i] = v;
        }
        __syncthreads();
        int* tmp = src; src = dst; dst = tmp;
    }
    for (int i = t; i < LL; i += 1024) {
        g_lo[b * LL + i] = max(i - (WIN - 1), src[i]);
    }
}

// ---------------- rope table: (l, pair) -> (c0,c1,s0,s1) ----------------
__global__ void __launch_bounds__(256) rope_table_kernel() {
    const int i = blockIdx.x * 256 + threadIdx.x;  // LL*16 entries
    if (i >= LL * 16) return;
    const int l = i >> 4;
    const int j = (i & 15) * 2;
    const float lg = logf(10000.0f) * (1.0f / 32.0f);
    const float f0 = expf(-lg * (float)j);
    const float f1 = expf(-lg * (float)(j + 1));
    float s0, c0, s1, c1;
    sincosf((float)l * f0, &s0, &c0);
    sincosf((float)l * f1, &s1, &c1);
    g_rope[i] = make_float4(c0, c1, s0, s1);
}

// ---------------- merged weight fp32 -> fp16 convert ----------------
__global__ void __launch_bounds__(256) conv_h_kernel(
    const float* __restrict__ wq, const float* __restrict__ wo)
{
    const int n1 = QKV_DIM * DD;
    const int n2 = DD * DD;
    const int i = (blockIdx.x * 256 + threadIdx.x) * 4;
    if (i < n1) {
        float4 v = *(const float4*)(wq + i);
        *(__half2*)(g_wqkvh + i) = __floats2half2_rn(v.x, v.y);
        *(__half2*)(g_wqkvh + i + 2) = __floats2half2_rn(v.z, v.w);
    } else if (i < n1 + n2) {
        const int k = i - n1;
        float4 v = *(const float4*)(wo + k);
        *(__half2*)(g_wouth + k) = __floats2half2_rn(v.x, v.y);
        *(__half2*)(g_wouth + k + 2) = __floats2half2_rn(v.z, v.w);
    }
}

// ---------------- kernel 1: rmsnorm over D -> fp16 (float4 path) ----------------
__global__ void __launch_bounds__(256) rmsnorm_kernel(const float* __restrict__ x) {
    const int row = blockIdx.x;
    const float4* xr = (const float4*)(x + (size_t)row * DD);
    __half2* hr = (__half2*)(g_hh + (size_t)row * DD);
    const int t = threadIdx.x;

    const float4 v = xr[t];
    float ss = v.x * v.x + v.y * v.y + v.z * v.z + v.w * v.w;

    __shared__ float red[8];
#pragma unroll
    for (int m = 16; m; m >>= 1) ss += __shfl_xor_sync(0xffffffffu, ss, m);
    if ((t & 31) == 0) red[t >> 5] = ss;
    __syncthreads();
    if (t < 8) {
        float r = red[t];
#pragma unroll
        for (int m = 4; m; m >>= 1) r += __shfl_xor_sync(0xffu, r, m, 8);
        if (t == 0) red[0] = r;
    }
    __syncthreads();
    const float inv = rsqrtf(red[0] * (1.0f / DD) + EPSV);
    hr[t * 2] = __floats2half2_rn(v.x * inv, v.y * inv);
    hr[t * 2 + 1] = __floats2half2_rn(v.z * inv, v.w * inv);
}

// ---------------- fp16 mma.sync GEMM ----------------
// EPI=1: C = A@W^T + res (fp32 out). EPI=2: fused per-head rmsnorm+rope -> q/k/v fp16.
#define NSTG 3
#define STG_B (128 * 128)
#define GSMEM (2 * NSTG * STG_B)

template <int EPI>
__global__ void __launch_bounds__(256) hgemm_kernel(
    const __half* __restrict__ A, const __half* __restrict__ W,
    const float* __restrict__ res, float* __restrict__ C,
    int M, int N, int K)
{
    extern __shared__ char smem[];
    const uint32_t sb = smem_u32(smem);
    const uint32_t Asm = sb;
    const uint32_t Bsm = sb + NSTG * STG_B;

    const int t = threadIdx.x;
    const int lane = t & 31;
    const int wid = t >> 5;
    const int wm = (wid & 1) * 64;
    const int wn = (wid >> 1) * 32;
    const int m0 = blockIdx.y * 128;
    const int n0 = blockIdx.x * 128;

    const int lrow = t >> 1;
    const int lcb0 = (t & 1) * 64;
    const int lswz = (lrow & 7) << 4;
    const char* Agb = (const char*)(A + (size_t)(m0 + lrow) * K);
    const char* Wgb = (const char*)(W + (size_t)(n0 + lrow) * K);
    const uint32_t arow = Asm + lrow * 128;
    const uint32_t brow = Bsm + lrow * 128;

    float acc[4][4][4];
#pragma unroll
    for (int i = 0; i < 4; i++)
#pragma unroll
        for (int j = 0; j < 4; j++)
#pragma unroll
            for (int r = 0; r < 4; r++) acc[i][j][r] = 0.f;

    const int grp = lane >> 3;
    const int li = lane & 7;
    uint32_t a_ro[4]; int a_sw[4];
    uint32_t b_ro[2]; int b_sw[2];
#pragma unroll
    for (int mi = 0; mi < 4; mi++) {
        const int r = wm + mi * 16 + li + (grp & 1) * 8;
        a_ro[mi] = r * 128;
        a_sw[mi] = (r & 7) << 4;
    }
#pragma unroll
    for (int nb = 0; nb < 2; nb++) {
        const int r = wn + nb * 16 + li + (grp >> 1) * 8;
        b_ro[nb] = r * 128;
        b_sw[nb] = (r & 7) << 4;
    }
    const int a_g16 = (grp >> 1) * 16;
    const int b_g16 = (grp & 1) * 16;

    const int nch = K >> 6;

#pragma unroll
    for (int s = 0; s < NSTG - 1; s++) {
#pragma unroll
        for (int i = 0; i < 4; i++) {
            const int cb = lcb0 + i * 16;
            cp16(arow + s * STG_B + (cb ^ lswz), Agb + s * 128 + cb);
            cp16(brow + s * STG_B + (cb ^ lswz), Wgb + s * 128 + cb);
        }
        cp_commit();
    }

    for (int c = 0; c < nch; c++) {
        cp_wait<NSTG - 2>();
        __syncthreads();

        const int pf = c + NSTG - 1;
        if (pf < nch) {
            const int s = pf % NSTG;
#pragma unroll
            for (int i = 0; i < 4; i++) {
                const int cb = lcb0 + i * 16;
                cp16(arow + s * STG_B + (cb ^ lswz), Agb + (size_t)pf * 128 + cb);
                cp16(brow + s * STG_B + (cb ^ lswz), Wgb + (size_t)pf * 128 + cb);
            }
        }
        cp_commit();

        const uint32_t as = Asm + (c % NSTG) * STG_B;
        const uint32_t bs = Bsm + (c % NSTG) * STG_B;

#pragma unroll
        for (int ks = 0; ks < 4; ks++) {
            uint32_t af[4][4], bf[2][4];
#pragma unroll
            for (int mi = 0; mi < 4; mi++)
                ldsm4(af[mi], as + a_ro[mi] + ((ks * 32 + a_g16) ^ a_sw[mi]));
#pragma unroll
            for (int nb = 0; nb < 2; nb++)
                ldsm4(bf[nb], bs + b_ro[nb] + ((ks * 32 + b_g16) ^ b_sw[nb]));
#pragma unroll
            for (int mi = 0; mi < 4; mi++)
#pragma unroll
                for (int ni = 0; ni < 4; ni++)
                    mma_f16(acc[mi][ni], af[mi], &bf[ni >> 1][(ni & 1) * 2]);
        }
    }

    const int g = lane >> 2;
    const int tg = lane & 3;

    if (EPI == 1) {
#pragma unroll
        for (int mi = 0; mi < 4; mi++) {
#pragma unroll
            for (int ni = 0; ni < 4; ni++) {
                const int row = m0 + wm + mi * 16 + g;
                const int col = n0 + wn + ni * 8 + tg * 2;
                float2 v0 = make_float2(acc[mi][ni][0], acc[mi][ni][1]);
                float2 v1 = make_float2(acc[mi][ni][2], acc[mi][ni][3]);
                const float2 r0 = *(const float2*)(res + (size_t)row * N + col);
                const float2 r1 = *(const float2*)(res + (size_t)(row + 8) * N + col);
                v0.x += r0.x; v0.y += r0.y;
                v1.x += r1.x; v1.y += r1.y;
                *(float2*)(C + (size_t)row * N + col) = v0;
                *(float2*)(C + (size_t)(row + 8) * N + col) = v1;
            }
        }
    } else {
        // ---- fused qkv epilogue: stage tile to smem, per-head norm+rope ----
        __syncthreads();  // all warps past last mainloop smem read
        float* sf = (float*)smem;  // [128][132]
#pragma unroll
        for (int mi = 0; mi < 4; mi++) {
#pragma unroll
            for (int ni = 0; ni < 4; ni++) {
                const int r = wm + mi * 16 + g;
                const int cl = wn + ni * 8 + tg * 2;
                *(float2*)&sf[r * 132 + cl] = make_float2(acc[mi][ni][0], acc[mi][ni][1]);
                *(float2*)&sf[(r + 8) * 132 + cl] = make_float2(acc[mi][ni][2], acc[mi][ni][3]);
            }
        }
        __syncthreads();

        const int gi = t >> 4;        // group 0..15
        const int tl = t & 15;
        const int j = tl * 2;
        const int hbase = n0 >> 6;    // first head in this tile

        for (int it = 0; it < 16; it++) {
            const int p = it * 16 + gi;     // (row, head-in-tile) pair
            const int r = p >> 1;
            const int hh = p & 1;
            const int head = hbase + hh;
            const int rowg = m0 + r;
            const int b = rowg >> 11;
            const int l = rowg & (LL - 1);
            const float* sr = &sf[r * 132 + hh * 64];

            const float a0 = sr[j], a1 = sr[j + 1];
            const float b0 = sr[j + 32], b1 = sr[j + 33];

            if (head < 20) {
                float ss = a0 * a0 + a1 * a1 + b0 * b0 + b1 * b1;
#pragma unroll
                for (int m = 8; m; m >>= 1)
                    ss += __shfl_xor_sync(0xffffffffu, ss, m, 16);
                const float inv = rsqrtf(ss * (1.0f / HD) + EPSV);
                const float4 rp = g_rope[l * 16 + tl];
                const float a0n = a0 * inv, a1n = a1 * inv;
                const float b0n = b0 * inv, b1n = b1 * inv;
                const float o0 = a0n * rp.x - b0n * rp.z;
                const float o1 = a1n * rp.y - b1n * rp.w;
                const float o2 = a0n * rp.z + b0n * rp.x;
                const float o3 = a1n * rp.w + b1n * rp.y;
                if (head < 16) {
                    const float sc = 0.125f;
                    __half* dq = g_qh + (((size_t)(b * NH + head)) * LL + l) * HD;
                    *(__half2*)(dq + j) = __floats2half2_rn(o0 * sc, o1 * sc);
                    *(__half2*)(dq + j + 32) = __floats2half2_rn(o2 * sc, o3 * sc);
                } else {
                    __half* dk = g_kh + (((size_t)(b * NKV + (head - 16))) * LL + l) * HD;
                    *(__half2*)(dk + j) = __floats2half2_rn(o0, o1);
                    *(__half2*)(dk + j + 32) = __floats2half2_rn(o2, o3);
                }
            } else {
                __half* dv = g_vh + (((size_t)(b * NKV + (head - 20))) * LL + l) * HD;
                *(__half2*)(dv + j) = __floats2half2_rn(a0, a1);
                *(__half2*)(dv + j + 32) = __floats2half2_rn(b0, b1);
            }
        }
    }
}

// ---------------- kernel 4: tensor-core flash attention ----------------
#define ATT_SMEM (5 * 8192)
__global__ void __launch_bounds__(128) attn_mma_kernel() {
    extern __shared__ char smc[];
    const uint32_t sb = smem_u32(smc);
    const uint32_t Qs = sb;
    const uint32_t Ks = sb + 8192;
    const uint32_t Vs = sb + 3 * 8192;
    __shared__ int lo_s[64];

    const int qb = blockIdx.x, h = blockIdx.y, b = blockIdx.z;
    const int t = threadIdx.x;
    const int lane = t & 31;
    const int w = t >> 5;
    const int q0 = qb * 64;
    const int kvh = h >> 2;
    const char* Qg = (const char*)(g_qh + (((size_t)(b * NH + h)) * LL + q0) * HD);
    const char* Kg = (const char*)(g_kh + ((size_t)(b * NKV + kvh)) * LL * HD);
    const char* Vg = (const char*)(g_vh + ((size_t)(b * NKV + kvh)) * LL * HD);

    const int kb0 = g_lo[b * LL + q0] & ~63;
    const int nt = ((q0 + 63 - kb0) >> 6) + 1;
    if (t < 64) lo_s[t] = g_lo[b * LL + q0 + t];

    const int lrow = t >> 1;
    const int lcb0 = (t & 1) * 64;
    const int lswz = (lrow & 7) << 4;
    const uint32_t qrow_s = Qs + lrow * 128;
    const uint32_t krow_s = Ks + lrow * 128;
    const uint32_t vrow_s = Vs + lrow * 128;

#pragma unroll
    for (int i = 0; i < 4; i++) {
        const int cb = lcb0 + i * 16;
        cp16(qrow_s + (cb ^ lswz), Qg + lrow * 128 + cb);
        cp16(krow_s + (cb ^ lswz), Kg + (size_t)(kb0 + lrow) * 128 + cb);
        cp16(vrow_s + (cb ^ lswz), Vg + (size_t)(kb0 + lrow) * 128 + cb);
    }
    cp_commit();

    const int grp = lane >> 3;
    const int li = lane & 7;
    const int g = lane >> 2;
    const int tg = lane & 3;
    const int row0 = w * 16 + g;
    const int qg0 = q0 + row0;
    const int qg1 = qg0 + 8;

    cp_wait<0>();
    __syncthreads();

    uint32_t aQ[4][4];
    {
        const int qr = w * 16 + li + (grp & 1) * 8;
        const uint32_t qa = Qs + qr * 128;
        const int qsw = (qr & 7) << 4;
        const int qg16 = (grp >> 1) * 16;
#pragma unroll
        for (int kk = 0; kk < 4; kk++)
            ldsm4(aQ[kk], qa + ((kk * 32 + qg16) ^ qsw));
    }

    const int lo0 = lo_s[row0];
    const int lo1 = lo_s[row0 + 8];

    uint32_t k_ro[4]; int k_sw[4];
    uint32_t v_co[4];
#pragma unroll
    for (int nb = 0; nb < 4; nb++) {
        const int r = nb * 16 + li + (grp >> 1) * 8;
        k_ro[nb] = r * 128;
        k_sw[nb] = (r & 7) << 4;
        v_co[nb] = nb * 32 + (grp >> 1) * 16;
    }
    const int k_g16 = (grp & 1) * 16;
    const int v_r8 = (grp & 1) * 8 + li;

    float m0 = -1e30f, m1 = -1e30f, l0 = 0.f, l1 = 0.f;
    float o[8][4];
#pragma unroll
    for (int jn = 0; jn < 8; jn++)
#pragma unroll
        for (int r = 0; r < 4; r++) o[jn][r] = 0.f;

    for (int i = 0; i < nt; i++) {
        const int kb = kb0 + i * 64;
        if (i + 1 < nt) {
            const int bo = ((i + 1) & 1) * 8192;
            const size_t go = (size_t)(kb + 64 + lrow) * 128;
#pragma unroll
            for (int c2 = 0; c2 < 4; c2++) {
                const int cb = lcb0 + c2 * 16;
                cp16(krow_s + bo + (cb ^ lswz), Kg + go + cb);
                cp16(vrow_s + bo + (cb ^ lswz), Vg + go + cb);
            }
        }
        cp_commit();
        cp_wait<1>();
        __syncthreads();

        const uint32_t Kb = Ks + (i & 1) * 8192;
        const uint32_t Vb = Vs + (i & 1) * 8192;

        float sc[8][4];
#pragma unroll
        for (int j = 0; j < 8; j++)
#pragma unroll
            for (int r = 0; r < 4; r++) sc[j][r] = 0.f;

#pragma unroll
        for (int kk = 0; kk < 4; kk++) {
            uint32_t bf[4][4];
#pragma unroll
            for (int nb = 0; nb < 4; nb++)
                ldsm4(bf[nb], Kb + k_ro[nb] + ((kk * 32 + k_g16) ^ k_sw[nb]));
#pragma unroll
            for (int j = 0; j < 8; j++)
                mma_f16(sc[j], aQ[kk], &bf[j >> 1][(j & 1) * 2]);
        }

        float mx0 = -1e30f, mx1 = -1e30f;
#pragma unroll
        for (int j = 0; j < 8; j++) {
            const int c0 = kb + j * 8 + tg * 2;
            const int c1 = c0 + 1;
            if (c0 < lo0 || c0 > qg0) sc[j][0] = -1e30f;
            if (c1 < lo0 || c1 > qg0) sc[j][1] = -1e30f;
            if (c0 < lo1 || c0 > qg1) sc[j][2] = -1e30f;
            if (c1 < lo1 || c1 > qg1) sc[j][3] = -1e30f;
            mx0 = fmaxf(mx0, fmaxf(sc[j][0], sc[j][1]));
            mx1 = fmaxf(mx1, fmaxf(sc[j][2], sc[j][3]));
        }
        mx0 = fmaxf(mx0, __shfl_xor_sync(0xffffffffu, mx0, 1));
        mx0 = fmaxf(mx0, __shfl_xor_sync(0xffffffffu, mx0, 2));
        mx1 = fmaxf(mx1, __shfl_xor_sync(0xffffffffu, mx1, 1));
        mx1 = fmaxf(mx1, __shfl_xor_sync(0xffffffffu, mx1, 2));

        const float mn0 = fmaxf(m0, mx0);
        const float mn1 = fmaxf(m1, mx1);
        const float al0 = __expf(m0 - mn0);
        const float al1 = __expf(m1 - mn1);

        float lp0 = 0.f, lp1 = 0.f;
        uint32_t ph[8][2];
#pragma unroll
        for (int j = 0; j < 8; j++) {
            const float p0 = (sc[j][0] > -1e29f) ? __expf(sc[j][0] - mn0) : 0.f;
            const float p1 = (sc[j][1] > -1e29f) ? __expf(sc[j][1] - mn0) : 0.f;
            const float p2 = (sc[j][2] > -1e29f) ? __expf(sc[j][2] - mn1) : 0.f;
            const float p3 = (sc[j][3] > -1e29f) ? __expf(sc[j][3] - mn1) : 0.f;
            lp0 += p0 + p1;
            lp1 += p2 + p3;
            __half2 h0 = __floats2half2_rn(p0, p1);
            __half2 h1 = __floats2half2_rn(p2, p3);
            ph[j][0] = *(uint32_t*)&h0;
            ph[j][1] = *(uint32_t*)&h1;
        }
        lp0 += __shfl_xor_sync(0xffffffffu, lp0, 1);
        lp0 += __shfl_xor_sync(0xffffffffu, lp0, 2);
        lp1 += __shfl_xor_sync(0xffffffffu, lp1, 1);
        lp1 += __shfl_xor_sync(0xffffffffu, lp1, 2);

        l0 = l0 * al0 + lp0;
        l1 = l1 * al1 + lp1;
        m0 = mn0; m1 = mn1;
#pragma unroll
        for (int jn = 0; jn < 8; jn++) {
            o[jn][0] *= al0; o[jn][1] *= al0;
            o[jn][2] *= al1; o[jn][3] *= al1;
        }

#pragma unroll
        for (int kk = 0; kk < 4; kk++) {
            uint32_t vf[4][4];
            const int vr = kk * 16 + v_r8;
            const uint32_t va = Vb + vr * 128;
            const int vsw = (vr & 7) << 4;
#pragma unroll
            for (int nb = 0; nb < 4; nb++)
                ldsm4t(vf[nb], va + (v_co[nb] ^ vsw));
            uint32_t aP[4] = { ph[2 * kk][0], ph[2 * kk][1],
                               ph[2 * kk + 1][0], ph[2 * kk + 1][1] };
#pragma unroll
            for (int jn = 0; jn < 8; jn++)
                mma_f16(o[jn], aP, &vf[jn >> 1][(jn & 1) * 2]);
        }
        __syncthreads();
    }

    const float iv0 = 1.0f / l0;
    const float iv1 = 1.0f / l1;
    __half* y0 = g_yh + ((size_t)(b * LL) + qg0) * DD + h * HD;
    __half* y1 = g_yh + ((size_t)(b * LL) + qg1) * DD + h * HD;
#pragma unroll
    for (int jn = 0; jn < 8; jn++) {
        __half2 r0 = __floats2half2_rn(o[jn][0] * iv0, o[jn][1] * iv0);
        __half2 r1 = __floats2half2_rn(o[jn][2] * iv1, o[jn][3] * iv1);
        *(__half2*)(y0 + jn * 8 + tg * 2) = r0;
        *(__half2*)(y1 + jn * 8 + tg * 2) = r1;
    }
}

// ---------------- launch ----------------
extern "C" void kernel_launch(void* const* d_in, const int* in_sizes, int n_in,
                              void* d_out, int out_size) {
    const float* x     = (const float*)d_in[0];
    const float* w_qkv = (const float*)d_in[1];
    const float* w_out = (const float*)d_in[2];
    const void*  mask  = d_in[3];
    float* out = (float*)d_out;

    __half *phh, *pwqh, *pwoh, *pyh;
    cudaGetSymbolAddress((void**)&phh, g_hh);
    cudaGetSymbolAddress((void**)&pwqh, g_wqkvh);
    cudaGetSymbolAddress((void**)&pwoh, g_wouth);
    cudaGetSymbolAddress((void**)&pyh, g_yh);

    const int M = BB * LL;

    cudaFuncSetAttribute(hgemm_kernel<1>,
                         cudaFuncAttributeMaxDynamicSharedMemorySize, GSMEM);
    cudaFuncSetAttribute(hgemm_kernel<2>,
                         cudaFuncAttributeMaxDynamicSharedMemorySize, GSMEM);
    cudaFuncSetAttribute(attn_mma_kernel,
                         cudaFuncAttributeMaxDynamicSharedMemorySize, ATT_SMEM);

    seg_kernel<<<BB, 1024>>>(mask);
    rope_table_kernel<<<(LL * 16 + 255) / 256, 256>>>();
    conv_h_kernel<<<((QKV_DIM * DD + DD * DD) / 4 + 255) / 256, 256>>>(w_qkv, w_out);
    rmsnorm_kernel<<<M, 256>>>(x);

    hgemm_kernel<2><<<dim3(QKV_DIM / 128, M / 128), 256, GSMEM>>>(
        phh, pwqh, nullptr, nullptr, M, QKV_DIM, DD);

    attn_mma_kernel<<<dim3(LL / 64, NH, BB), 128, ATT_SMEM>>>();

    hgemm_kernel<1><<<dim3(DD / 128, M / 128), 256, GSMEM>>>(
        pyh, pwoh, x, out, M, DD, DD);
}

// round 8
// speedup vs baseline: 5.8630x; 1.0656x over previous
#include <cuda_runtime.h>
#include <cuda_fp16.h>
#include <math.h>
#include <stdint.h>

#define BB 2
#define LL 2048
#define DD 1024
#define NH 16
#define NKV 4
#define HD 64
#define WIN 1024
#define QKV_DIM 1536
#define EPSV 1.1920929e-07f

// ---------------- scratch (no cudaMalloc allowed) ----------------
__device__ __half g_hh[BB * LL * DD];        // rmsnorm(x) in fp16
__device__ __half g_wqkvh[QKV_DIM * DD];     // w_qkv fp16
__device__ __half g_wouth[DD * DD];          // w_out fp16
__device__ __half g_yh[BB * LL * DD];        // attention out fp16
__device__ __half g_qh[BB * NH * LL * HD];   // q fp16 (normed, roped, pre-scaled)
__device__ __half g_kh[BB * NKV * LL * HD];  // k fp16
__device__ __half g_vh[BB * NKV * LL * HD];  // v fp16
__device__ int    g_lo[BB * LL];
__device__ float4 g_rope[LL * 16];           // (c0,c1,s0,s1) per (l, pair)

// ---------------- ptx helpers ----------------
__device__ __forceinline__ uint32_t smem_u32(const void* p) {
    uint32_t a;
    asm("{ .reg .u64 t; cvta.to.shared.u64 t, %1; cvt.u32.u64 %0, t; }"
        : "=r"(a) : "l"(p));
    return a;
}
__device__ __forceinline__ void cp16(uint32_t smem_dst, const void* gsrc) {
    asm volatile("cp.async.cg.shared.global [%0], [%1], 16;\n"
                 :: "r"(smem_dst), "l"(gsrc));
}
__device__ __forceinline__ void cp_commit() {
    asm volatile("cp.async.commit_group;\n");
}
template <int N>
__device__ __forceinline__ void cp_wait() {
    asm volatile("cp.async.wait_group %0;\n" :: "n"(N));
}
__device__ __forceinline__ void ldsm4(uint32_t* r, uint32_t addr) {
    asm volatile("ldmatrix.sync.aligned.m8n8.x4.shared.b16 {%0,%1,%2,%3}, [%4];"
                 : "=r"(r[0]), "=r"(r[1]), "=r"(r[2]), "=r"(r[3]) : "r"(addr));
}
__device__ __forceinline__ void ldsm4t(uint32_t* r, uint32_t addr) {
    asm volatile("ldmatrix.sync.aligned.m8n8.x4.trans.shared.b16 {%0,%1,%2,%3}, [%4];"
                 : "=r"(r[0]), "=r"(r[1]), "=r"(r[2]), "=r"(r[3]) : "r"(addr));
}
__device__ __forceinline__ void mma_f16(float* c, const uint32_t* a, const uint32_t* b) {
    asm volatile(
        "mma.sync.aligned.m16n8k16.row.col.f32.f16.f16.f32 "
        "{%0,%1,%2,%3}, {%4,%5,%6,%7}, {%8,%9}, {%0,%1,%2,%3};"
        : "+f"(c[0]), "+f"(c[1]), "+f"(c[2]), "+f"(c[3])
        : "r"(a[0]), "r"(a[1]), "r"(a[2]), "r"(a[3]), "r"(b[0]), "r"(b[1]));
}

// ---------------- fused prep kernel ----------------
// block ranges: [0,2) seg scan | [2,130) rope table | [130,2690) weight conv
// | [2690, 6786) rmsnorm. All parts independent -> run concurrently.
#define NB_SEG  BB
#define NB_ROPE 128
#define NB_CONV 2560
#define NB_RMS  (BB * LL)
#define NB_TOT  (NB_SEG + NB_ROPE + NB_CONV + NB_RMS)

__global__ void __launch_bounds__(256) prep_kernel(
    const float* __restrict__ x, const float* __restrict__ wq,
    const float* __restrict__ wo, const void* __restrict__ mask)
{
    const int bid = blockIdx.x;
    const int t = threadIdx.x;

    if (bid < NB_SEG) {
        // ---- segment scan -> g_lo ----
        __shared__ int sA[256];
        __shared__ int sB[256];
        __shared__ int encs;
        const int b = bid;
        if (t == 0) {
            const unsigned* mi = (const unsigned*)mask;
            int e = 0;
            for (int i = 0; i < 64; i++) {
                unsigned v = mi[i];
                if (v == 0x3F800000u) { e = 2; break; }
                if (v > 1u) e = 1;
            }
            encs = e;
        }
        __syncthreads();
        const int e = encs;

        int pref[8];
        int run = 0;
        const int base = t * 8;
#pragma unroll
        for (int i = 0; i < 8; i++) {
            const int idx = base + i;
            int mset;
            if (e == 0)      mset = ((const int*)mask)[b * LL + idx] != 0;
            else if (e == 1) mset = ((const unsigned char*)mask)[b * LL + idx] != 0;
            else             mset = ((const float*)mask)[b * LL + idx] != 0.0f;
            run = max(run, mset ? idx : 0);
            pref[i] = run;
        }
        sA[t] = run;
        __syncthreads();
        int* s = sA;
        int* d = sB;
        for (int off = 1; off < 256; off <<= 1) {
            int v = s[t];
            if (t >= off) v = max(v, s[t - off]);
            d[t] = v;
            __syncthreads();
            int* tmp = s; s = d; d = tmp;
        }
        const int excl = (t > 0) ? s[t - 1] : 0;
#pragma unroll
        for (int i = 0; i < 8; i++) {
            const int idx = base + i;
            g_lo[b * LL + idx] = max(idx - (WIN - 1), max(excl, pref[i]));
        }
    } else if (bid < NB_SEG + NB_ROPE) {
        // ---- rope table ----
        const int i = (bid - NB_SEG) * 256 + t;   // < LL*16
        const int l = i >> 4;
        const int j = (i & 15) * 2;
        const float lg = logf(10000.0f) * (1.0f / 32.0f);
        const float f0 = expf(-lg * (float)j);
        const float f1 = expf(-lg * (float)(j + 1));
        float s0, c0, s1, c1;
        sincosf((float)l * f0, &s0, &c0);
        sincosf((float)l * f1, &s1, &c1);
        g_rope[i] = make_float4(c0, c1, s0, s1);
    } else if (bid < NB_SEG + NB_ROPE + NB_CONV) {
        // ---- weight fp32 -> fp16 ----
        const int n1 = QKV_DIM * DD;
        const int i = ((bid - NB_SEG - NB_ROPE) * 256 + t) * 4;
        if (i < n1) {
            float4 v = *(const float4*)(wq + i);
            *(__half2*)(g_wqkvh + i) = __floats2half2_rn(v.x, v.y);
            *(__half2*)(g_wqkvh + i + 2) = __floats2half2_rn(v.z, v.w);
        } else {
            const int k = i - n1;
            float4 v = *(const float4*)(wo + k);
            *(__half2*)(g_wouth + k) = __floats2half2_rn(v.x, v.y);
            *(__half2*)(g_wouth + k + 2) = __floats2half2_rn(v.z, v.w);
        }
    } else {
        // ---- rmsnorm over D -> fp16 ----
        const int row = bid - (NB_SEG + NB_ROPE + NB_CONV);
        const float4* xr = (const float4*)(x + (size_t)row * DD);
        __half2* hr = (__half2*)(g_hh + (size_t)row * DD);
        const float4 v = xr[t];
        float ss = v.x * v.x + v.y * v.y + v.z * v.z + v.w * v.w;

        __shared__ float red[8];
#pragma unroll
        for (int m = 16; m; m >>= 1) ss += __shfl_xor_sync(0xffffffffu, ss, m);
        if ((t & 31) == 0) red[t >> 5] = ss;
        __syncthreads();
        if (t < 8) {
            float r = red[t];
#pragma unroll
            for (int m = 4; m; m >>= 1) r += __shfl_xor_sync(0xffu, r, m, 8);
            if (t == 0) red[0] = r;
        }
        __syncthreads();
        const float inv = rsqrtf(red[0] * (1.0f / DD) + EPSV);
        hr[t * 2] = __floats2half2_rn(v.x * inv, v.y * inv);
        hr[t * 2 + 1] = __floats2half2_rn(v.z * inv, v.w * inv);
    }
}

// ---------------- fp16 mma.sync GEMM ----------------
// EPI=1: C = A@W^T + res (fp32 out). EPI=2: fused per-head rmsnorm+rope -> q/k/v fp16.
#define NSTG 3
#define STG_B (128 * 128)
#define GSMEM (2 * NSTG * STG_B)

template <int EPI>
__global__ void __launch_bounds__(256) hgemm_kernel(
    const __half* __restrict__ A, const __half* __restrict__ W,
    const float* __restrict__ res, float* __restrict__ C,
    int M, int N, int K)
{
    extern __shared__ char smem[];
    const uint32_t sb = smem_u32(smem);
    const uint32_t Asm = sb;
    const uint32_t Bsm = sb + NSTG * STG_B;

    const int t = threadIdx.x;
    const int lane = t & 31;
    const int wid = t >> 5;
    const int wm = (wid & 1) * 64;
    const int wn = (wid >> 1) * 32;
    const int m0 = blockIdx.y * 128;
    const int n0 = blockIdx.x * 128;

    const int lrow = t >> 1;
    const int lcb0 = (t & 1) * 64;
    const int lswz = (lrow & 7) << 4;
    const char* Agb = (const char*)(A + (size_t)(m0 + lrow) * K);
    const char* Wgb = (const char*)(W + (size_t)(n0 + lrow) * K);
    const uint32_t arow = Asm + lrow * 128;
    const uint32_t brow = Bsm + lrow * 128;

    float acc[4][4][4];
#pragma unroll
    for (int i = 0; i < 4; i++)
#pragma unroll
        for (int j = 0; j < 4; j++)
#pragma unroll
            for (int r = 0; r < 4; r++) acc[i][j][r] = 0.f;

    const int grp = lane >> 3;
    const int li = lane & 7;
    uint32_t a_ro[4]; int a_sw[4];
    uint32_t b_ro[2]; int b_sw[2];
#pragma unroll
    for (int mi = 0; mi < 4; mi++) {
        const int r = wm + mi * 16 + li + (grp & 1) * 8;
        a_ro[mi] = r * 128;
        a_sw[mi] = (r & 7) << 4;
    }
#pragma unroll
    for (int nb = 0; nb < 2; nb++) {
        const int r = wn + nb * 16 + li + (grp >> 1) * 8;
        b_ro[nb] = r * 128;
        b_sw[nb] = (r & 7) << 4;
    }
    const int a_g16 = (grp >> 1) * 16;
    const int b_g16 = (grp & 1) * 16;

    const int nch = K >> 6;

#pragma unroll
    for (int s = 0; s < NSTG - 1; s++) {
#pragma unroll
        for (int i = 0; i < 4; i++) {
            const int cb = lcb0 + i * 16;
            cp16(arow + s * STG_B + (cb ^ lswz), Agb + s * 128 + cb);
            cp16(brow + s * STG_B + (cb ^ lswz), Wgb + s * 128 + cb);
        }
        cp_commit();
    }

    for (int c = 0; c < nch; c++) {
        cp_wait<NSTG - 2>();
        __syncthreads();

        const int pf = c + NSTG - 1;
        if (pf < nch) {
            const int s = pf % NSTG;
#pragma unroll
            for (int i = 0; i < 4; i++) {
                const int cb = lcb0 + i * 16;
                cp16(arow + s * STG_B + (cb ^ lswz), Agb + (size_t)pf * 128 + cb);
                cp16(brow + s * STG_B + (cb ^ lswz), Wgb + (size_t)pf * 128 + cb);
            }
        }
        cp_commit();

        const uint32_t as = Asm + (c % NSTG) * STG_B;
        const uint32_t bs = Bsm + (c % NSTG) * STG_B;

#pragma unroll
        for (int ks = 0; ks < 4; ks++) {
            uint32_t af[4][4], bf[2][4];
#pragma unroll
            for (int mi = 0; mi < 4; mi++)
                ldsm4(af[mi], as + a_ro[mi] + ((ks * 32 + a_g16) ^ a_sw[mi]));
#pragma unroll
            for (int nb = 0; nb < 2; nb++)
                ldsm4(bf[nb], bs + b_ro[nb] + ((ks * 32 + b_g16) ^ b_sw[nb]));
#pragma unroll
            for (int mi = 0; mi < 4; mi++)
#pragma unroll
                for (int ni = 0; ni < 4; ni++)
                    mma_f16(acc[mi][ni], af[mi], &bf[ni >> 1][(ni & 1) * 2]);
        }
    }

    const int g = lane >> 2;
    const int tg = lane & 3;

    if (EPI == 1) {
#pragma unroll
        for (int mi = 0; mi < 4; mi++) {
#pragma unroll
            for (int ni = 0; ni < 4; ni++) {
                const int row = m0 + wm + mi * 16 + g;
                const int col = n0 + wn + ni * 8 + tg * 2;
                float2 v0 = make_float2(acc[mi][ni][0], acc[mi][ni][1]);
                float2 v1 = make_float2(acc[mi][ni][2], acc[mi][ni][3]);
                const float2 r0 = *(const float2*)(res + (size_t)row * N + col);
                const float2 r1 = *(const float2*)(res + (size_t)(row + 8) * N + col);
                v0.x += r0.x; v0.y += r0.y;
                v1.x += r1.x; v1.y += r1.y;
                *(float2*)(C + (size_t)row * N + col) = v0;
                *(float2*)(C + (size_t)(row + 8) * N + col) = v1;
            }
        }
    } else {
        // ---- fused qkv epilogue: stage tile to smem, per-head norm+rope ----
        __syncthreads();
        float* sf = (float*)smem;  // [128][132]
#pragma unroll
        for (int mi = 0; mi < 4; mi++) {
#pragma unroll
            for (int ni = 0; ni < 4; ni++) {
                const int r = wm + mi * 16 + g;
                const int cl = wn + ni * 8 + tg * 2;
                *(float2*)&sf[r * 132 + cl] = make_float2(acc[mi][ni][0], acc[mi][ni][1]);
                *(float2*)&sf[(r + 8) * 132 + cl] = make_float2(acc[mi][ni][2], acc[mi][ni][3]);
            }
        }
        __syncthreads();

        const int gi = t >> 4;
        const int tl = t & 15;
        const int j = tl * 2;
        const int hbase = n0 >> 6;

        for (int it = 0; it < 16; it++) {
            const int p = it * 16 + gi;
            const int r = p >> 1;
            const int hh = p & 1;
            const int head = hbase + hh;
            const int rowg = m0 + r;
            const int b = rowg >> 11;
            const int l = rowg & (LL - 1);
            const float* sr = &sf[r * 132 + hh * 64];

            const float a0 = sr[j], a1 = sr[j + 1];
            const float b0 = sr[j + 32], b1 = sr[j + 33];

            if (head < 20) {
                float ss = a0 * a0 + a1 * a1 + b0 * b0 + b1 * b1;
#pragma unroll
                for (int m = 8; m; m >>= 1)
                    ss += __shfl_xor_sync(0xffffffffu, ss, m, 16);
                const float inv = rsqrtf(ss * (1.0f / HD) + EPSV);
                const float4 rp = g_rope[l * 16 + tl];
                const float a0n = a0 * inv, a1n = a1 * inv;
                const float b0n = b0 * inv, b1n = b1 * inv;
                const float o0 = a0n * rp.x - b0n * rp.z;
                const float o1 = a1n * rp.y - b1n * rp.w;
                const float o2 = a0n * rp.z + b0n * rp.x;
                const float o3 = a1n * rp.w + b1n * rp.y;
                if (head < 16) {
                    const float sc = 0.125f;
                    __half* dq = g_qh + (((size_t)(b * NH + head)) * LL + l) * HD;
                    *(__half2*)(dq + j) = __floats2half2_rn(o0 * sc, o1 * sc);
                    *(__half2*)(dq + j + 32) = __floats2half2_rn(o2 * sc, o3 * sc);
                } else {
                    __half* dk = g_kh + (((size_t)(b * NKV + (head - 16))) * LL + l) * HD;
                    *(__half2*)(dk + j) = __floats2half2_rn(o0, o1);
                    *(__half2*)(dk + j + 32) = __floats2half2_rn(o2, o3);
                }
            } else {
                __half* dv = g_vh + (((size_t)(b * NKV + (head - 20))) * LL + l) * HD;
                *(__half2*)(dv + j) = __floats2half2_rn(a0, a1);
                *(__half2*)(dv + j + 32) = __floats2half2_rn(b0, b1);
            }
        }
    }
}

// ---------------- tensor-core flash attention ----------------
#define ATT_SMEM (5 * 8192)
__global__ void __launch_bounds__(128) attn_mma_kernel() {
    extern __shared__ char smc[];
    const uint32_t sb = smem_u32(smc);
    const uint32_t Qs = sb;
    const uint32_t Ks = sb + 8192;
    const uint32_t Vs = sb + 3 * 8192;
    __shared__ int lo_s[64];

    const int qb = blockIdx.x, h = blockIdx.y, b = blockIdx.z;
    const int t = threadIdx.x;
    const int lane = t & 31;
    const int w = t >> 5;
    const int q0 = qb * 64;
    const int kvh = h >> 2;
    const char* Qg = (const char*)(g_qh + (((size_t)(b * NH + h)) * LL + q0) * HD);
    const char* Kg = (const char*)(g_kh + ((size_t)(b * NKV + kvh)) * LL * HD);
    const char* Vg = (const char*)(g_vh + ((size_t)(b * NKV + kvh)) * LL * HD);

    const int kb0 = g_lo[b * LL + q0] & ~63;
    const int nt = ((q0 + 63 - kb0) >> 6) + 1;
    if (t < 64) lo_s[t] = g_lo[b * LL + q0 + t];

    const int lrow = t >> 1;
    const int lcb0 = (t & 1) * 64;
    const int lswz = (lrow & 7) << 4;
    const uint32_t qrow_s = Qs + lrow * 128;
    const uint32_t krow_s = Ks + lrow * 128;
    const uint32_t vrow_s = Vs + lrow * 128;

#pragma unroll
    for (int i = 0; i < 4; i++) {
        const int cb = lcb0 + i * 16;
        cp16(qrow_s + (cb ^ lswz), Qg + lrow * 128 + cb);
        cp16(krow_s + (cb ^ lswz), Kg + (size_t)(kb0 + lrow) * 128 + cb);
        cp16(vrow_s + (cb ^ lswz), Vg + (size_t)(kb0 + lrow) * 128 + cb);
    }
    cp_commit();

    const int grp = lane >> 3;
    const int li = lane & 7;
    const int g = lane >> 2;
    const int tg = lane & 3;
    const int row0 = w * 16 + g;
    const int qg0 = q0 + row0;
    const int qg1 = qg0 + 8;

    cp_wait<0>();
    __syncthreads();

    uint32_t aQ[4][4];
    {
        const int qr = w * 16 + li + (grp & 1) * 8;
        const uint32_t qa = Qs + qr * 128;
        const int qsw = (qr & 7) << 4;
        const int qg16 = (grp >> 1) * 16;
#pragma unroll
        for (int kk = 0; kk < 4; kk++)
            ldsm4(aQ[kk], qa + ((kk * 32 + qg16) ^ qsw));
    }

    const int lo0 = lo_s[row0];
    const int lo1 = lo_s[row0 + 8];

    uint32_t k_ro[4]; int k_sw[4];
    uint32_t v_co[4];
#pragma unroll
    for (int nb = 0; nb < 4; nb++) {
        const int r = nb * 16 + li + (grp >> 1) * 8;
        k_ro[nb] = r * 128;
        k_sw[nb] = (r & 7) << 4;
        v_co[nb] = nb * 32 + (grp >> 1) * 16;
    }
    const int k_g16 = (grp & 1) * 16;
    const int v_r8 = (grp & 1) * 8 + li;

    float m0 = -1e30f, m1 = -1e30f, l0 = 0.f, l1 = 0.f;
    float o[8][4];
#pragma unroll
    for (int jn = 0; jn < 8; jn++)
#pragma unroll
        for (int r = 0; r < 4; r++) o[jn][r] = 0.f;

    for (int i = 0; i < nt; i++) {
        const int kb = kb0 + i * 64;
        if (i + 1 < nt) {
            const int bo = ((i + 1) & 1) * 8192;
            const size_t go = (size_t)(kb + 64 + lrow) * 128;
#pragma unroll
            for (int c2 = 0; c2 < 4; c2++) {
                const int cb = lcb0 + c2 * 16;
                cp16(krow_s + bo + (cb ^ lswz), Kg + go + cb);
                cp16(vrow_s + bo + (cb ^ lswz), Vg + go + cb);
            }
        }
        cp_commit();
        cp_wait<1>();
        __syncthreads();

        const uint32_t Kb = Ks + (i & 1) * 8192;
        const uint32_t Vb = Vs + (i & 1) * 8192;

        float sc[8][4];
#pragma unroll
        for (int j = 0; j < 8; j++)
#pragma unroll
            for (int r = 0; r < 4; r++) sc[j][r] = 0.f;

#pragma unroll
        for (int kk = 0; kk < 4; kk++) {
            uint32_t bf[4][4];
#pragma unroll
            for (int nb = 0; nb < 4; nb++)
                ldsm4(bf[nb], Kb + k_ro[nb] + ((kk * 32 + k_g16) ^ k_sw[nb]));
#pragma unroll
            for (int j = 0; j < 8; j++)
                mma_f16(sc[j], aQ[kk], &bf[j >> 1][(j & 1) * 2]);
        }

        float mx0 = -1e30f, mx1 = -1e30f;
#pragma unroll
        for (int j = 0; j < 8; j++) {
            const int c0 = kb + j * 8 + tg * 2;
            const int c1 = c0 + 1;
            if (c0 < lo0 || c0 > qg0) sc[j][0] = -1e30f;
            if (c1 < lo0 || c1 > qg0) sc[j][1] = -1e30f;
            if (c0 < lo1 || c0 > qg1) sc[j][2] = -1e30f;
            if (c1 < lo1 || c1 > qg1) sc[j][3] = -1e30f;
            mx0 = fmaxf(mx0, fmaxf(sc[j][0], sc[j][1]));
            mx1 = fmaxf(mx1, fmaxf(sc[j][2], sc[j][3]));
        }
        mx0 = fmaxf(mx0, __shfl_xor_sync(0xffffffffu, mx0, 1));
        mx0 = fmaxf(mx0, __shfl_xor_sync(0xffffffffu, mx0, 2));
        mx1 = fmaxf(mx1, __shfl_xor_sync(0xffffffffu, mx1, 1));
        mx1 = fmaxf(mx1, __shfl_xor_sync(0xffffffffu, mx1, 2));

        const float mn0 = fmaxf(m0, mx0);
        const float mn1 = fmaxf(m1, mx1);
        const float al0 = __expf(m0 - mn0);
        const float al1 = __expf(m1 - mn1);

        float lp0 = 0.f, lp1 = 0.f;
        uint32_t ph[8][2];
#pragma unroll
        for (int j = 0; j < 8; j++) {
            const float p0 = (sc[j][0] > -1e29f) ? __expf(sc[j][0] - mn0) : 0.f;
            const float p1 = (sc[j][1] > -1e29f) ? __expf(sc[j][1] - mn0) : 0.f;
            const float p2 = (sc[j][2] > -1e29f) ? __expf(sc[j][2] - mn1) : 0.f;
            const float p3 = (sc[j][3] > -1e29f) ? __expf(sc[j][3] - mn1) : 0.f;
            lp0 += p0 + p1;
            lp1 += p2 + p3;
            __half2 h0 = __floats2half2_rn(p0, p1);
            __half2 h1 = __floats2half2_rn(p2, p3);
            ph[j][0] = *(uint32_t*)&h0;
            ph[j][1] = *(uint32_t*)&h1;
        }
        lp0 += __shfl_xor_sync(0xffffffffu, lp0, 1);
        lp0 += __shfl_xor_sync(0xffffffffu, lp0, 2);
        lp1 += __shfl_xor_sync(0xffffffffu, lp1, 1);
        lp1 += __shfl_xor_sync(0xffffffffu, lp1, 2);

        l0 = l0 * al0 + lp0;
        l1 = l1 * al1 + lp1;
        m0 = mn0; m1 = mn1;
#pragma unroll
        for (int jn = 0; jn < 8; jn++) {
            o[jn][0] *= al0; o[jn][1] *= al0;
            o[jn][2] *= al1; o[jn][3] *= al1;
        }

#pragma unroll
        for (int kk = 0; kk < 4; kk++) {
            uint32_t vf[4][4];
            const int vr = kk * 16 + v_r8;
            const uint32_t va = Vb + vr * 128;
            const int vsw = (vr & 7) << 4;
#pragma unroll
            for (int nb = 0; nb < 4; nb++)
                ldsm4t(vf[nb], va + (v_co[nb] ^ vsw));
            uint32_t aP[4] = { ph[2 * kk][0], ph[2 * kk][1],
                               ph[2 * kk + 1][0], ph[2 * kk + 1][1] };
#pragma unroll
            for (int jn = 0; jn < 8; jn++)
                mma_f16(o[jn], aP, &vf[jn >> 1][(jn & 1) * 2]);
        }
        __syncthreads();
    }

    const float iv0 = 1.0f / l0;
    const float iv1 = 1.0f / l1;
    __half* y0 = g_yh + ((size_t)(b * LL) + qg0) * DD + h * HD;
    __half* y1 = g_yh + ((size_t)(b * LL) + qg1) * DD + h * HD;
#pragma unroll
    for (int jn = 0; jn < 8; jn++) {
        __half2 r0 = __floats2half2_rn(o[jn][0] * iv0, o[jn][1] * iv0);
        __half2 r1 = __floats2half2_rn(o[jn][2] * iv1, o[jn][3] * iv1);
        *(__half2*)(y0 + jn * 8 + tg * 2) = r0;
        *(__half2*)(y1 + jn * 8 + tg * 2) = r1;
    }
}

// ---------------- launch ----------------
extern "C" void kernel_launch(void* const* d_in, const int* in_sizes, int n_in,
                              void* d_out, int out_size) {
    const float* x     = (const float*)d_in[0];
    const float* w_qkv = (const float*)d_in[1];
    const float* w_out = (const float*)d_in[2];
    const void*  mask  = d_in[3];
    float* out = (float*)d_out;

    __half *phh, *pwqh, *pwoh, *pyh;
    cudaGetSymbolAddress((void**)&phh, g_hh);
    cudaGetSymbolAddress((void**)&pwqh, g_wqkvh);
    cudaGetSymbolAddress((void**)&pwoh, g_wouth);
    cudaGetSymbolAddress((void**)&pyh, g_yh);

    const int M = BB * LL;

    cudaFuncSetAttribute(hgemm_kernel<1>,
                         cudaFuncAttributeMaxDynamicSharedMemorySize, GSMEM);
    cudaFuncSetAttribute(hgemm_kernel<2>,
                         cudaFuncAttributeMaxDynamicSharedMemorySize, GSMEM);
    cudaFuncSetAttribute(attn_mma_kernel,
                         cudaFuncAttributeMaxDynamicSharedMemorySize, ATT_SMEM);

    prep_kernel<<<NB_TOT, 256>>>(x, w_qkv, w_out, mask);

    hgemm_kernel<2><<<dim3(QKV_DIM / 128, M / 128), 256, GSMEM>>>(
        phh, pwqh, nullptr, nullptr, M, QKV_DIM, DD);

    attn_mma_kernel<<<dim3(LL / 64, NH, BB), 128, ATT_SMEM>>>();

    hgemm_kernel<1><<<dim3(DD / 128, M / 128), 256, GSMEM>>>(
        pyh, pwoh, x, out, M, DD, DD);
}

// round 9
// speedup vs baseline: 6.0609x; 1.0338x over previous
#include <cuda_runtime.h>
#include <cuda_fp16.h>
#include <math.h>
#include <stdint.h>

#define BB 2
#define LL 2048
#define DD 1024
#define NH 16
#define NKV 4
#define HD 64
#define WIN 1024
#define QKV_DIM 1536
#define EPSV 1.1920929e-07f

// ---------------- scratch (no cudaMalloc allowed) ----------------
__device__ __half g_hh[BB * LL * DD];
__device__ __half g_wqkvh[QKV_DIM * DD];
__device__ __half g_wouth[DD * DD];
__device__ __half g_yh[BB * LL * DD];
__device__ __half g_qh[BB * NH * LL * HD];
__device__ __half g_kh[BB * NKV * LL * HD];
__device__ __half g_vh[BB * NKV * LL * HD];
__device__ int    g_lo[BB * LL];
__device__ float4 g_rope[LL * 16];

// ---------------- ptx helpers ----------------
__device__ __forceinline__ uint32_t smem_u32(const void* p) {
    uint32_t a;
    asm("{ .reg .u64 t; cvta.to.shared.u64 t, %1; cvt.u32.u64 %0, t; }"
        : "=r"(a) : "l"(p));
    return a;
}
__device__ __forceinline__ void cp16(uint32_t smem_dst, const void* gsrc) {
    asm volatile("cp.async.cg.shared.global [%0], [%1], 16;\n"
                 :: "r"(smem_dst), "l"(gsrc));
}
__device__ __forceinline__ void cp_commit() {
    asm volatile("cp.async.commit_group;\n");
}
template <int N>
__device__ __forceinline__ void cp_wait() {
    asm volatile("cp.async.wait_group %0;\n" :: "n"(N));
}
__device__ __forceinline__ void ldsm4(uint32_t* r, uint32_t addr) {
    asm volatile("ldmatrix.sync.aligned.m8n8.x4.shared.b16 {%0,%1,%2,%3}, [%4];"
                 : "=r"(r[0]), "=r"(r[1]), "=r"(r[2]), "=r"(r[3]) : "r"(addr));
}
__device__ __forceinline__ void ldsm4t(uint32_t* r, uint32_t addr) {
    asm volatile("ldmatrix.sync.aligned.m8n8.x4.trans.shared.b16 {%0,%1,%2,%3}, [%4];"
                 : "=r"(r[0]), "=r"(r[1]), "=r"(r[2]), "=r"(r[3]) : "r"(addr));
}
__device__ __forceinline__ void mma_f16(float* c, const uint32_t* a, const uint32_t* b) {
    asm volatile(
        "mma.sync.aligned.m16n8k16.row.col.f32.f16.f16.f32 "
        "{%0,%1,%2,%3}, {%4,%5,%6,%7}, {%8,%9}, {%0,%1,%2,%3};"
        : "+f"(c[0]), "+f"(c[1]), "+f"(c[2]), "+f"(c[3])
        : "r"(a[0]), "r"(a[1]), "r"(a[2]), "r"(a[3]), "r"(b[0]), "r"(b[1]));
}

// ---------------- fused prep kernel ----------------
#define NB_SEG  BB
#define NB_ROPE 128
#define NB_CONV 2560
#define NB_RMS  (BB * LL)
#define NB_TOT  (NB_SEG + NB_ROPE + NB_CONV + NB_RMS)

__global__ void __launch_bounds__(256) prep_kernel(
    const float* __restrict__ x, const float* __restrict__ wq,
    const float* __restrict__ wo, const void* __restrict__ mask)
{
    const int bid = blockIdx.x;
    const int t = threadIdx.x;

    if (bid < NB_SEG) {
        __shared__ int sA[256];
        __shared__ int sB[256];
        __shared__ int encs;
        const int b = bid;
        if (t == 0) {
            const unsigned* mi = (const unsigned*)mask;
            int e = 0;
            for (int i = 0; i < 64; i++) {
                unsigned v = mi[i];
                if (v == 0x3F800000u) { e = 2; break; }
                if (v > 1u) e = 1;
            }
            encs = e;
        }
        __syncthreads();
        const int e = encs;

        int pref[8];
        int run = 0;
        const int base = t * 8;
#pragma unroll
        for (int i = 0; i < 8; i++) {
            const int idx = base + i;
            int mset;
            if (e == 0)      mset = ((const int*)mask)[b * LL + idx] != 0;
            else if (e == 1) mset = ((const unsigned char*)mask)[b * LL + idx] != 0;
            else             mset = ((const float*)mask)[b * LL + idx] != 0.0f;
            run = max(run, mset ? idx : 0);
            pref[i] = run;
        }
        sA[t] = run;
        __syncthreads();
        int* s = sA;
        int* d = sB;
        for (int off = 1; off < 256; off <<= 1) {
            int v = s[t];
            if (t >= off) v = max(v, s[t - off]);
            d[t] = v;
            __syncthreads();
            int* tmp = s; s = d; d = tmp;
        }
        const int excl = (t > 0) ? s[t - 1] : 0;
#pragma unroll
        for (int i = 0; i < 8; i++) {
            const int idx = base + i;
            g_lo[b * LL + idx] = max(idx - (WIN - 1), max(excl, pref[i]));
        }
    } else if (bid < NB_SEG + NB_ROPE) {
        const int i = (bid - NB_SEG) * 256 + t;
        const int l = i >> 4;
        const int j = (i & 15) * 2;
        const float lg = logf(10000.0f) * (1.0f / 32.0f);
        const float f0 = expf(-lg * (float)j);
        const float f1 = expf(-lg * (float)(j + 1));
        float s0, c0, s1, c1;
        sincosf((float)l * f0, &s0, &c0);
        sincosf((float)l * f1, &s1, &c1);
        g_rope[i] = make_float4(c0, c1, s0, s1);
    } else if (bid < NB_SEG + NB_ROPE + NB_CONV) {
        const int n1 = QKV_DIM * DD;
        const int i = ((bid - NB_SEG - NB_ROPE) * 256 + t) * 4;
        if (i < n1) {
            float4 v = *(const float4*)(wq + i);
            *(__half2*)(g_wqkvh + i) = __floats2half2_rn(v.x, v.y);
            *(__half2*)(g_wqkvh + i + 2) = __floats2half2_rn(v.z, v.w);
        } else {
            const int k = i - n1;
            float4 v = *(const float4*)(wo + k);
            *(__half2*)(g_wouth + k) = __floats2half2_rn(v.x, v.y);
            *(__half2*)(g_wouth + k + 2) = __floats2half2_rn(v.z, v.w);
        }
    } else {
        const int row = bid - (NB_SEG + NB_ROPE + NB_CONV);
        const float4* xr = (const float4*)(x + (size_t)row * DD);
        __half2* hr = (__half2*)(g_hh + (size_t)row * DD);
        const float4 v = xr[t];
        float ss = v.x * v.x + v.y * v.y + v.z * v.z + v.w * v.w;

        __shared__ float red[8];
#pragma unroll
        for (int m = 16; m; m >>= 1) ss += __shfl_xor_sync(0xffffffffu, ss, m);
        if ((t & 31) == 0) red[t >> 5] = ss;
        __syncthreads();
        if (t < 8) {
            float r = red[t];
#pragma unroll
            for (int m = 4; m; m >>= 1) r += __shfl_xor_sync(0xffu, r, m, 8);
            if (t == 0) red[0] = r;
        }
        __syncthreads();
        const float inv = rsqrtf(red[0] * (1.0f / DD) + EPSV);
        hr[t * 2] = __floats2half2_rn(v.x * inv, v.y * inv);
        hr[t * 2 + 1] = __floats2half2_rn(v.z * inv, v.w * inv);
    }
}

// ---------------- fp16 mma.sync GEMM, fragment-double-buffered ----------------
// 128x128 tile, BK=64, NSTG=4 stages (128KB smem -> 1 CTA/SM, regs unconstrained).
// EPI=1: C = A@W^T + res. EPI=2: fused per-head rmsnorm+rope -> q/k/v fp16.
#define NSTG 4
#define STG_B (128 * 128)
#define GSMEM (2 * NSTG * STG_B)

template <int EPI>
__global__ void __launch_bounds__(256) hgemm_kernel(
    const __half* __restrict__ A, const __half* __restrict__ W,
    const float* __restrict__ res, float* __restrict__ C,
    int M, int N, int K)
{
    extern __shared__ char smem[];
    const uint32_t sb = smem_u32(smem);
    const uint32_t Asm = sb;
    const uint32_t Bsm = sb + NSTG * STG_B;

    const int t = threadIdx.x;
    const int lane = t & 31;
    const int wid = t >> 5;
    const int wm = (wid & 1) * 64;
    const int wn = (wid >> 1) * 32;
    const int m0 = blockIdx.y * 128;
    const int n0 = blockIdx.x * 128;

    const int lrow = t >> 1;
    const int lcb0 = (t & 1) * 64;
    const int lswz = (lrow & 7) << 4;
    const char* Agb = (const char*)(A + (size_t)(m0 + lrow) * K);
    const char* Wgb = (const char*)(W + (size_t)(n0 + lrow) * K);
    const uint32_t arow = Asm + lrow * 128;
    const uint32_t brow = Bsm + lrow * 128;

    float acc[4][4][4];
#pragma unroll
    for (int i = 0; i < 4; i++)
#pragma unroll
        for (int j = 0; j < 4; j++)
#pragma unroll
            for (int r = 0; r < 4; r++) acc[i][j][r] = 0.f;

    const int grp = lane >> 3;
    const int li = lane & 7;
    uint32_t a_ro[4]; int a_sw[4];
    uint32_t b_ro[2]; int b_sw[2];
#pragma unroll
    for (int mi = 0; mi < 4; mi++) {
        const int r = wm + mi * 16 + li + (grp & 1) * 8;
        a_ro[mi] = r * 128;
        a_sw[mi] = (r & 7) << 4;
    }
#pragma unroll
    for (int nb = 0; nb < 2; nb++) {
        const int r = wn + nb * 16 + li + (grp >> 1) * 8;
        b_ro[nb] = r * 128;
        b_sw[nb] = (r & 7) << 4;
    }
    const int a_g16 = (grp >> 1) * 16;
    const int b_g16 = (grp & 1) * 16;

    const int nch = K >> 6;

    // preload stages 0..NSTG-2
#pragma unroll
    for (int s = 0; s < NSTG - 1; s++) {
#pragma unroll
        for (int i = 0; i < 4; i++) {
            const int cb = lcb0 + i * 16;
            cp16(arow + s * STG_B + (cb ^ lswz), Agb + s * 128 + cb);
            cp16(brow + s * STG_B + (cb ^ lswz), Wgb + s * 128 + cb);
        }
        cp_commit();
    }

    cp_wait<NSTG - 2>();
    __syncthreads();

    // fragment double buffers
    uint32_t af[2][4][4], bf[2][2][4];
#pragma unroll
    for (int mi = 0; mi < 4; mi++)
        ldsm4(af[0][mi], Asm + a_ro[mi] + (a_g16 ^ a_sw[mi]));
#pragma unroll
    for (int nb = 0; nb < 2; nb++)
        ldsm4(bf[0][nb], Bsm + b_ro[nb] + (b_g16 ^ b_sw[nb]));

    int buf = 0;
    for (int c = 0; c < nch; c++) {
        const uint32_t as = Asm + (c % NSTG) * STG_B;
        const uint32_t bs = Bsm + (c % NSTG) * STG_B;
        const uint32_t asn = Asm + ((c + 1) % NSTG) * STG_B;
        const uint32_t bsn = Bsm + ((c + 1) % NSTG) * STG_B;

#pragma unroll
        for (int ks = 0; ks < 4; ks++) {
            if (ks == 3) {
                // next chunk's stage must be ready before loading its frags
                cp_wait<NSTG - 2>();
                __syncthreads();
            }
            if (c < nch - 1 || ks < 3) {
                const uint32_t las = (ks < 3) ? as : asn;
                const uint32_t lbs = (ks < 3) ? bs : bsn;
                const int koff = ((ks + 1) & 3) * 32;
#pragma unroll
                for (int mi = 0; mi < 4; mi++)
                    ldsm4(af[buf ^ 1][mi], las + a_ro[mi] + ((koff + a_g16) ^ a_sw[mi]));
#pragma unroll
                for (int nb = 0; nb < 2; nb++)
                    ldsm4(bf[buf ^ 1][nb], lbs + b_ro[nb] + ((koff + b_g16) ^ b_sw[nb]));
            }
            if (ks == 0) {
                const int pf = c + NSTG - 1;
                if (pf < nch) {
                    const int s = pf % NSTG;
#pragma unroll
                    for (int i = 0; i < 4; i++) {
                        const int cb = lcb0 + i * 16;
                        cp16(arow + s * STG_B + (cb ^ lswz), Agb + (size_t)pf * 128 + cb);
                        cp16(brow + s * STG_B + (cb ^ lswz), Wgb + (size_t)pf * 128 + cb);
                    }
                }
                cp_commit();
            }
#pragma unroll
            for (int mi = 0; mi < 4; mi++)
#pragma unroll
                for (int ni = 0; ni < 4; ni++)
                    mma_f16(acc[mi][ni], af[buf][mi], &bf[buf][ni >> 1][(ni & 1) * 2]);
            buf ^= 1;
        }
    }

    const int g = lane >> 2;
    const int tg = lane & 3;

    if (EPI == 1) {
#pragma unroll
        for (int mi = 0; mi < 4; mi++) {
#pragma unroll
            for (int ni = 0; ni < 4; ni++) {
                const int row = m0 + wm + mi * 16 + g;
                const int col = n0 + wn + ni * 8 + tg * 2;
                float2 v0 = make_float2(acc[mi][ni][0], acc[mi][ni][1]);
                float2 v1 = make_float2(acc[mi][ni][2], acc[mi][ni][3]);
                const float2 r0 = *(const float2*)(res + (size_t)row * N + col);
                const float2 r1 = *(const float2*)(res + (size_t)(row + 8) * N + col);
                v0.x += r0.x; v0.y += r0.y;
                v1.x += r1.x; v1.y += r1.y;
                *(float2*)(C + (size_t)row * N + col) = v0;
                *(float2*)(C + (size_t)(row + 8) * N + col) = v1;
            }
        }
    } else {
        // ---- fused qkv epilogue: stage tile to smem, per-head norm+rope ----
        __syncthreads();
        float* sf = (float*)smem;  // [128][132]
#pragma unroll
        for (int mi = 0; mi < 4; mi++) {
#pragma unroll
            for (int ni = 0; ni < 4; ni++) {
                const int r = wm + mi * 16 + g;
                const int cl = wn + ni * 8 + tg * 2;
                *(float2*)&sf[r * 132 + cl] = make_float2(acc[mi][ni][0], acc[mi][ni][1]);
                *(float2*)&sf[(r + 8) * 132 + cl] = make_float2(acc[mi][ni][2], acc[mi][ni][3]);
            }
        }
        __syncthreads();

        const int gi = t >> 4;
        const int tl = t & 15;
        const int j = tl * 2;
        const int hbase = n0 >> 6;

        for (int it = 0; it < 16; it++) {
            const int p = it * 16 + gi;
            const int r = p >> 1;
            const int hh = p & 1;
            const int head = hbase + hh;
            const int rowg = m0 + r;
            const int b = rowg >> 11;
            const int l = rowg & (LL - 1);
            const float* sr = &sf[r * 132 + hh * 64];

            const float a0 = sr[j], a1 = sr[j + 1];
            const float b0 = sr[j + 32], b1 = sr[j + 33];

            if (head < 20) {
                float ss = a0 * a0 + a1 * a1 + b0 * b0 + b1 * b1;
#pragma unroll
                for (int m = 8; m; m >>= 1)
                    ss += __shfl_xor_sync(0xffffffffu, ss, m, 16);
                const float inv = rsqrtf(ss * (1.0f / HD) + EPSV);
                const float4 rp = g_rope[l * 16 + tl];
                const float a0n = a0 * inv, a1n = a1 * inv;
                const float b0n = b0 * inv, b1n = b1 * inv;
                const float o0 = a0n * rp.x - b0n * rp.z;
                const float o1 = a1n * rp.y - b1n * rp.w;
                const float o2 = a0n * rp.z + b0n * rp.x;
                const float o3 = a1n * rp.w + b1n * rp.y;
                if (head < 16) {
                    const float sc = 0.125f;
                    __half* dq = g_qh + (((size_t)(b * NH + head)) * LL + l) * HD;
                    *(__half2*)(dq + j) = __floats2half2_rn(o0 * sc, o1 * sc);
                    *(__half2*)(dq + j + 32) = __floats2half2_rn(o2 * sc, o3 * sc);
                } else {
                    __half* dk = g_kh + (((size_t)(b * NKV + (head - 16))) * LL + l) * HD;
                    *(__half2*)(dk + j) = __floats2half2_rn(o0, o1);
                    *(__half2*)(dk + j + 32) = __floats2half2_rn(o2, o3);
                }
            } else {
                __half* dv = g_vh + (((size_t)(b * NKV + (head - 20))) * LL + l) * HD;
                *(__half2*)(dv + j) = __floats2half2_rn(a0, a1);
                *(__half2*)(dv + j + 32) = __floats2half2_rn(b0, b1);
            }
        }
    }
}

// ---------------- tensor-core flash attention ----------------
#define ATT_SMEM (5 * 8192)
__global__ void __launch_bounds__(128) attn_mma_kernel() {
    extern __shared__ char smc[];
    const uint32_t sb = smem_u32(smc);
    const uint32_t Qs = sb;
    const uint32_t Ks = sb + 8192;
    const uint32_t Vs = sb + 3 * 8192;
    __shared__ int lo_s[64];

    const int qb = blockIdx.x, h = blockIdx.y, b = blockIdx.z;
    const int t = threadIdx.x;
    const int lane = t & 31;
    const int w = t >> 5;
    const int q0 = qb * 64;
    const int kvh = h >> 2;
    const char* Qg = (const char*)(g_qh + (((size_t)(b * NH + h)) * LL + q0) * HD);
    const char* Kg = (const char*)(g_kh + ((size_t)(b * NKV + kvh)) * LL * HD);
    const char* Vg = (const char*)(g_vh + ((size_t)(b * NKV + kvh)) * LL * HD);

    const int kb0 = g_lo[b * LL + q0] & ~63;
    const int nt = ((q0 + 63 - kb0) >> 6) + 1;
    if (t < 64) lo_s[t] = g_lo[b * LL + q0 + t];

    const int lrow = t >> 1;
    const int lcb0 = (t & 1) * 64;
    const int lswz = (lrow & 7) << 4;
    const uint32_t qrow_s = Qs + lrow * 128;
    const uint32_t krow_s = Ks + lrow * 128;
    const uint32_t vrow_s = Vs + lrow * 128;

#pragma unroll
    for (int i = 0; i < 4; i++) {
        const int cb = lcb0 + i * 16;
        cp16(qrow_s + (cb ^ lswz), Qg + lrow * 128 + cb);
        cp16(krow_s + (cb ^ lswz), Kg + (size_t)(kb0 + lrow) * 128 + cb);
        cp16(vrow_s + (cb ^ lswz), Vg + (size_t)(kb0 + lrow) * 128 + cb);
    }
    cp_commit();

    const int grp = lane >> 3;
    const int li = lane & 7;
    const int g = lane >> 2;
    const int tg = lane & 3;
    const int row0 = w * 16 + g;
    const int qg0 = q0 + row0;
    const int qg1 = qg0 + 8;

    cp_wait<0>();
    __syncthreads();

    uint32_t aQ[4][4];
    {
        const int qr = w * 16 + li + (grp & 1) * 8;
        const uint32_t qa = Qs + qr * 128;
        const int qsw = (qr & 7) << 4;
        const int qg16 = (grp >> 1) * 16;
#pragma unroll
        for (int kk = 0; kk < 4; kk++)
            ldsm4(aQ[kk], qa + ((kk * 32 + qg16) ^ qsw));
    }

    const int lo0 = lo_s[row0];
    const int lo1 = lo_s[row0 + 8];

    uint32_t k_ro[4]; int k_sw[4];
    uint32_t v_co[4];
#pragma unroll
    for (int nb = 0; nb < 4; nb++) {
        const int r = nb * 16 + li + (grp >> 1) * 8;
        k_ro[nb] = r * 128;
        k_sw[nb] = (r & 7) << 4;
        v_co[nb] = nb * 32 + (grp >> 1) * 16;
    }
    const int k_g16 = (grp & 1) * 16;
    const int v_r8 = (grp & 1) * 8 + li;

    float m0 = -1e30f, m1 = -1e30f, l0 = 0.f, l1 = 0.f;
    float o[8][4];
#pragma unroll
    for (int jn = 0; jn < 8; jn++)
#pragma unroll
        for (int r = 0; r < 4; r++) o[jn][r] = 0.f;

    for (int i = 0; i < nt; i++) {
        const int kb = kb0 + i * 64;
        if (i + 1 < nt) {
            const int bo = ((i + 1) & 1) * 8192;
            const size_t go = (size_t)(kb + 64 + lrow) * 128;
#pragma unroll
            for (int c2 = 0; c2 < 4; c2++) {
                const int cb = lcb0 + c2 * 16;
                cp16(krow_s + bo + (cb ^ lswz), Kg + go + cb);
                cp16(vrow_s + bo + (cb ^ lswz), Vg + go + cb);
            }
        }
        cp_commit();
        cp_wait<1>();
        __syncthreads();

        const uint32_t Kb = Ks + (i & 1) * 8192;
        const uint32_t Vb = Vs + (i & 1) * 8192;

        float sc[8][4];
#pragma unroll
        for (int j = 0; j < 8; j++)
#pragma unroll
            for (int r = 0; r < 4; r++) sc[j][r] = 0.f;

#pragma unroll
        for (int kk = 0; kk < 4; kk++) {
            uint32_t bfr[4][4];
#pragma unroll
            for (int nb = 0; nb < 4; nb++)
                ldsm4(bfr[nb], Kb + k_ro[nb] + ((kk * 32 + k_g16) ^ k_sw[nb]));
#pragma unroll
            for (int j = 0; j < 8; j++)
                mma_f16(sc[j], aQ[kk], &bfr[j >> 1][(j & 1) * 2]);
        }

        float mx0 = -1e30f, mx1 = -1e30f;
#pragma unroll
        for (int j = 0; j < 8; j++) {
            const int c0 = kb + j * 8 + tg * 2;
            const int c1 = c0 + 1;
            if (c0 < lo0 || c0 > qg0) sc[j][0] = -1e30f;
            if (c1 < lo0 || c1 > qg0) sc[j][1] = -1e30f;
            if (c0 < lo1 || c0 > qg1) sc[j][2] = -1e30f;
            if (c1 < lo1 || c1 > qg1) sc[j][3] = -1e30f;
            mx0 = fmaxf(mx0, fmaxf(sc[j][0], sc[j][1]));
            mx1 = fmaxf(mx1, fmaxf(sc[j][2], sc[j][3]));
        }
        mx0 = fmaxf(mx0, __shfl_xor_sync(0xffffffffu, mx0, 1));
        mx0 = fmaxf(mx0, __shfl_xor_sync(0xffffffffu, mx0, 2));
        mx1 = fmaxf(mx1, __shfl_xor_sync(0xffffffffu, mx1, 1));
        mx1 = fmaxf(mx1, __shfl_xor_sync(0xffffffffu, mx1, 2));

        const float mn0 = fmaxf(m0, mx0);
        const float mn1 = fmaxf(m1, mx1);
        const float al0 = __expf(m0 - mn0);
        const float al1 = __expf(m1 - mn1);

        float lp0 = 0.f, lp1 = 0.f;
        uint32_t ph[8][2];
#pragma unroll
        for (int j = 0; j < 8; j++) {
            const float p0 = (sc[j][0] > -1e29f) ? __expf(sc[j][0] - mn0) : 0.f;
            const float p1 = (sc[j][1] > -1e29f) ? __expf(sc[j][1] - mn0) : 0.f;
            const float p2 = (sc[j][2] > -1e29f) ? __expf(sc[j][2] - mn1) : 0.f;
            const float p3 = (sc[j][3] > -1e29f) ? __expf(sc[j][3] - mn1) : 0.f;
            lp0 += p0 + p1;
            lp1 += p2 + p3;
            __half2 h0 = __floats2half2_rn(p0, p1);
            __half2 h1 = __floats2half2_rn(p2, p3);
            ph[j][0] = *(uint32_t*)&h0;
            ph[j][1] = *(uint32_t*)&h1;
        }
        lp0 += __shfl_xor_sync(0xffffffffu, lp0, 1);
        lp0 += __shfl_xor_sync(0xffffffffu, lp0, 2);
        lp1 += __shfl_xor_sync(0xffffffffu, lp1, 1);
        lp1 += __shfl_xor_sync(0xffffffffu, lp1, 2);

        l0 = l0 * al0 + lp0;
        l1 = l1 * al1 + lp1;
        m0 = mn0; m1 = mn1;
#pragma unroll
        for (int jn = 0; jn < 8; jn++) {
            o[jn][0] *= al0; o[jn][1] *= al0;
            o[jn][2] *= al1; o[jn][3] *= al1;
        }

#pragma unroll
        for (int kk = 0; kk < 4; kk++) {
            uint32_t vf[4][4];
            const int vr = kk * 16 + v_r8;
            const uint32_t va = Vb + vr * 128;
            const int vsw = (vr & 7) << 4;
#pragma unroll
            for (int nb = 0; nb < 4; nb++)
                ldsm4t(vf[nb], va + (v_co[nb] ^ vsw));
            uint32_t aP[4] = { ph[2 * kk][0], ph[2 * kk][1],
                               ph[2 * kk + 1][0], ph[2 * kk + 1][1] };
#pragma unroll
            for (int jn = 0; jn < 8; jn++)
                mma_f16(o[jn], aP, &vf[jn >> 1][(jn & 1) * 2]);
        }
        __syncthreads();
    }

    const float iv0 = 1.0f / l0;
    const float iv1 = 1.0f / l1;
    __half* y0 = g_yh + ((size_t)(b * LL) + qg0) * DD + h * HD;
    __half* y1 = g_yh + ((size_t)(b * LL) + qg1) * DD + h * HD;
#pragma unroll
    for (int jn = 0; jn < 8; jn++) {
        __half2 r0 = __floats2half2_rn(o[jn][0] * iv0, o[jn][1] * iv0);
        __half2 r1 = __floats2half2_rn(o[jn][2] * iv1, o[jn][3] * iv1);
        *(__half2*)(y0 + jn * 8 + tg * 2) = r0;
        *(__half2*)(y1 + jn * 8 + tg * 2) = r1;
    }
}

// ---------------- launch ----------------
extern "C" void kernel_launch(void* const* d_in, const int* in_sizes, int n_in,
                              void* d_out, int out_size) {
    const float* x     = (const float*)d_in[0];
    const float* w_qkv = (const float*)d_in[1];
    const float* w_out = (const float*)d_in[2];
    const void*  mask  = d_in[3];
    float* out = (float*)d_out;

    __half *phh, *pwqh, *pwoh, *pyh;
    cudaGetSymbolAddress((void**)&phh, g_hh);
    cudaGetSymbolAddress((void**)&pwqh, g_wqkvh);
    cudaGetSymbolAddress((void**)&pwoh, g_wouth);
    cudaGetSymbolAddress((void**)&pyh, g_yh);

    const int M = BB * LL;

    cudaFuncSetAttribute(hgemm_kernel<1>,
                         cudaFuncAttributeMaxDynamicSharedMemorySize, GSMEM);
    cudaFuncSetAttribute(hgemm_kernel<2>,
                         cudaFuncAttributeMaxDynamicSharedMemorySize, GSMEM);
    cudaFuncSetAttribute(attn_mma_kernel,
                         cudaFuncAttributeMaxDynamicSharedMemorySize, ATT_SMEM);

    prep_kernel<<<NB_TOT, 256>>>(x, w_qkv, w_out, mask);

    hgemm_kernel<2><<<dim3(QKV_DIM / 128, M / 128), 256, GSMEM>>>(
        phh, pwqh, nullptr, nullptr, M, QKV_DIM, DD);

    attn_mma_kernel<<<dim3(LL / 64, NH, BB), 128, ATT_SMEM>>>();

    hgemm_kernel<1><<<dim3(DD / 128, M / 128), 256, GSMEM>>>(
        pyh, pwoh, x, out, M, DD, DD);
}

// round 10
// speedup vs baseline: 7.0073x; 1.1561x over previous
#include <cuda_runtime.h>
#include <cuda_fp16.h>
#include <math.h>
#include <stdint.h>

#define BB 2
#define LL 2048
#define DD 1024
#define NH 16
#define NKV 4
#define HD 64
#define WIN 1024
#define QKV_DIM 1536
#define EPSV 1.1920929e-07f

// ---------------- scratch (no cudaMalloc allowed) ----------------
__device__ __half g_hh[BB * LL * DD];
__device__ __half g_wqkvh[QKV_DIM * DD];
__device__ __half g_wouth[DD * DD];
__device__ __half g_yh[BB * LL * DD];
__device__ __half g_qh[BB * NH * LL * HD];
__device__ __half g_kh[BB * NKV * LL * HD];
__device__ __half g_vh[BB * NKV * LL * HD];
__device__ int    g_lo[BB * LL];
__device__ float4 g_rope[LL * 16];

// ---------------- ptx helpers ----------------
__device__ __forceinline__ uint32_t smem_u32(const void* p) {
    uint32_t a;
    asm("{ .reg .u64 t; cvta.to.shared.u64 t, %1; cvt.u32.u64 %0, t; }"
        : "=r"(a) : "l"(p));
    return a;
}
__device__ __forceinline__ void cp16(uint32_t smem_dst, const void* gsrc) {
    asm volatile("cp.async.cg.shared.global [%0], [%1], 16;\n"
                 :: "r"(smem_dst), "l"(gsrc));
}
__device__ __forceinline__ void cp_commit() {
    asm volatile("cp.async.commit_group;\n");
}
template <int N>
__device__ __forceinline__ void cp_wait() {
    asm volatile("cp.async.wait_group %0;\n" :: "n"(N));
}
__device__ __forceinline__ void ldsm4(uint32_t* r, uint32_t addr) {
    asm volatile("ldmatrix.sync.aligned.m8n8.x4.shared.b16 {%0,%1,%2,%3}, [%4];"
                 : "=r"(r[0]), "=r"(r[1]), "=r"(r[2]), "=r"(r[3]) : "r"(addr));
}
__device__ __forceinline__ void ldsm4t(uint32_t* r, uint32_t addr) {
    asm volatile("ldmatrix.sync.aligned.m8n8.x4.trans.shared.b16 {%0,%1,%2,%3}, [%4];"
                 : "=r"(r[0]), "=r"(r[1]), "=r"(r[2]), "=r"(r[3]) : "r"(addr));
}
__device__ __forceinline__ void mma_f16(float* c, const uint32_t* a, const uint32_t* b) {
    asm volatile(
        "mma.sync.aligned.m16n8k16.row.col.f32.f16.f16.f32 "
        "{%0,%1,%2,%3}, {%4,%5,%6,%7}, {%8,%9}, {%0,%1,%2,%3};"
        : "+f"(c[0]), "+f"(c[1]), "+f"(c[2]), "+f"(c[3])
        : "r"(a[0]), "r"(a[1]), "r"(a[2]), "r"(a[3]), "r"(b[0]), "r"(b[1]));
}

// ---------------- fused prep kernel ----------------
#define NB_SEG  BB
#define NB_ROPE 128
#define NB_CONV 2560
#define NB_RMS  (BB * LL)
#define NB_TOT  (NB_SEG + NB_ROPE + NB_CONV + NB_RMS)

__global__ void __launch_bounds__(256) prep_kernel(
    const float* __restrict__ x, const float* __restrict__ wq,
    const float* __restrict__ wo, const void* __restrict__ mask)
{
    const int bid = blockIdx.x;
    const int t = threadIdx.x;

    if (bid < NB_SEG) {
        __shared__ int sA[256];
        __shared__ int sB[256];
        __shared__ int encs;
        const int b = bid;
        if (t == 0) {
            const unsigned* mi = (const unsigned*)mask;
            int e = 0;
            for (int i = 0; i < 64; i++) {
                unsigned v = mi[i];
                if (v == 0x3F800000u) { e = 2; break; }
                if (v > 1u) e = 1;
            }
            encs = e;
        }
        __syncthreads();
        const int e = encs;

        int pref[8];
        int run = 0;
        const int base = t * 8;
#pragma unroll
        for (int i = 0; i < 8; i++) {
            const int idx = base + i;
            int mset;
            if (e == 0)      mset = ((const int*)mask)[b * LL + idx] != 0;
            else if (e == 1) mset = ((const unsigned char*)mask)[b * LL + idx] != 0;
            else             mset = ((const float*)mask)[b * LL + idx] != 0.0f;
            run = max(run, mset ? idx : 0);
            pref[i] = run;
        }
        sA[t] = run;
        __syncthreads();
        int* s = sA;
        int* d = sB;
        for (int off = 1; off < 256; off <<= 1) {
            int v = s[t];
            if (t >= off) v = max(v, s[t - off]);
            d[t] = v;
            __syncthreads();
            int* tmp = s; s = d; d = tmp;
        }
        const int excl = (t > 0) ? s[t - 1] : 0;
#pragma unroll
        for (int i = 0; i < 8; i++) {
            const int idx = base + i;
            g_lo[b * LL + idx] = max(idx - (WIN - 1), max(excl, pref[i]));
        }
    } else if (bid < NB_SEG + NB_ROPE) {
        const int i = (bid - NB_SEG) * 256 + t;
        const int l = i >> 4;
        const int j = (i & 15) * 2;
        const float lg = logf(10000.0f) * (1.0f / 32.0f);
        const float f0 = expf(-lg * (float)j);
        const float f1 = expf(-lg * (float)(j + 1));
        float s0, c0, s1, c1;
        sincosf((float)l * f0, &s0, &c0);
        sincosf((float)l * f1, &s1, &c1);
        g_rope[i] = make_float4(c0, c1, s0, s1);
    } else if (bid < NB_SEG + NB_ROPE + NB_CONV) {
        const int n1 = QKV_DIM * DD;
        const int i = ((bid - NB_SEG - NB_ROPE) * 256 + t) * 4;
        if (i < n1) {
            float4 v = *(const float4*)(wq + i);
            *(__half2*)(g_wqkvh + i) = __floats2half2_rn(v.x, v.y);
            *(__half2*)(g_wqkvh + i + 2) = __floats2half2_rn(v.z, v.w);
        } else {
            const int k = i - n1;
            float4 v = *(const float4*)(wo + k);
            *(__half2*)(g_wouth + k) = __floats2half2_rn(v.x, v.y);
            *(__half2*)(g_wouth + k + 2) = __floats2half2_rn(v.z, v.w);
        }
    } else {
        const int row = bid - (NB_SEG + NB_ROPE + NB_CONV);
        const float4* xr = (const float4*)(x + (size_t)row * DD);
        __half2* hr = (__half2*)(g_hh + (size_t)row * DD);
        const float4 v = xr[t];
        float ss = v.x * v.x + v.y * v.y + v.z * v.z + v.w * v.w;

        __shared__ float red[8];
#pragma unroll
        for (int m = 16; m; m >>= 1) ss += __shfl_xor_sync(0xffffffffu, ss, m);
        if ((t & 31) == 0) red[t >> 5] = ss;
        __syncthreads();
        if (t < 8) {
            float r = red[t];
#pragma unroll
            for (int m = 4; m; m >>= 1) r += __shfl_xor_sync(0xffu, r, m, 8);
            if (t == 0) red[0] = r;
        }
        __syncthreads();
        const float inv = rsqrtf(red[0] * (1.0f / DD) + EPSV);
        hr[t * 2] = __floats2half2_rn(v.x * inv, v.y * inv);
        hr[t * 2 + 1] = __floats2half2_rn(v.z * inv, v.w * inv);
    }
}

// ---------------- fp16 mma.sync GEMM: 512 threads, 16 warps (4/SMSP) ----------------
// 128x128 tile, BK=64, NSTG=4 (128KB smem -> 1 CTA/SM). Warp tile 32x32 (4m x 4n).
// Fragment double-buffered. EPI=1: C=A@W^T+res. EPI=2: fused rmsnorm+rope qkv.
#define NSTG 4
#define STG_B (128 * 128)
#define GSMEM (2 * NSTG * STG_B)

template <int EPI>
__global__ void __launch_bounds__(512) hgemm_kernel(
    const __half* __restrict__ A, const __half* __restrict__ W,
    const float* __restrict__ res, float* __restrict__ C,
    int M, int N, int K)
{
    extern __shared__ char smem[];
    const uint32_t sb = smem_u32(smem);
    const uint32_t Asm = sb;
    const uint32_t Bsm = sb + NSTG * STG_B;

    const int t = threadIdx.x;
    const int lane = t & 31;
    const int wid = t >> 5;               // 0..15
    const int wm = (wid & 3) * 32;        // 4 m-warps
    const int wn = (wid >> 2) * 32;       // 4 n-warps
    const int m0 = blockIdx.y * 128;
    const int n0 = blockIdx.x * 128;

    // loader: 512 threads; thread -> row t/4, 2 x 16B chunks at (t&3)*32
    const int lrow = t >> 2;
    const int lcb0 = (t & 3) * 32;
    const int lswz = (lrow & 7) << 4;
    const char* Agb = (const char*)(A + (size_t)(m0 + lrow) * K);
    const char* Wgb = (const char*)(W + (size_t)(n0 + lrow) * K);
    const uint32_t arow = Asm + lrow * 128;
    const uint32_t brow = Bsm + lrow * 128;

    float acc[2][4][4];
#pragma unroll
    for (int i = 0; i < 2; i++)
#pragma unroll
        for (int j = 0; j < 4; j++)
#pragma unroll
            for (int r = 0; r < 4; r++) acc[i][j][r] = 0.f;

    const int grp = lane >> 3;
    const int li = lane & 7;
    uint32_t a_ro[2]; int a_sw[2];
    uint32_t b_ro[2]; int b_sw[2];
#pragma unroll
    for (int mi = 0; mi < 2; mi++) {
        const int r = wm + mi * 16 + li + (grp & 1) * 8;
        a_ro[mi] = r * 128;
        a_sw[mi] = (r & 7) << 4;
    }
#pragma unroll
    for (int nb = 0; nb < 2; nb++) {
        const int r = wn + nb * 16 + li + (grp >> 1) * 8;
        b_ro[nb] = r * 128;
        b_sw[nb] = (r & 7) << 4;
    }
    const int a_g16 = (grp >> 1) * 16;
    const int b_g16 = (grp & 1) * 16;

    const int nch = K >> 6;

    // preload stages 0..NSTG-2
#pragma unroll
    for (int s = 0; s < NSTG - 1; s++) {
#pragma unroll
        for (int i = 0; i < 2; i++) {
            const int cb = lcb0 + i * 16;
            cp16(arow + s * STG_B + (cb ^ lswz), Agb + s * 128 + cb);
            cp16(brow + s * STG_B + (cb ^ lswz), Wgb + s * 128 + cb);
        }
        cp_commit();
    }

    cp_wait<NSTG - 2>();
    __syncthreads();

    // fragment double buffers
    uint32_t af[2][2][4], bf[2][2][4];
#pragma unroll
    for (int mi = 0; mi < 2; mi++)
        ldsm4(af[0][mi], Asm + a_ro[mi] + (a_g16 ^ a_sw[mi]));
#pragma unroll
    for (int nb = 0; nb < 2; nb++)
        ldsm4(bf[0][nb], Bsm + b_ro[nb] + (b_g16 ^ b_sw[nb]));

    int buf = 0;
    for (int c = 0; c < nch; c++) {
        const uint32_t as = Asm + (c % NSTG) * STG_B;
        const uint32_t bs = Bsm + (c % NSTG) * STG_B;
        const uint32_t asn = Asm + ((c + 1) % NSTG) * STG_B;
        const uint32_t bsn = Bsm + ((c + 1) % NSTG) * STG_B;

#pragma unroll
        for (int ks = 0; ks < 4; ks++) {
            if (ks == 3) {
                cp_wait<NSTG - 2>();
                __syncthreads();
            }
            if (c < nch - 1 || ks < 3) {
                const uint32_t las = (ks < 3) ? as : asn;
                const uint32_t lbs = (ks < 3) ? bs : bsn;
                const int koff = ((ks + 1) & 3) * 32;
#pragma unroll
                for (int mi = 0; mi < 2; mi++)
                    ldsm4(af[buf ^ 1][mi], las + a_ro[mi] + ((koff + a_g16) ^ a_sw[mi]));
#pragma unroll
                for (int nb = 0; nb < 2; nb++)
                    ldsm4(bf[buf ^ 1][nb], lbs + b_ro[nb] + ((koff + b_g16) ^ b_sw[nb]));
            }
            if (ks == 0) {
                const int pf = c + NSTG - 1;
                if (pf < nch) {
                    const int s = pf % NSTG;
#pragma unroll
                    for (int i = 0; i < 2; i++) {
                        const int cb = lcb0 + i * 16;
                        cp16(arow + s * STG_B + (cb ^ lswz), Agb + (size_t)pf * 128 + cb);
                        cp16(brow + s * STG_B + (cb ^ lswz), Wgb + (size_t)pf * 128 + cb);
                    }
                }
                cp_commit();
            }
#pragma unroll
            for (int mi = 0; mi < 2; mi++)
#pragma unroll
                for (int ni = 0; ni < 4; ni++)
                    mma_f16(acc[mi][ni], af[buf][mi], &bf[buf][ni >> 1][(ni & 1) * 2]);
            buf ^= 1;
        }
    }

    const int g = lane >> 2;
    const int tg = lane & 3;

    if (EPI == 1) {
#pragma unroll
        for (int mi = 0; mi < 2; mi++) {
#pragma unroll
            for (int ni = 0; ni < 4; ni++) {
                const int row = m0 + wm + mi * 16 + g;
                const int col = n0 + wn + ni * 8 + tg * 2;
                float2 v0 = make_float2(acc[mi][ni][0], acc[mi][ni][1]);
                float2 v1 = make_float2(acc[mi][ni][2], acc[mi][ni][3]);
                const float2 r0 = *(const float2*)(res + (size_t)row * N + col);
                const float2 r1 = *(const float2*)(res + (size_t)(row + 8) * N + col);
                v0.x += r0.x; v0.y += r0.y;
                v1.x += r1.x; v1.y += r1.y;
                *(float2*)(C + (size_t)row * N + col) = v0;
                *(float2*)(C + (size_t)(row + 8) * N + col) = v1;
            }
        }
    } else {
        // ---- fused qkv epilogue: stage tile to smem, per-head norm+rope ----
        __syncthreads();
        float* sf = (float*)smem;  // [128][132]
#pragma unroll
        for (int mi = 0; mi < 2; mi++) {
#pragma unroll
            for (int ni = 0; ni < 4; ni++) {
                const int r = wm + mi * 16 + g;
                const int cl = wn + ni * 8 + tg * 2;
                *(float2*)&sf[r * 132 + cl] = make_float2(acc[mi][ni][0], acc[mi][ni][1]);
                *(float2*)&sf[(r + 8) * 132 + cl] = make_float2(acc[mi][ni][2], acc[mi][ni][3]);
            }
        }
        __syncthreads();

        const int gi = t >> 4;        // group 0..31
        const int tl = t & 15;
        const int j = tl * 2;
        const int hbase = n0 >> 6;

        for (int it = 0; it < 8; it++) {
            const int p = it * 32 + gi;   // 256 (row, head-in-tile) pairs
            const int r = p >> 1;
            const int hh = p & 1;
            const int head = hbase + hh;
            const int rowg = m0 + r;
            const int b = rowg >> 11;
            const int l = rowg & (LL - 1);
            const float* sr = &sf[r * 132 + hh * 64];

            const float a0 = sr[j], a1 = sr[j + 1];
            const float b0 = sr[j + 32], b1 = sr[j + 33];

            if (head < 20) {
                float ss = a0 * a0 + a1 * a1 + b0 * b0 + b1 * b1;
#pragma unroll
                for (int m = 8; m; m >>= 1)
                    ss += __shfl_xor_sync(0xffffffffu, ss, m, 16);
                const float inv = rsqrtf(ss * (1.0f / HD) + EPSV);
                const float4 rp = g_rope[l * 16 + tl];
                const float a0n = a0 * inv, a1n = a1 * inv;
                const float b0n = b0 * inv, b1n = b1 * inv;
                const float o0 = a0n * rp.x - b0n * rp.z;
                const float o1 = a1n * rp.y - b1n * rp.w;
                const float o2 = a0n * rp.z + b0n * rp.x;
                const float o3 = a1n * rp.w + b1n * rp.y;
                if (head < 16) {
                    const float sc = 0.125f;
                    __half* dq = g_qh + (((size_t)(b * NH + head)) * LL + l) * HD;
                    *(__half2*)(dq + j) = __floats2half2_rn(o0 * sc, o1 * sc);
                    *(__half2*)(dq + j + 32) = __floats2half2_rn(o2 * sc, o3 * sc);
                } else {
                    __half* dk = g_kh + (((size_t)(b * NKV + (head - 16))) * LL + l) * HD;
                    *(__half2*)(dk + j) = __floats2half2_rn(o0, o1);
                    *(__half2*)(dk + j + 32) = __floats2half2_rn(o2, o3);
                }
            } else {
                __half* dv = g_vh + (((size_t)(b * NKV + (head - 20))) * LL + l) * HD;
                *(__half2*)(dv + j) = __floats2half2_rn(a0, a1);
                *(__half2*)(dv + j + 32) = __floats2half2_rn(b0, b1);
            }
        }
    }
}

// ---------------- tensor-core flash attention ----------------
#define ATT_SMEM (5 * 8192)
__global__ void __launch_bounds__(128) attn_mma_kernel() {
    extern __shared__ char smc[];
    const uint32_t sb = smem_u32(smc);
    const uint32_t Qs = sb;
    const uint32_t Ks = sb + 8192;
    const uint32_t Vs = sb + 3 * 8192;
    __shared__ int lo_s[64];

    const int qb = blockIdx.x, h = blockIdx.y, b = blockIdx.z;
    const int t = threadIdx.x;
    const int lane = t & 31;
    const int w = t >> 5;
    const int q0 = qb * 64;
    const int kvh = h >> 2;
    const char* Qg = (const char*)(g_qh + (((size_t)(b * NH + h)) * LL + q0) * HD);
    const char* Kg = (const char*)(g_kh + ((size_t)(b * NKV + kvh)) * LL * HD);
    const char* Vg = (const char*)(g_vh + ((size_t)(b * NKV + kvh)) * LL * HD);

    const int kb0 = g_lo[b * LL + q0] & ~63;
    const int nt = ((q0 + 63 - kb0) >> 6) + 1;
    if (t < 64) lo_s[t] = g_lo[b * LL + q0 + t];

    const int lrow = t >> 1;
    const int lcb0 = (t & 1) * 64;
    const int lswz = (lrow & 7) << 4;
    const uint32_t qrow_s = Qs + lrow * 128;
    const uint32_t krow_s = Ks + lrow * 128;
    const uint32_t vrow_s = Vs + lrow * 128;

#pragma unroll
    for (int i = 0; i < 4; i++) {
        const int cb = lcb0 + i * 16;
        cp16(qrow_s + (cb ^ lswz), Qg + lrow * 128 + cb);
        cp16(krow_s + (cb ^ lswz), Kg + (size_t)(kb0 + lrow) * 128 + cb);
        cp16(vrow_s + (cb ^ lswz), Vg + (size_t)(kb0 + lrow) * 128 + cb);
    }
    cp_commit();

    const int grp = lane >> 3;
    const int li = lane & 7;
    const int g = lane >> 2;
    const int tg = lane & 3;
    const int row0 = w * 16 + g;
    const int qg0 = q0 + row0;
    const int qg1 = qg0 + 8;

    cp_wait<0>();
    __syncthreads();

    uint32_t aQ[4][4];
    {
        const int qr = w * 16 + li + (grp & 1) * 8;
        const uint32_t qa = Qs + qr * 128;
        const int qsw = (qr & 7) << 4;
        const int qg16 = (grp >> 1) * 16;
#pragma unroll
        for (int kk = 0; kk < 4; kk++)
            ldsm4(aQ[kk], qa + ((kk * 32 + qg16) ^ qsw));
    }

    const int lo0 = lo_s[row0];
    const int lo1 = lo_s[row0 + 8];

    uint32_t k_ro[4]; int k_sw[4];
    uint32_t v_co[4];
#pragma unroll
    for (int nb = 0; nb < 4; nb++) {
        const int r = nb * 16 + li + (grp >> 1) * 8;
        k_ro[nb] = r * 128;
        k_sw[nb] = (r & 7) << 4;
        v_co[nb] = nb * 32 + (grp >> 1) * 16;
    }
    const int k_g16 = (grp & 1) * 16;
    const int v_r8 = (grp & 1) * 8 + li;

    float m0 = -1e30f, m1 = -1e30f, l0 = 0.f, l1 = 0.f;
    float o[8][4];
#pragma unroll
    for (int jn = 0; jn < 8; jn++)
#pragma unroll
        for (int r = 0; r < 4; r++) o[jn][r] = 0.f;

    for (int i = 0; i < nt; i++) {
        const int kb = kb0 + i * 64;
        if (i + 1 < nt) {
            const int bo = ((i + 1) & 1) * 8192;
            const size_t go = (size_t)(kb + 64 + lrow) * 128;
#pragma unroll
            for (int c2 = 0; c2 < 4; c2++) {
                const int cb = lcb0 + c2 * 16;
                cp16(krow_s + bo + (cb ^ lswz), Kg + go + cb);
                cp16(vrow_s + bo + (cb ^ lswz), Vg + go + cb);
            }
        }
        cp_commit();
        cp_wait<1>();
        __syncthreads();

        const uint32_t Kb = Ks + (i & 1) * 8192;
        const uint32_t Vb = Vs + (i & 1) * 8192;

        float sc[8][4];
#pragma unroll
        for (int j = 0; j < 8; j++)
#pragma unroll
            for (int r = 0; r < 4; r++) sc[j][r] = 0.f;

#pragma unroll
        for (int kk = 0; kk < 4; kk++) {
            uint32_t bfr[4][4];
#pragma unroll
            for (int nb = 0; nb < 4; nb++)
                ldsm4(bfr[nb], Kb + k_ro[nb] + ((kk * 32 + k_g16) ^ k_sw[nb]));
#pragma unroll
            for (int j = 0; j < 8; j++)
                mma_f16(sc[j], aQ[kk], &bfr[j >> 1][(j & 1) * 2]);
        }

        float mx0 = -1e30f, mx1 = -1e30f;
#pragma unroll
        for (int j = 0; j < 8; j++) {
            const int c0 = kb + j * 8 + tg * 2;
            const int c1 = c0 + 1;
            if (c0 < lo0 || c0 > qg0) sc[j][0] = -1e30f;
            if (c1 < lo0 || c1 > qg0) sc[j][1] = -1e30f;
            if (c0 < lo1 || c0 > qg1) sc[j][2] = -1e30f;
            if (c1 < lo1 || c1 > qg1) sc[j][3] = -1e30f;
            mx0 = fmaxf(mx0, fmaxf(sc[j][0], sc[j][1]));
            mx1 = fmaxf(mx1, fmaxf(sc[j][2], sc[j][3]));
        }
        mx0 = fmaxf(mx0, __shfl_xor_sync(0xffffffffu, mx0, 1));
        mx0 = fmaxf(mx0, __shfl_xor_sync(0xffffffffu, mx0, 2));
        mx1 = fmaxf(mx1, __shfl_xor_sync(0xffffffffu, mx1, 1));
        mx1 = fmaxf(mx1, __shfl_xor_sync(0xffffffffu, mx1, 2));

        const float mn0 = fmaxf(m0, mx0);
        const float mn1 = fmaxf(m1, mx1);
        const float al0 = __expf(m0 - mn0);
        const float al1 = __expf(m1 - mn1);

        float lp0 = 0.f, lp1 = 0.f;
        uint32_t ph[8][2];
#pragma unroll
        for (int j = 0; j < 8; j++) {
            const float p0 = (sc[j][0] > -1e29f) ? __expf(sc[j][0] - mn0) : 0.f;
            const float p1 = (sc[j][1] > -1e29f) ? __expf(sc[j][1] - mn0) : 0.f;
            const float p2 = (sc[j][2] > -1e29f) ? __expf(sc[j][2] - mn1) : 0.f;
            const float p3 = (sc[j][3] > -1e29f) ? __expf(sc[j][3] - mn1) : 0.f;
            lp0 += p0 + p1;
            lp1 += p2 + p3;
            __half2 h0 = __floats2half2_rn(p0, p1);
            __half2 h1 = __floats2half2_rn(p2, p3);
            ph[j][0] = *(uint32_t*)&h0;
            ph[j][1] = *(uint32_t*)&h1;
        }
        lp0 += __shfl_xor_sync(0xffffffffu, lp0, 1);
        lp0 += __shfl_xor_sync(0xffffffffu, lp0, 2);
        lp1 += __shfl_xor_sync(0xffffffffu, lp1, 1);
        lp1 += __shfl_xor_sync(0xffffffffu, lp1, 2);

        l0 = l0 * al0 + lp0;
        l1 = l1 * al1 + lp1;
        m0 = mn0; m1 = mn1;
#pragma unroll
        for (int jn = 0; jn < 8; jn++) {
            o[jn][0] *= al0; o[jn][1] *= al0;
            o[jn][2] *= al1; o[jn][3] *= al1;
        }

#pragma unroll
        for (int kk = 0; kk < 4; kk++) {
            uint32_t vf[4][4];
            const int vr = kk * 16 + v_r8;
            const uint32_t va = Vb + vr * 128;
            const int vsw = (vr & 7) << 4;
#pragma unroll
            for (int nb = 0; nb < 4; nb++)
                ldsm4t(vf[nb], va + (v_co[nb] ^ vsw));
            uint32_t aP[4] = { ph[2 * kk][0], ph[2 * kk][1],
                               ph[2 * kk + 1][0], ph[2 * kk + 1][1] };
#pragma unroll
            for (int jn = 0; jn < 8; jn++)
                mma_f16(o[jn], aP, &vf[jn >> 1][(jn & 1) * 2]);
        }
        __syncthreads();
    }

    const float iv0 = 1.0f / l0;
    const float iv1 = 1.0f / l1;
    __half* y0 = g_yh + ((size_t)(b * LL) + qg0) * DD + h * HD;
    __half* y1 = g_yh + ((size_t)(b * LL) + qg1) * DD + h * HD;
#pragma unroll
    for (int jn = 0; jn < 8; jn++) {
        __half2 r0 = __floats2half2_rn(o[jn][0] * iv0, o[jn][1] * iv0);
        __half2 r1 = __floats2half2_rn(o[jn][2] * iv1, o[jn][3] * iv1);
        *(__half2*)(y0 + jn * 8 + tg * 2) = r0;
        *(__half2*)(y1 + jn * 8 + tg * 2) = r1;
    }
}

// ---------------- launch ----------------
extern "C" void kernel_launch(void* const* d_in, const int* in_sizes, int n_in,
                              void* d_out, int out_size) {
    const float* x     = (const float*)d_in[0];
    const float* w_qkv = (const float*)d_in[1];
    const float* w_out = (const float*)d_in[2];
    const void*  mask  = d_in[3];
    float* out = (float*)d_out;

    __half *phh, *pwqh, *pwoh, *pyh;
    cudaGetSymbolAddress((void**)&phh, g_hh);
    cudaGetSymbolAddress((void**)&pwqh, g_wqkvh);
    cudaGetSymbolAddress((void**)&pwoh, g_wouth);
    cudaGetSymbolAddress((void**)&pyh, g_yh);

    const int M = BB * LL;

    cudaFuncSetAttribute(hgemm_kernel<1>,
                         cudaFuncAttributeMaxDynamicSharedMemorySize, GSMEM);
    cudaFuncSetAttribute(hgemm_kernel<2>,
                         cudaFuncAttributeMaxDynamicSharedMemorySize, GSMEM);
    cudaFuncSetAttribute(attn_mma_kernel,
                         cudaFuncAttributeMaxDynamicSharedMemorySize, ATT_SMEM);

    prep_kernel<<<NB_TOT, 256>>>(x, w_qkv, w_out, mask);

    hgemm_kernel<2><<<dim3(QKV_DIM / 128, M / 128), 512, GSMEM>>>(
        phh, pwqh, nullptr, nullptr, M, QKV_DIM, DD);

    attn_mma_kernel<<<dim3(LL / 64, NH, BB), 128, ATT_SMEM>>>();

    hgemm_kernel<1><<<dim3(DD / 128, M / 128), 512, GSMEM>>>(
        pyh, pwoh, x, out, M, DD, DD);
}